// round 1
// baseline (speedup 1.0000x reference)
#include <cuda_runtime.h>
#include <cuda_bf16.h>
#include <math.h>

#define B_      2
#define S_      2048
#define HID_    2048
#define H_      16
#define QLORA_  1536
#define KVLORA_ 512
#define DR_     64
#define DN_     128
#define DQK_    192
#define DV_     128
#define NTOK_   (B_*S_)          /* 4096 */
#define SCALING_ 0.07216878364870322f  /* 1/sqrt(192) */

/* ---------------- scratch (device globals; no allocations allowed) -------- */
__device__ float g_qlat  [NTOK_*QLORA_];        /* 4096x1536  q_a output / q_resid (rms in-place) */
__device__ float g_qflat [NTOK_*H_*DQK_];       /* 4096x3072  q_b output                          */
__device__ float g_qfull [B_*H_*S_*DQK_];       /* [b,h,s,192] roped q                            */
__device__ float g_ckv   [NTOK_*(KVLORA_+DR_)]; /* 4096x576                                       */
__device__ float g_kc    [NTOK_*KVLORA_];       /* 4096x512   rms-normed latent kv                */
__device__ float g_kpe   [B_*S_*DR_];           /* roped shared k_pe                              */
__device__ float g_kvflat[NTOK_*H_*(DN_+DV_)];  /* 4096x4096  kv_b output                         */
__device__ float g_kfull [B_*H_*S_*DQK_];       /* [b,h,s,192]                                    */
__device__ float g_v     [B_*H_*S_*DV_];        /* [b,h,s,128]                                    */
__device__ float g_omid  [NTOK_*H_*DV_];        /* [b,s,h*128] attention output pre-o_proj        */

/* ---------------- generic batched SGEMM: 128x128x8, 8x8 per thread -------- */
__global__ __launch_bounds__(256) void sgemm_kernel(
    const float* __restrict__ A, const float* __restrict__ Bm, float* __restrict__ C,
    int M, int N, int K, int lda, int ldb, int ldc,
    long long sA, long long sB,
    int zdiv, long long csOut, long long csIn,
    float alpha, int transB, int causalSkip, int causalK)
{
    const int row0 = blockIdx.y * 128;
    const int col0 = blockIdx.x * 128;
    if (causalSkip && col0 > row0 + 127) return;   /* tile fully above the diagonal */
    const int bz = blockIdx.z;
    const float* Ab = A  + (long long)bz * sA;
    const float* Bb = Bm + (long long)bz * sB;
    float* Cb = C + (long long)(bz / zdiv) * csOut + (long long)(bz % zdiv) * csIn;

    __shared__ __align__(16) float As[8][128];
    __shared__ __align__(16) float Bs[8][128];

    const int tid  = threadIdx.x;
    const int arow = tid >> 1;
    const int acol = (tid & 1) << 2;
    const int brow = tid >> 5;
    const int bcol = (tid & 31) << 2;
    const int trow = (tid >> 4) << 3;
    const int tcol = (tid & 15) << 3;

    float acc[8][8];
    #pragma unroll
    for (int i = 0; i < 8; i++)
        #pragma unroll
        for (int j = 0; j < 8; j++) acc[i][j] = 0.0f;

    int kend = K;
    if (causalK) { int kl = row0 + 128; if (kl < kend) kend = kl; }

    for (int k0 = 0; k0 < kend; k0 += 8) {
        /* A tile: 128 rows x 8 cols, stored transposed As[k][m] */
        {
            float4 v = make_float4(0.f, 0.f, 0.f, 0.f);
            int gr = row0 + arow;
            if (gr < M)
                v = *reinterpret_cast<const float4*>(Ab + (long long)gr * lda + (k0 + acol));
            As[acol  ][arow] = v.x;
            As[acol+1][arow] = v.y;
            As[acol+2][arow] = v.z;
            As[acol+3][arow] = v.w;
        }
        /* B tile */
        if (!transB) {
            float4 v = make_float4(0.f, 0.f, 0.f, 0.f);
            int gc = col0 + bcol;
            const float* bp = Bb + (long long)(k0 + brow) * ldb;
            if (gc + 3 < N) {
                v = *reinterpret_cast<const float4*>(bp + gc);
            } else if (gc < N) {
                v.x = bp[gc];
                if (gc + 1 < N) v.y = bp[gc + 1];
                if (gc + 2 < N) v.z = bp[gc + 2];
            }
            *reinterpret_cast<float4*>(&Bs[brow][bcol]) = v;
        } else {
            /* B is row-major [N,K]; element (k,n) = Bb[n*ldb + k] */
            float4 v = make_float4(0.f, 0.f, 0.f, 0.f);
            int gn = col0 + (tid >> 1);
            int bk = (tid & 1) << 2;
            if (gn < N)
                v = *reinterpret_cast<const float4*>(Bb + (long long)gn * ldb + (k0 + bk));
            Bs[bk  ][tid >> 1] = v.x;
            Bs[bk+1][tid >> 1] = v.y;
            Bs[bk+2][tid >> 1] = v.z;
            Bs[bk+3][tid >> 1] = v.w;
        }
        __syncthreads();

        #pragma unroll
        for (int kk = 0; kk < 8; kk++) {
            float4 a0 = *reinterpret_cast<const float4*>(&As[kk][trow]);
            float4 a1 = *reinterpret_cast<const float4*>(&As[kk][trow + 4]);
            float4 b0 = *reinterpret_cast<const float4*>(&Bs[kk][tcol]);
            float4 b1 = *reinterpret_cast<const float4*>(&Bs[kk][tcol + 4]);
            float ar[8] = {a0.x, a0.y, a0.z, a0.w, a1.x, a1.y, a1.z, a1.w};
            float br[8] = {b0.x, b0.y, b0.z, b0.w, b1.x, b1.y, b1.z, b1.w};
            #pragma unroll
            for (int i = 0; i < 8; i++)
                #pragma unroll
                for (int j = 0; j < 8; j++)
                    acc[i][j] = fmaf(ar[i], br[j], acc[i][j]);
        }
        __syncthreads();
    }

    #pragma unroll
    for (int i = 0; i < 8; i++) {
        int gr = row0 + trow + i;
        if (gr >= M) continue;
        #pragma unroll
        for (int j = 0; j < 8; j++) {
            int gc = col0 + tcol + j;
            if (gc < N) Cb[(long long)gr * ldc + gc] = acc[i][j] * alpha;
        }
    }
}

/* ---------------- RMS norm: one block per row ------------------------------ */
__global__ __launch_bounds__(256) void rmsnorm_kernel(
    const float* __restrict__ x, const float* __restrict__ w, float* __restrict__ y,
    int n, int ldx, int ldy)
{
    int row = blockIdx.x;
    const float* xr = x + (long long)row * ldx;
    float* yr = y + (long long)row * ldy;
    int tid = threadIdx.x;

    float ss = 0.0f;
    for (int i = tid; i < n; i += 256) { float v = xr[i]; ss += v * v; }
    __shared__ float red[8];
    #pragma unroll
    for (int o = 16; o; o >>= 1) ss += __shfl_xor_sync(0xffffffffu, ss, o);
    if ((tid & 31) == 0) red[tid >> 5] = ss;
    __syncthreads();
    if (tid < 32) {
        float v = (tid < 8) ? red[tid] : 0.0f;
        #pragma unroll
        for (int o = 4; o; o >>= 1) v += __shfl_xor_sync(0xffffffffu, v, o);
        if (tid == 0) red[0] = v;
    }
    __syncthreads();
    float inv = rsqrtf(red[0] / (float)n + 1e-6f);
    for (int i = tid; i < n; i += 256) yr[i] = w[i] * xr[i] * inv;
}

/* ---------------- q: [b,s,h,192] -> [b,h,s,192] with rope on last 64 ------- */
__global__ void qrope_kernel(const float* __restrict__ qf, const float* __restrict__ cs,
                             const float* __restrict__ sn, float* __restrict__ qfull)
{
    long long idx = (long long)blockIdx.x * blockDim.x + threadIdx.x;
    const long long total = (long long)B_ * H_ * S_ * DQK_;
    if (idx >= total) return;
    int d = (int)(idx % DQK_);
    long long t = idx / DQK_;
    int s = (int)(t % S_); t /= S_;
    int h = (int)(t % H_);
    int b = (int)(t / H_);
    const float* src = qf + (((long long)(b * S_ + s)) * H_ + h) * DQK_;
    float val;
    if (d < DN_) {
        val = src[d];
    } else {
        int p = d - DN_;
        float x = src[DN_ + p];
        float other = (p < DR_ / 2) ? -src[DN_ + p + DR_ / 2] : src[DN_ + p - DR_ / 2];
        long long co = ((long long)b * S_ + s) * DR_ + p;
        val = x * cs[co] + other * sn[co];
    }
    qfull[idx] = val;
}

/* ---------------- k_pe rope (shared across heads) -------------------------- */
__global__ void krope_kernel(const float* __restrict__ ckv, const float* __restrict__ cs,
                             const float* __restrict__ sn, float* __restrict__ kpe)
{
    int idx = blockIdx.x * blockDim.x + threadIdx.x;
    if (idx >= B_ * S_ * DR_) return;
    int p  = idx % DR_;
    int bs = idx / DR_;
    const float* src = ckv + (long long)bs * (KVLORA_ + DR_) + KVLORA_;
    float x = src[p];
    float other = (p < DR_ / 2) ? -src[p + DR_ / 2] : src[p - DR_ / 2];
    kpe[idx] = x * cs[idx] + other * sn[idx];
}

/* ---------------- k_full build: concat(k_nope, broadcast k_pe) ------------- */
__global__ void kbuild_kernel(const float* __restrict__ kvflat, const float* __restrict__ kpe,
                              float* __restrict__ kfull)
{
    long long idx = (long long)blockIdx.x * blockDim.x + threadIdx.x;
    const long long total = (long long)B_ * H_ * S_ * DQK_;
    if (idx >= total) return;
    int d = (int)(idx % DQK_);
    long long t = idx / DQK_;
    int s = (int)(t % S_); t /= S_;
    int h = (int)(t % H_);
    int b = (int)(t / H_);
    float val;
    if (d < DN_)
        val = kvflat[(((long long)(b * S_ + s)) * H_ + h) * (DN_ + DV_) + d];
    else
        val = kpe[((long long)b * S_ + s) * DR_ + (d - DN_)];
    kfull[idx] = val;
}

/* ---------------- v build: [b,h,s,128] -------------------------------------- */
__global__ void vbuild_kernel(const float* __restrict__ kvflat, float* __restrict__ v)
{
    long long idx = (long long)blockIdx.x * blockDim.x + threadIdx.x;
    const long long total = (long long)B_ * H_ * S_ * DV_;
    if (idx >= total) return;
    int d = (int)(idx % DV_);
    long long t = idx / DV_;
    int s = (int)(t % S_); t /= S_;
    int h = (int)(t % H_);
    int b = (int)(t / H_);
    v[idx] = kvflat[(((long long)(b * S_ + s)) * H_ + h) * (DN_ + DV_) + DN_ + d];
}

/* ---------------- causal softmax, in place over d_out weights --------------- */
__global__ __launch_bounds__(256) void softmax_kernel(float* __restrict__ wts)
{
    long long row = blockIdx.x;              /* over B*H*S rows */
    int i = (int)(row % S_);                 /* query index -> causal bound */
    float* r = wts + row * (long long)S_;
    int tid = threadIdx.x;
    int nvalid = i + 1;

    float e[8];
    float mx = -1e30f;
    int cnt = 0;
    for (int j = tid; j < nvalid; j += 256) { e[cnt] = r[j]; mx = fmaxf(mx, e[cnt]); cnt++; }

    __shared__ float sm[8];
    #pragma unroll
    for (int o = 16; o; o >>= 1) mx = fmaxf(mx, __shfl_xor_sync(0xffffffffu, mx, o));
    if ((tid & 31) == 0) sm[tid >> 5] = mx;
    __syncthreads();
    if (tid < 32) {
        float v = (tid < 8) ? sm[tid] : -1e30f;
        #pragma unroll
        for (int o = 4; o; o >>= 1) v = fmaxf(v, __shfl_xor_sync(0xffffffffu, v, o));
        if (tid == 0) sm[0] = v;
    }
    __syncthreads();
    mx = sm[0];
    __syncthreads();

    float sum = 0.0f;
    cnt = 0;
    for (int j = tid; j < nvalid; j += 256) {
        float ev = expf(e[cnt] - mx);
        e[cnt] = ev;
        sum += ev;
        cnt++;
    }
    #pragma unroll
    for (int o = 16; o; o >>= 1) sum += __shfl_xor_sync(0xffffffffu, sum, o);
    if ((tid & 31) == 0) sm[tid >> 5] = sum;
    __syncthreads();
    if (tid < 32) {
        float v = (tid < 8) ? sm[tid] : 0.0f;
        #pragma unroll
        for (int o = 4; o; o >>= 1) v += __shfl_xor_sync(0xffffffffu, v, o);
        if (tid == 0) sm[0] = v;
    }
    __syncthreads();
    float inv = 1.0f / sm[0];

    cnt = 0;
    for (int j = tid; j < nvalid; j += 256) { r[j] = e[cnt] * inv; cnt++; }
    for (int j = nvalid + tid; j < S_; j += 256) r[j] = 0.0f;  /* exp(-1e9-..)==0 exactly */
}

/* ---------------- host launch --------------------------------------------- */
static inline void sgemm(const float* A, const float* Bm, float* C,
                         int M, int N, int K, int lda, int ldb, int ldc,
                         long long sA, long long sB,
                         int zdiv, long long csOut, long long csIn,
                         float alpha, int transB, int causalSkip, int causalK, int batch)
{
    dim3 grid((N + 127) / 128, (M + 127) / 128, batch);
    sgemm_kernel<<<grid, 256>>>(A, Bm, C, M, N, K, lda, ldb, ldc,
                                sA, sB, zdiv, csOut, csIn,
                                alpha, transB, causalSkip, causalK);
}

extern "C" void kernel_launch(void* const* d_in, const int* in_sizes, int n_in,
                              void* d_out, int out_size)
{
    const float* hs      = (const float*)d_in[0];
    const float* cs      = (const float*)d_in[1];
    const float* sn      = (const float*)d_in[2];
    /* d_in[3] attention_mask: exact causal -1e9, handled analytically */
    const float* q_a_w   = (const float*)d_in[4];
    const float* q_a_ln  = (const float*)d_in[5];
    const float* q_b_w   = (const float*)d_in[6];
    const float* kv_a_w  = (const float*)d_in[7];
    const float* kv_a_ln = (const float*)d_in[8];
    const float* kv_b_w  = (const float*)d_in[9];
    const float* o_w     = (const float*)d_in[10];

    float* out = (float*)d_out;                       /* attn_output: [B,S,HID]  */
    float* wts = out + (long long)B_ * S_ * HID_;     /* attn_weights: [B,H,S,S] */

    float *qlat, *qflat, *qfull, *ckv, *kc, *kpe, *kvflat, *kfull, *v, *omid;
    cudaGetSymbolAddress((void**)&qlat,   g_qlat);
    cudaGetSymbolAddress((void**)&qflat,  g_qflat);
    cudaGetSymbolAddress((void**)&qfull,  g_qfull);
    cudaGetSymbolAddress((void**)&ckv,    g_ckv);
    cudaGetSymbolAddress((void**)&kc,     g_kc);
    cudaGetSymbolAddress((void**)&kpe,    g_kpe);
    cudaGetSymbolAddress((void**)&kvflat, g_kvflat);
    cudaGetSymbolAddress((void**)&kfull,  g_kfull);
    cudaGetSymbolAddress((void**)&v,      g_v);
    cudaGetSymbolAddress((void**)&omid,   g_omid);

    /* 1. q_a: [4096,2048] @ [2048,1536] -> qlat */
    sgemm(hs, q_a_w, qlat, NTOK_, QLORA_, HID_, HID_, QLORA_, QLORA_,
          0, 0, 1, 0, 0, 1.0f, 0, 0, 0, 1);
    /* 2. rms-norm q latent (in place) */
    rmsnorm_kernel<<<NTOK_, 256>>>(qlat, q_a_ln, qlat, QLORA_, QLORA_, QLORA_);
    /* 3. q_b: [4096,1536] @ [1536,3072] -> qflat */
    sgemm(qlat, q_b_w, qflat, NTOK_, H_ * DQK_, QLORA_, QLORA_, H_ * DQK_, H_ * DQK_,
          0, 0, 1, 0, 0, 1.0f, 0, 0, 0, 1);
    /* 4. build q_full [b,h,s,192] with rope */
    {
        long long total = (long long)B_ * H_ * S_ * DQK_;
        qrope_kernel<<<(unsigned)((total + 255) / 256), 256>>>(qflat, cs, sn, qfull);
    }
    /* 5. kv_a: [4096,2048] @ [2048,576] -> ckv */
    sgemm(hs, kv_a_w, ckv, NTOK_, KVLORA_ + DR_, HID_, HID_, KVLORA_ + DR_, KVLORA_ + DR_,
          0, 0, 1, 0, 0, 1.0f, 0, 0, 0, 1);
    /* 6. rms-norm latent kv -> kc */
    rmsnorm_kernel<<<NTOK_, 256>>>(ckv, kv_a_ln, kc, KVLORA_, KVLORA_ + DR_, KVLORA_);
    /* 7. rope k_pe */
    krope_kernel<<<(B_ * S_ * DR_) / 256, 256>>>(ckv, cs, sn, kpe);
    /* 8. kv_b: [4096,512] @ [512,4096] -> kvflat */
    sgemm(kc, kv_b_w, kvflat, NTOK_, H_ * (DN_ + DV_), KVLORA_,
          KVLORA_, H_ * (DN_ + DV_), H_ * (DN_ + DV_),
          0, 0, 1, 0, 0, 1.0f, 0, 0, 0, 1);
    /* 9. scatter k_full and v */
    {
        long long totk = (long long)B_ * H_ * S_ * DQK_;
        kbuild_kernel<<<(unsigned)((totk + 255) / 256), 256>>>(kvflat, kpe, kfull);
        long long totv = (long long)B_ * H_ * S_ * DV_;
        vbuild_kernel<<<(unsigned)((totv + 255) / 256), 256>>>(kvflat, v);
    }
    /* 10. scores: per (b,h): q_full [S,192] @ k_full^T -> wts, causal tile skip */
    sgemm(qfull, kfull, wts, S_, S_, DQK_, DQK_, DQK_, S_,
          (long long)S_ * DQK_, (long long)S_ * DQK_,
          1, (long long)S_ * S_, 0,
          SCALING_, 1 /*transB*/, 1 /*causalSkip*/, 0, B_ * H_);
    /* 11. causal softmax in place (writes exact zeros above diagonal) */
    softmax_kernel<<<B_ * H_ * S_, 256>>>(wts);
    /* 12. out = wts @ v -> omid laid out [b,s,h*128]; causal K-limit */
    sgemm(wts, v, omid, S_, DV_, S_, S_, DV_, H_ * DV_,
          (long long)S_ * S_, (long long)S_ * DV_,
          H_, (long long)S_ * H_ * DV_, (long long)DV_,
          1.0f, 0, 0, 1 /*causalK*/, B_ * H_);
    /* 13. o_proj: [4096,2048] @ [2048,2048] -> attn_output */
    sgemm(omid, o_w, out, NTOK_, HID_, H_ * DV_, H_ * DV_, HID_, HID_,
          0, 0, 1, 0, 0, 1.0f, 0, 0, 0, 1);
}

// round 3
// speedup vs baseline: 2.2116x; 2.2116x over previous
#include <cuda_runtime.h>
#include <cuda_bf16.h>
#include <math.h>
#include <stdint.h>

#define B_      2
#define S_      2048
#define HID_    2048
#define H_      16
#define QLORA_  1536
#define KVLORA_ 512
#define DR_     64
#define DN_     128
#define DQK_    192
#define DV_     128
#define NTOK_   (B_*S_)
#define SCALING_ 0.07216878364870322f

/* ------------------------------- scratch ---------------------------------- */
__device__ float g_qlat  [NTOK_*QLORA_];
__device__ float g_qflat [NTOK_*H_*DQK_];
__device__ float g_qfull [B_*H_*S_*DQK_];
__device__ float g_ckv   [NTOK_*(KVLORA_+DR_)];
__device__ float g_kc    [NTOK_*KVLORA_];
__device__ float g_kpe   [B_*S_*DR_];
__device__ float g_kvflat[NTOK_*H_*(DN_+DV_)];
__device__ float g_kfull [B_*H_*S_*DQK_];
__device__ float g_vT    [B_*H_*DV_*S_];
__device__ float g_omid  [NTOK_*H_*DV_];
__device__ float g_wqaT [QLORA_*HID_];
__device__ float g_wqbT [H_*DQK_*QLORA_];
__device__ float g_wkvaT[(KVLORA_+DR_)*HID_];
__device__ float g_wkvbT[H_*(DN_+DV_)*KVLORA_];
__device__ float g_woT  [HID_*H_*DV_];

/* --------------------------- mma helpers ---------------------------------- */
__device__ __forceinline__ uint32_t smem_u32(const void* p) {
    uint32_t a;
    asm("{ .reg .u64 t; cvta.to.shared.u64 t, %1; cvt.u32.u64 %0, t; }" : "=r"(a) : "l"(p));
    return a;
}
__device__ __forceinline__ void ldsm_x4(uint32_t& r0, uint32_t& r1, uint32_t& r2, uint32_t& r3,
                                        uint32_t addr) {
    asm volatile("ldmatrix.sync.aligned.m8n8.x4.shared.b16 {%0,%1,%2,%3}, [%4];"
                 : "=r"(r0), "=r"(r1), "=r"(r2), "=r"(r3) : "r"(addr));
}
__device__ __forceinline__ void mma16816(float* c, const uint32_t* a, uint32_t b0, uint32_t b1) {
    asm volatile("mma.sync.aligned.m16n8k16.row.col.f32.bf16.bf16.f32 "
                 "{%0,%1,%2,%3}, {%4,%5,%6,%7}, {%8,%9}, {%0,%1,%2,%3};"
                 : "+f"(c[0]), "+f"(c[1]), "+f"(c[2]), "+f"(c[3])
                 : "r"(a[0]), "r"(a[1]), "r"(a[2]), "r"(a[3]), "r"(b0), "r"(b1));
}

/* split 4 floats -> packed bf16 hi pair-regs + lo pair-regs */
__device__ __forceinline__ void split4(float4 v, uint2& hi, uint2& lo) {
    float f[4] = {v.x, v.y, v.z, v.w};
    unsigned short h[4], l[4];
    #pragma unroll
    for (int i = 0; i < 4; i++) {
        __nv_bfloat16 hb = __float2bfloat16(f[i]);
        float r = f[i] - __bfloat162float(hb);
        __nv_bfloat16 lb = __float2bfloat16(r);
        h[i] = *(unsigned short*)&hb;
        l[i] = *(unsigned short*)&lb;
    }
    hi.x = (uint32_t)h[0] | ((uint32_t)h[1] << 16);
    hi.y = (uint32_t)h[2] | ((uint32_t)h[3] << 16);
    lo.x = (uint32_t)l[0] | ((uint32_t)l[1] << 16);
    lo.y = (uint32_t)l[2] | ((uint32_t)l[3] << 16);
}

/* smem layout (bytes), rows padded to 40 bf16 = 80B */
#define ROWB   80
#define AHI_O  0
#define ALO_O  10240
#define BHI_O  20480
#define BLO_O  30720
#define BUFSZ  40960
#define GEMM_SMEM (2*BUFSZ)

/* --------------------------- HMMA GEMM ------------------------------------ */
/* C[M,N] = alpha * A[M,K] @ B[N,K]^T ; fp32 io, bf16x2 3-pass; M%128==0, K%32==0 */
__global__ __launch_bounds__(256, 1) void mma_gemm_kernel(
    const float* __restrict__ A, const float* __restrict__ Bm, float* __restrict__ C,
    int M, int N, int K, int lda, int ldb, int ldc,
    long long sA, long long sB, int zdiv, long long csOut, long long csIn,
    float alpha, int causalSkip, int causalK)
{
    const int row0 = blockIdx.y * 128;
    const int col0 = blockIdx.x * 128;
    if (causalSkip && col0 > row0 + 127) return;
    const int bz = blockIdx.z;
    const float* Ab = A + (long long)bz * sA;
    const float* Bb = Bm + (long long)bz * sB;
    float* Cb = C + (long long)(bz / zdiv) * csOut + (long long)(bz % zdiv) * csIn;

    extern __shared__ __align__(16) char smem[];
    const uint32_t sb = smem_u32(smem);

    const int tid  = threadIdx.x;
    const int wid  = tid >> 5;
    const int lane = tid & 31;
    const int wm = wid & 3;          /* warp M index: rows wm*32..+32 */
    const int wn = wid >> 2;         /* warp N index: cols wn*64..+64 */
    const int laneIn = lane & 7;
    const int quad   = lane >> 3;

    /* per-lane ldmatrix base offsets (bytes) */
    const uint32_t aBase = (uint32_t)((wm * 32 + laneIn + (quad & 1) * 8) * ROWB
                                      + ((quad >> 1) * 8) * 2);
    const uint32_t bBase = (uint32_t)((wn * 64 + laneIn + (quad >> 1) * 8) * ROWB
                                      + ((quad & 1) * 8) * 2);

    int kend = K;
    if (causalK) { int kl = row0 + 128; if (kl < kend) kend = kl; }
    const int nch = kend >> 5;

    float acc[2][8][4];
    #pragma unroll
    for (int i = 0; i < 2; i++)
        #pragma unroll
        for (int j = 0; j < 8; j++)
            #pragma unroll
            for (int q = 0; q < 4; q++) acc[i][j][q] = 0.0f;

    /* thread's gmem-load coordinates: 4 float4 per operand per chunk */
    int lrow[4], lcol[4];
    #pragma unroll
    for (int i = 0; i < 4; i++) {
        int g = tid + i * 256;
        lrow[i] = g >> 3;
        lcol[i] = (g & 7) << 2;
    }

    float4 aS[4], bS[4];

    /* load chunk 0 */
    #pragma unroll
    for (int i = 0; i < 4; i++) {
        aS[i] = *reinterpret_cast<const float4*>(Ab + (long long)(row0 + lrow[i]) * lda + lcol[i]);
        bS[i] = (col0 + lrow[i] < N)
            ? *reinterpret_cast<const float4*>(Bb + (long long)(col0 + lrow[i]) * ldb + lcol[i])
            : make_float4(0.f, 0.f, 0.f, 0.f);
    }
    #pragma unroll
    for (int i = 0; i < 4; i++) {
        uint2 hi, lo;
        uint32_t off = (uint32_t)(lrow[i] * ROWB + lcol[i] * 2);
        split4(aS[i], hi, lo);
        *reinterpret_cast<uint2*>(smem + AHI_O + off) = hi;
        *reinterpret_cast<uint2*>(smem + ALO_O + off) = lo;
        split4(bS[i], hi, lo);
        *reinterpret_cast<uint2*>(smem + BHI_O + off) = hi;
        *reinterpret_cast<uint2*>(smem + BLO_O + off) = lo;
    }
    __syncthreads();

    for (int c = 0; c < nch; c++) {
        const int k0n = (c + 1) << 5;
        if (c + 1 < nch) {
            #pragma unroll
            for (int i = 0; i < 4; i++) {
                aS[i] = *reinterpret_cast<const float4*>(
                    Ab + (long long)(row0 + lrow[i]) * lda + k0n + lcol[i]);
                bS[i] = (col0 + lrow[i] < N)
                    ? *reinterpret_cast<const float4*>(
                          Bb + (long long)(col0 + lrow[i]) * ldb + k0n + lcol[i])
                    : make_float4(0.f, 0.f, 0.f, 0.f);
            }
        }

        const uint32_t bufb = sb + (uint32_t)(c & 1) * BUFSZ;
        /* 3 passes: (Ahi,Bhi), (Ahi,Blo), (Alo,Bhi) */
        #pragma unroll
        for (int p = 0; p < 3; p++) {
            const uint32_t aOp = bufb + (p == 2 ? ALO_O : AHI_O);
            const uint32_t bOp = bufb + (p == 1 ? BLO_O : BHI_O);
            #pragma unroll
            for (int ks = 0; ks < 2; ks++) {
                const uint32_t kb = (uint32_t)(ks * 16 * 2);
                uint32_t af[2][4];
                #pragma unroll
                for (int mt = 0; mt < 2; mt++)
                    ldsm_x4(af[mt][0], af[mt][1], af[mt][2], af[mt][3],
                            aOp + aBase + (uint32_t)(mt * 16 * ROWB) + kb);
                uint32_t bf[4][4];
                #pragma unroll
                for (int np = 0; np < 4; np++)
                    ldsm_x4(bf[np][0], bf[np][1], bf[np][2], bf[np][3],
                            bOp + bBase + (uint32_t)(np * 16 * ROWB) + kb);
                #pragma unroll
                for (int mt = 0; mt < 2; mt++)
                    #pragma unroll
                    for (int nt = 0; nt < 8; nt++)
                        mma16816(acc[mt][nt], af[mt],
                                 bf[nt >> 1][(nt & 1) * 2], bf[nt >> 1][(nt & 1) * 2 + 1]);
            }
        }

        if (c + 1 < nch) {
            char* dst = smem + ((c + 1) & 1) * BUFSZ;
            #pragma unroll
            for (int i = 0; i < 4; i++) {
                uint2 hi, lo;
                uint32_t off = (uint32_t)(lrow[i] * ROWB + lcol[i] * 2);
                split4(aS[i], hi, lo);
                *reinterpret_cast<uint2*>(dst + AHI_O + off) = hi;
                *reinterpret_cast<uint2*>(dst + ALO_O + off) = lo;
                split4(bS[i], hi, lo);
                *reinterpret_cast<uint2*>(dst + BHI_O + off) = hi;
                *reinterpret_cast<uint2*>(dst + BLO_O + off) = lo;
            }
        }
        __syncthreads();
    }

    /* epilogue */
    const int lr  = lane >> 2;
    const int lc2 = (lane & 3) * 2;
    #pragma unroll
    for (int mt = 0; mt < 2; mt++) {
        #pragma unroll
        for (int nt = 0; nt < 8; nt++) {
            int gr = row0 + wm * 32 + mt * 16 + lr;
            int gc = col0 + wn * 64 + nt * 8 + lc2;
            if (gc < N) {
                float2 v0 = make_float2(acc[mt][nt][0] * alpha, acc[mt][nt][1] * alpha);
                float2 v1 = make_float2(acc[mt][nt][2] * alpha, acc[mt][nt][3] * alpha);
                *reinterpret_cast<float2*>(Cb + (long long)gr * ldc + gc) = v0;
                *reinterpret_cast<float2*>(Cb + (long long)(gr + 8) * ldc + gc) = v1;
            }
        }
    }
}

/* ---------------- transpose [K,N] -> [N,K] --------------------------------- */
__global__ void transpose_kernel(const float* __restrict__ in, float* __restrict__ out,
                                 int K, int N)
{
    __shared__ float t[32][33];
    int k0 = blockIdx.y * 32, n0 = blockIdx.x * 32;
    int x = threadIdx.x, y = threadIdx.y;
    #pragma unroll
    for (int i = 0; i < 32; i += 8) {
        int k = k0 + y + i, n = n0 + x;
        t[y + i][x] = (k < K && n < N) ? in[(long long)k * N + n] : 0.0f;
    }
    __syncthreads();
    #pragma unroll
    for (int i = 0; i < 32; i += 8) {
        int n = n0 + y + i, k = k0 + x;
        if (n < N && k < K) out[(long long)n * K + k] = t[x][y + i];
    }
}

/* ---------------- RMS norm -------------------------------------------------- */
__global__ __launch_bounds__(256) void rmsnorm_kernel(
    const float* __restrict__ x, const float* __restrict__ w, float* __restrict__ y,
    int n, int ldx, int ldy)
{
    int row = blockIdx.x;
    const float* xr = x + (long long)row * ldx;
    float* yr = y + (long long)row * ldy;
    int tid = threadIdx.x;
    float ss = 0.0f;
    for (int i = tid; i < n; i += 256) { float v = xr[i]; ss += v * v; }
    __shared__ float red[8];
    #pragma unroll
    for (int o = 16; o; o >>= 1) ss += __shfl_xor_sync(0xffffffffu, ss, o);
    if ((tid & 31) == 0) red[tid >> 5] = ss;
    __syncthreads();
    if (tid < 32) {
        float v = (tid < 8) ? red[tid] : 0.0f;
        #pragma unroll
        for (int o = 4; o; o >>= 1) v += __shfl_xor_sync(0xffffffffu, v, o);
        if (tid == 0) red[0] = v;
    }
    __syncthreads();
    float inv = rsqrtf(red[0] / (float)n + 1e-6f);
    for (int i = tid; i < n; i += 256) yr[i] = w[i] * xr[i] * inv;
}

/* ---------------- q rope scatter ------------------------------------------- */
__global__ void qrope_kernel(const float* __restrict__ qf, const float* __restrict__ cs,
                             const float* __restrict__ sn, float* __restrict__ qfull)
{
    long long idx = (long long)blockIdx.x * blockDim.x + threadIdx.x;
    const long long total = (long long)B_ * H_ * S_ * DQK_;
    if (idx >= total) return;
    int d = (int)(idx % DQK_);
    long long t = idx / DQK_;
    int s = (int)(t % S_); t /= S_;
    int h = (int)(t % H_);
    int b = (int)(t / H_);
    const float* src = qf + (((long long)(b * S_ + s)) * H_ + h) * DQK_;
    float val;
    if (d < DN_) val = src[d];
    else {
        int p = d - DN_;
        float x = src[DN_ + p];
        float other = (p < DR_ / 2) ? -src[DN_ + p + DR_ / 2] : src[DN_ + p - DR_ / 2];
        long long co = ((long long)b * S_ + s) * DR_ + p;
        val = x * cs[co] + other * sn[co];
    }
    qfull[idx] = val;
}

__global__ void krope_kernel(const float* __restrict__ ckv, const float* __restrict__ cs,
                             const float* __restrict__ sn, float* __restrict__ kpe)
{
    int idx = blockIdx.x * blockDim.x + threadIdx.x;
    if (idx >= B_ * S_ * DR_) return;
    int p = idx % DR_;
    int bs = idx / DR_;
    const float* src = ckv + (long long)bs * (KVLORA_ + DR_) + KVLORA_;
    float x = src[p];
    float other = (p < DR_ / 2) ? -src[p + DR_ / 2] : src[p - DR_ / 2];
    kpe[idx] = x * cs[idx] + other * sn[idx];
}

__global__ void kbuild_kernel(const float* __restrict__ kvflat, const float* __restrict__ kpe,
                              float* __restrict__ kfull)
{
    long long idx = (long long)blockIdx.x * blockDim.x + threadIdx.x;
    const long long total = (long long)B_ * H_ * S_ * DQK_;
    if (idx >= total) return;
    int d = (int)(idx % DQK_);
    long long t = idx / DQK_;
    int s = (int)(t % S_); t /= S_;
    int h = (int)(t % H_);
    int b = (int)(t / H_);
    float val;
    if (d < DN_)
        val = kvflat[(((long long)(b * S_ + s)) * H_ + h) * (DN_ + DV_) + d];
    else
        val = kpe[((long long)b * S_ + s) * DR_ + (d - DN_)];
    kfull[idx] = val;
}

__global__ void vbuildT_kernel(const float* __restrict__ kvflat, float* __restrict__ vT)
{
    long long idx = (long long)blockIdx.x * blockDim.x + threadIdx.x;
    const long long total = (long long)B_ * H_ * S_ * DV_;
    if (idx >= total) return;
    int s = (int)(idx % S_);
    long long t = idx / S_;
    int d = (int)(t % DV_); t /= DV_;
    int h = (int)(t % H_);
    int b = (int)(t / H_);
    vT[idx] = kvflat[(((long long)(b * S_ + s)) * H_ + h) * (DN_ + DV_) + DN_ + d];
}

/* ---------------- causal softmax ------------------------------------------- */
__global__ __launch_bounds__(256) void softmax_kernel(float* __restrict__ wts)
{
    long long row = blockIdx.x;
    int i = (int)(row % S_);
    float* r = wts + row * (long long)S_;
    int tid = threadIdx.x;
    int nvalid = i + 1;

    float e[8];
    float mx = -1e30f;
    int cnt = 0;
    for (int j = tid; j < nvalid; j += 256) { e[cnt] = r[j]; mx = fmaxf(mx, e[cnt]); cnt++; }

    __shared__ float sm[8];
    #pragma unroll
    for (int o = 16; o; o >>= 1) mx = fmaxf(mx, __shfl_xor_sync(0xffffffffu, mx, o));
    if ((tid & 31) == 0) sm[tid >> 5] = mx;
    __syncthreads();
    if (tid < 32) {
        float v = (tid < 8) ? sm[tid] : -1e30f;
        #pragma unroll
        for (int o = 4; o; o >>= 1) v = fmaxf(v, __shfl_xor_sync(0xffffffffu, v, o));
        if (tid == 0) sm[0] = v;
    }
    __syncthreads();
    mx = sm[0];
    __syncthreads();

    float sum = 0.0f;
    cnt = 0;
    for (int j = tid; j < nvalid; j += 256) {
        float ev = expf(e[cnt] - mx);
        e[cnt] = ev;
        sum += ev;
        cnt++;
    }
    #pragma unroll
    for (int o = 16; o; o >>= 1) sum += __shfl_xor_sync(0xffffffffu, sum, o);
    if ((tid & 31) == 0) sm[tid >> 5] = sum;
    __syncthreads();
    if (tid < 32) {
        float v = (tid < 8) ? sm[tid] : 0.0f;
        #pragma unroll
        for (int o = 4; o; o >>= 1) v += __shfl_xor_sync(0xffffffffu, v, o);
        if (tid == 0) sm[0] = v;
    }
    __syncthreads();
    float inv = 1.0f / sm[0];

    cnt = 0;
    for (int j = tid; j < nvalid; j += 256) { r[j] = e[cnt] * inv; cnt++; }
    for (int j = nvalid + tid; j < S_; j += 256) r[j] = 0.0f;
}

/* ---------------- host ------------------------------------------------------ */
static inline void mma_gemm(const float* A, const float* Bm, float* C,
                            int M, int N, int K, int lda, int ldb, int ldc,
                            long long sA, long long sB,
                            int zdiv, long long csOut, long long csIn,
                            float alpha, int causalSkip, int causalK, int batch)
{
    dim3 grid((N + 127) / 128, (M + 127) / 128, batch);
    mma_gemm_kernel<<<grid, 256, GEMM_SMEM>>>(A, Bm, C, M, N, K, lda, ldb, ldc,
                                              sA, sB, zdiv, csOut, csIn,
                                              alpha, causalSkip, causalK);
}

extern "C" void kernel_launch(void* const* d_in, const int* in_sizes, int n_in,
                              void* d_out, int out_size)
{
    const float* hs      = (const float*)d_in[0];
    const float* cs      = (const float*)d_in[1];
    const float* sn      = (const float*)d_in[2];
    const float* q_a_w   = (const float*)d_in[4];
    const float* q_a_ln  = (const float*)d_in[5];
    const float* q_b_w   = (const float*)d_in[6];
    const float* kv_a_w  = (const float*)d_in[7];
    const float* kv_a_ln = (const float*)d_in[8];
    const float* kv_b_w  = (const float*)d_in[9];
    const float* o_w     = (const float*)d_in[10];

    float* out = (float*)d_out;
    float* wts = out + (long long)B_ * S_ * HID_;

    static bool attr_set = false;
    if (!attr_set) {
        cudaFuncSetAttribute(mma_gemm_kernel, cudaFuncAttributeMaxDynamicSharedMemorySize, GEMM_SMEM);
        attr_set = true;
    }

    float *qlat, *qflat, *qfull, *ckv, *kc, *kpe, *kvflat, *kfull, *vT, *omid;
    float *wqaT, *wqbT, *wkvaT, *wkvbT, *woT;
    cudaGetSymbolAddress((void**)&qlat,   g_qlat);
    cudaGetSymbolAddress((void**)&qflat,  g_qflat);
    cudaGetSymbolAddress((void**)&qfull,  g_qfull);
    cudaGetSymbolAddress((void**)&ckv,    g_ckv);
    cudaGetSymbolAddress((void**)&kc,     g_kc);
    cudaGetSymbolAddress((void**)&kpe,    g_kpe);
    cudaGetSymbolAddress((void**)&kvflat, g_kvflat);
    cudaGetSymbolAddress((void**)&kfull,  g_kfull);
    cudaGetSymbolAddress((void**)&vT,     g_vT);
    cudaGetSymbolAddress((void**)&omid,   g_omid);
    cudaGetSymbolAddress((void**)&wqaT,   g_wqaT);
    cudaGetSymbolAddress((void**)&wqbT,   g_wqbT);
    cudaGetSymbolAddress((void**)&wkvaT,  g_wkvaT);
    cudaGetSymbolAddress((void**)&wkvbT,  g_wkvbT);
    cudaGetSymbolAddress((void**)&woT,    g_woT);

    dim3 tb(32, 8);
    transpose_kernel<<<dim3(QLORA_ / 32, HID_ / 32), tb>>>(q_a_w, wqaT, HID_, QLORA_);
    transpose_kernel<<<dim3(H_ * DQK_ / 32, QLORA_ / 32), tb>>>(q_b_w, wqbT, QLORA_, H_ * DQK_);
    transpose_kernel<<<dim3((KVLORA_ + DR_) / 32, HID_ / 32), tb>>>(kv_a_w, wkvaT, HID_, KVLORA_ + DR_);
    transpose_kernel<<<dim3(H_ * (DN_ + DV_) / 32, KVLORA_ / 32), tb>>>(kv_b_w, wkvbT, KVLORA_, H_ * (DN_ + DV_));
    transpose_kernel<<<dim3(HID_ / 32, (H_ * DV_) / 32), tb>>>(o_w, woT, H_ * DV_, HID_);

    /* 1. q_a */
    mma_gemm(hs, wqaT, qlat, NTOK_, QLORA_, HID_, HID_, HID_, QLORA_,
             0, 0, 1, 0, 0, 1.0f, 0, 0, 1);
    /* 2. rms norm (in place) */
    rmsnorm_kernel<<<NTOK_, 256>>>(qlat, q_a_ln, qlat, QLORA_, QLORA_, QLORA_);
    /* 3. q_b */
    mma_gemm(qlat, wqbT, qflat, NTOK_, H_ * DQK_, QLORA_, QLORA_, QLORA_, H_ * DQK_,
             0, 0, 1, 0, 0, 1.0f, 0, 0, 1);
    /* 4. q rope */
    {
        long long total = (long long)B_ * H_ * S_ * DQK_;
        qrope_kernel<<<(unsigned)((total + 255) / 256), 256>>>(qflat, cs, sn, qfull);
    }
    /* 5. kv_a */
    mma_gemm(hs, wkvaT, ckv, NTOK_, KVLORA_ + DR_, HID_, HID_, HID_, KVLORA_ + DR_,
             0, 0, 1, 0, 0, 1.0f, 0, 0, 1);
    /* 6. rms norm latent kv */
    rmsnorm_kernel<<<NTOK_, 256>>>(ckv, kv_a_ln, kc, KVLORA_, KVLORA_ + DR_, KVLORA_);
    /* 7. k_pe rope */
    krope_kernel<<<(B_ * S_ * DR_) / 256, 256>>>(ckv, cs, sn, kpe);
    /* 8. kv_b */
    mma_gemm(kc, wkvbT, kvflat, NTOK_, H_ * (DN_ + DV_), KVLORA_,
             KVLORA_, KVLORA_, H_ * (DN_ + DV_),
             0, 0, 1, 0, 0, 1.0f, 0, 0, 1);
    /* 9. build k_full and vT */
    {
        long long totk = (long long)B_ * H_ * S_ * DQK_;
        kbuild_kernel<<<(unsigned)((totk + 255) / 256), 256>>>(kvflat, kpe, kfull);
        long long totv = (long long)B_ * H_ * S_ * DV_;
        vbuildT_kernel<<<(unsigned)((totv + 255) / 256), 256>>>(kvflat, vT);
    }
    /* 10. scores (causal tile skip) */
    mma_gemm(qfull, kfull, wts, S_, S_, DQK_, DQK_, DQK_, S_,
             (long long)S_ * DQK_, (long long)S_ * DQK_,
             1, (long long)S_ * S_, 0,
             SCALING_, 1, 0, B_ * H_);
    /* 11. softmax */
    softmax_kernel<<<B_ * H_ * S_, 256>>>(wts);
    /* 12. PV (causal K-limit) -> omid [b,s,h*128] */
    mma_gemm(wts, vT, omid, S_, DV_, S_, S_, S_, H_ * DV_,
             (long long)S_ * S_, (long long)DV_ * S_,
             H_, (long long)S_ * H_ * DV_, (long long)DV_,
             1.0f, 0, 1, B_ * H_);
    /* 13. o_proj */
    mma_gemm(omid, woT, out, NTOK_, HID_, H_ * DV_, H_ * DV_, H_ * DV_, HID_,
             0, 0, 1, 0, 0, 1.0f, 0, 0, 1);
}

// round 4
// speedup vs baseline: 2.2483x; 1.0166x over previous
#include <cuda_runtime.h>
#include <cuda_bf16.h>
#include <math.h>
#include <stdint.h>

#define B_      2
#define S_      2048
#define HID_    2048
#define H_      16
#define QLORA_  1536
#define KVLORA_ 512
#define DR_     64
#define DN_     128
#define DQK_    192
#define DV_     128
#define NTOK_   (B_*S_)
#define SCALING_ 0.07216878364870322f

/* ------------------------------- scratch ---------------------------------- */
__device__ float g_qlat  [NTOK_*QLORA_];
__device__ float g_qflat [NTOK_*H_*DQK_];
__device__ float g_qfull [B_*H_*S_*DQK_];
__device__ float g_ckv   [NTOK_*(KVLORA_+DR_)];
__device__ float g_kc    [NTOK_*KVLORA_];
__device__ float g_kpe   [B_*S_*DR_];
__device__ float g_kvflat[NTOK_*H_*(DN_+DV_)];
__device__ float g_kfull [B_*H_*S_*DQK_];
__device__ float g_vT    [B_*H_*DV_*S_];
__device__ float g_omid  [NTOK_*H_*DV_];
__device__ float g_wqaT [QLORA_*HID_];
__device__ float g_wqbT [H_*DQK_*QLORA_];
__device__ float g_wkvaT[(KVLORA_+DR_)*HID_];
__device__ float g_wkvbT[H_*(DN_+DV_)*KVLORA_];
__device__ float g_woT  [HID_*H_*DV_];

/* --------------------------- mma helpers ---------------------------------- */
__device__ __forceinline__ uint32_t smem_u32(const void* p) {
    uint32_t a;
    asm("{ .reg .u64 t; cvta.to.shared.u64 t, %1; cvt.u32.u64 %0, t; }" : "=r"(a) : "l"(p));
    return a;
}
__device__ __forceinline__ void ldsm_x4(uint32_t& r0, uint32_t& r1, uint32_t& r2, uint32_t& r3,
                                        uint32_t addr) {
    asm volatile("ldmatrix.sync.aligned.m8n8.x4.shared.b16 {%0,%1,%2,%3}, [%4];"
                 : "=r"(r0), "=r"(r1), "=r"(r2), "=r"(r3) : "r"(addr));
}
__device__ __forceinline__ void mma16816(float* c, const uint32_t* a, uint32_t b0, uint32_t b1) {
    asm volatile("mma.sync.aligned.m16n8k16.row.col.f32.bf16.bf16.f32 "
                 "{%0,%1,%2,%3}, {%4,%5,%6,%7}, {%8,%9}, {%0,%1,%2,%3};"
                 : "+f"(c[0]), "+f"(c[1]), "+f"(c[2]), "+f"(c[3])
                 : "r"(a[0]), "r"(a[1]), "r"(a[2]), "r"(a[3]), "r"(b0), "r"(b1));
}

__device__ __forceinline__ void split4(float4 v, uint2& hi, uint2& lo) {
    float f[4] = {v.x, v.y, v.z, v.w};
    unsigned short h[4], l[4];
    #pragma unroll
    for (int i = 0; i < 4; i++) {
        __nv_bfloat16 hb = __float2bfloat16(f[i]);
        float r = f[i] - __bfloat162float(hb);
        __nv_bfloat16 lb = __float2bfloat16(r);
        h[i] = *(unsigned short*)&hb;
        l[i] = *(unsigned short*)&lb;
    }
    hi.x = (uint32_t)h[0] | ((uint32_t)h[1] << 16);
    hi.y = (uint32_t)h[2] | ((uint32_t)h[3] << 16);
    lo.x = (uint32_t)l[0] | ((uint32_t)l[1] << 16);
    lo.y = (uint32_t)l[2] | ((uint32_t)l[3] << 16);
}

/* FFMA-only exp (no MUFU): exp(x) = 2^(x*log2e), poly over [-0.5,0.5] */
__device__ __forceinline__ float fast_exp(float x) {
    float t = x * 1.4426950408889634f;
    float r = rintf(t);
    float f = t - r;
    float p =          1.339887440266574e-3f;
    p = fmaf(p, f,     9.618437357674640e-3f);
    p = fmaf(p, f,     5.550332471162809e-2f);
    p = fmaf(p, f,     2.402264791363012e-1f);
    p = fmaf(p, f,     6.931472028550421e-1f);
    p = fmaf(p, f,     1.0f);
    int ri = (int)r;
    if (ri < -126) ri = -126;
    float s = __int_as_float((uint32_t)(ri + 127) << 23);
    return p * s;
}

/* smem layout (bytes), rows padded to 40 bf16 = 80B */
#define ROWB   80
#define AHI_O  0
#define ALO_O  10240
#define BHI_O  20480
#define BLO_O  30720
#define BUFSZ  40960
#define GEMM_SMEM (2*BUFSZ)

/* --------------------------- HMMA GEMM ------------------------------------ */
__global__ __launch_bounds__(256, 1) void mma_gemm_kernel(
    const float* __restrict__ A, const float* __restrict__ Bm, float* __restrict__ C,
    int M, int N, int K, int lda, int ldb, int ldc,
    long long sA, long long sB, int zdiv, long long csOut, long long csIn,
    float alpha, int causalSkip, int causalK)
{
    const int row0 = blockIdx.y * 128;
    const int col0 = blockIdx.x * 128;
    if (causalSkip && col0 > row0 + 127) return;
    const int bz = blockIdx.z;
    const float* Ab = A + (long long)bz * sA;
    const float* Bb = Bm + (long long)bz * sB;
    float* Cb = C + (long long)(bz / zdiv) * csOut + (long long)(bz % zdiv) * csIn;

    extern __shared__ __align__(16) char smem[];
    const uint32_t sb = smem_u32(smem);

    const int tid  = threadIdx.x;
    const int wid  = tid >> 5;
    const int lane = tid & 31;
    const int wm = wid & 3;
    const int wn = wid >> 2;
    const int laneIn = lane & 7;
    const int quad   = lane >> 3;

    const uint32_t aBase = (uint32_t)((wm * 32 + laneIn + (quad & 1) * 8) * ROWB
                                      + ((quad >> 1) * 8) * 2);
    const uint32_t bBase = (uint32_t)((wn * 64 + laneIn + (quad >> 1) * 8) * ROWB
                                      + ((quad & 1) * 8) * 2);

    int kend = K;
    if (causalK) { int kl = row0 + 128; if (kl < kend) kend = kl; }
    const int nch = kend >> 5;

    float acc[2][8][4];
    #pragma unroll
    for (int i = 0; i < 2; i++)
        #pragma unroll
        for (int j = 0; j < 8; j++)
            #pragma unroll
            for (int q = 0; q < 4; q++) acc[i][j][q] = 0.0f;

    int lrow[4], lcol[4];
    #pragma unroll
    for (int i = 0; i < 4; i++) {
        int g = tid + i * 256;
        lrow[i] = g >> 3;
        lcol[i] = (g & 7) << 2;
    }

    float4 aS[4], bS[4];

    #pragma unroll
    for (int i = 0; i < 4; i++) {
        aS[i] = *reinterpret_cast<const float4*>(Ab + (long long)(row0 + lrow[i]) * lda + lcol[i]);
        bS[i] = (col0 + lrow[i] < N)
            ? *reinterpret_cast<const float4*>(Bb + (long long)(col0 + lrow[i]) * ldb + lcol[i])
            : make_float4(0.f, 0.f, 0.f, 0.f);
    }
    #pragma unroll
    for (int i = 0; i < 4; i++) {
        uint2 hi, lo;
        uint32_t off = (uint32_t)(lrow[i] * ROWB + lcol[i] * 2);
        split4(aS[i], hi, lo);
        *reinterpret_cast<uint2*>(smem + AHI_O + off) = hi;
        *reinterpret_cast<uint2*>(smem + ALO_O + off) = lo;
        split4(bS[i], hi, lo);
        *reinterpret_cast<uint2*>(smem + BHI_O + off) = hi;
        *reinterpret_cast<uint2*>(smem + BLO_O + off) = lo;
    }
    __syncthreads();

    for (int c = 0; c < nch; c++) {
        const int k0n = (c + 1) << 5;
        if (c + 1 < nch) {
            #pragma unroll
            for (int i = 0; i < 4; i++) {
                aS[i] = *reinterpret_cast<const float4*>(
                    Ab + (long long)(row0 + lrow[i]) * lda + k0n + lcol[i]);
                bS[i] = (col0 + lrow[i] < N)
                    ? *reinterpret_cast<const float4*>(
                          Bb + (long long)(col0 + lrow[i]) * ldb + k0n + lcol[i])
                    : make_float4(0.f, 0.f, 0.f, 0.f);
            }
        }

        const uint32_t bufb = sb + (uint32_t)(c & 1) * BUFSZ;
        #pragma unroll
        for (int p = 0; p < 3; p++) {
            const uint32_t aOp = bufb + (p == 2 ? ALO_O : AHI_O);
            const uint32_t bOp = bufb + (p == 1 ? BLO_O : BHI_O);
            #pragma unroll
            for (int ks = 0; ks < 2; ks++) {
                const uint32_t kb = (uint32_t)(ks * 16 * 2);
                uint32_t af[2][4];
                #pragma unroll
                for (int mt = 0; mt < 2; mt++)
                    ldsm_x4(af[mt][0], af[mt][1], af[mt][2], af[mt][3],
                            aOp + aBase + (uint32_t)(mt * 16 * ROWB) + kb);
                uint32_t bf[4][4];
                #pragma unroll
                for (int np = 0; np < 4; np++)
                    ldsm_x4(bf[np][0], bf[np][1], bf[np][2], bf[np][3],
                            bOp + bBase + (uint32_t)(np * 16 * ROWB) + kb);
                #pragma unroll
                for (int mt = 0; mt < 2; mt++)
                    #pragma unroll
                    for (int nt = 0; nt < 8; nt++)
                        mma16816(acc[mt][nt], af[mt],
                                 bf[nt >> 1][(nt & 1) * 2], bf[nt >> 1][(nt & 1) * 2 + 1]);
            }
        }

        if (c + 1 < nch) {
            char* dst = smem + ((c + 1) & 1) * BUFSZ;
            #pragma unroll
            for (int i = 0; i < 4; i++) {
                uint2 hi, lo;
                uint32_t off = (uint32_t)(lrow[i] * ROWB + lcol[i] * 2);
                split4(aS[i], hi, lo);
                *reinterpret_cast<uint2*>(dst + AHI_O + off) = hi;
                *reinterpret_cast<uint2*>(dst + ALO_O + off) = lo;
                split4(bS[i], hi, lo);
                *reinterpret_cast<uint2*>(dst + BHI_O + off) = hi;
                *reinterpret_cast<uint2*>(dst + BLO_O + off) = lo;
            }
        }
        __syncthreads();
    }

    const int lr  = lane >> 2;
    const int lc2 = (lane & 3) * 2;
    #pragma unroll
    for (int mt = 0; mt < 2; mt++) {
        #pragma unroll
        for (int nt = 0; nt < 8; nt++) {
            int gr = row0 + wm * 32 + mt * 16 + lr;
            int gc = col0 + wn * 64 + nt * 8 + lc2;
            if (gc < N) {
                float2 v0 = make_float2(acc[mt][nt][0] * alpha, acc[mt][nt][1] * alpha);
                float2 v1 = make_float2(acc[mt][nt][2] * alpha, acc[mt][nt][3] * alpha);
                *reinterpret_cast<float2*>(Cb + (long long)gr * ldc + gc) = v0;
                *reinterpret_cast<float2*>(Cb + (long long)(gr + 8) * ldc + gc) = v1;
            }
        }
    }
}

/* ---------------- transpose [K,N] -> [N,K] --------------------------------- */
__global__ void transpose_kernel(const float* __restrict__ in, float* __restrict__ out,
                                 int K, int N)
{
    __shared__ float t[32][33];
    int k0 = blockIdx.y * 32, n0 = blockIdx.x * 32;
    int x = threadIdx.x, y = threadIdx.y;
    #pragma unroll
    for (int i = 0; i < 32; i += 8) {
        int k = k0 + y + i, n = n0 + x;
        t[y + i][x] = (k < K && n < N) ? in[(long long)k * N + n] : 0.0f;
    }
    __syncthreads();
    #pragma unroll
    for (int i = 0; i < 32; i += 8) {
        int n = n0 + y + i, k = k0 + x;
        if (n < N && k < K) out[(long long)n * K + k] = t[x][y + i];
    }
}

/* ---------------- RMS norm -------------------------------------------------- */
__global__ __launch_bounds__(256) void rmsnorm_kernel(
    const float* __restrict__ x, const float* __restrict__ w, float* __restrict__ y,
    int n, int ldx, int ldy)
{
    int row = blockIdx.x;
    const float* xr = x + (long long)row * ldx;
    float* yr = y + (long long)row * ldy;
    int tid = threadIdx.x;
    float ss = 0.0f;
    for (int i = tid; i < n; i += 256) { float v = xr[i]; ss += v * v; }
    __shared__ float red[8];
    #pragma unroll
    for (int o = 16; o; o >>= 1) ss += __shfl_xor_sync(0xffffffffu, ss, o);
    if ((tid & 31) == 0) red[tid >> 5] = ss;
    __syncthreads();
    if (tid < 32) {
        float v = (tid < 8) ? red[tid] : 0.0f;
        #pragma unroll
        for (int o = 4; o; o >>= 1) v += __shfl_xor_sync(0xffffffffu, v, o);
        if (tid == 0) red[0] = v;
    }
    __syncthreads();
    float inv = rsqrtf(red[0] / (float)n + 1e-6f);
    for (int i = tid; i < n; i += 256) yr[i] = w[i] * xr[i] * inv;
}

/* ---------------- q rope scatter (float4) ----------------------------------- */
__global__ void qrope_kernel(const float* __restrict__ qf, const float* __restrict__ cs,
                             const float* __restrict__ sn, float* __restrict__ qfull)
{
    int idx = blockIdx.x * blockDim.x + threadIdx.x;  /* over total/4 = 3.15M */
    const int total4 = B_ * H_ * S_ * (DQK_ / 4);
    if (idx >= total4) return;
    int d4 = idx % (DQK_ / 4);
    int t = idx / (DQK_ / 4);
    int s = t % S_; t /= S_;
    int h = t % H_;
    int b = t / H_;
    int d = d4 * 4;
    const float* src = qf + (((long long)(b * S_ + s)) * H_ + h) * DQK_;
    float4 val;
    if (d < DN_) {
        val = *reinterpret_cast<const float4*>(src + d);
    } else {
        int p = d - DN_;
        float4 x = *reinterpret_cast<const float4*>(src + DN_ + p);
        float4 other;
        if (p < DR_ / 2) {
            float4 o = *reinterpret_cast<const float4*>(src + DN_ + p + DR_ / 2);
            other = make_float4(-o.x, -o.y, -o.z, -o.w);
        } else {
            other = *reinterpret_cast<const float4*>(src + DN_ + p - DR_ / 2);
        }
        long long co = ((long long)b * S_ + s) * DR_ + p;
        float4 c = *reinterpret_cast<const float4*>(cs + co);
        float4 ss2 = *reinterpret_cast<const float4*>(sn + co);
        val.x = fmaf(x.x, c.x, other.x * ss2.x);
        val.y = fmaf(x.y, c.y, other.y * ss2.y);
        val.z = fmaf(x.z, c.z, other.z * ss2.z);
        val.w = fmaf(x.w, c.w, other.w * ss2.w);
    }
    *reinterpret_cast<float4*>(qfull + (long long)idx * 4) = val;
}

__global__ void krope_kernel(const float* __restrict__ ckv, const float* __restrict__ cs,
                             const float* __restrict__ sn, float* __restrict__ kpe)
{
    int idx = blockIdx.x * blockDim.x + threadIdx.x;  /* over B*S*16 */
    if (idx >= B_ * S_ * (DR_ / 4)) return;
    int p4 = idx % (DR_ / 4);
    int bs = idx / (DR_ / 4);
    int p = p4 * 4;
    const float* src = ckv + (long long)bs * (KVLORA_ + DR_) + KVLORA_;
    float4 x = *reinterpret_cast<const float4*>(src + p);
    float4 other;
    if (p < DR_ / 2) {
        float4 o = *reinterpret_cast<const float4*>(src + p + DR_ / 2);
        other = make_float4(-o.x, -o.y, -o.z, -o.w);
    } else {
        other = *reinterpret_cast<const float4*>(src + p - DR_ / 2);
    }
    long long co = (long long)bs * DR_ + p;
    float4 c = *reinterpret_cast<const float4*>(cs + co);
    float4 ss2 = *reinterpret_cast<const float4*>(sn + co);
    float4 val;
    val.x = fmaf(x.x, c.x, other.x * ss2.x);
    val.y = fmaf(x.y, c.y, other.y * ss2.y);
    val.z = fmaf(x.z, c.z, other.z * ss2.z);
    val.w = fmaf(x.w, c.w, other.w * ss2.w);
    *reinterpret_cast<float4*>(kpe + co) = val;
}

__global__ void kbuild_kernel(const float* __restrict__ kvflat, const float* __restrict__ kpe,
                              float* __restrict__ kfull)
{
    int idx = blockIdx.x * blockDim.x + threadIdx.x;  /* over total/4 */
    const int total4 = B_ * H_ * S_ * (DQK_ / 4);
    if (idx >= total4) return;
    int d4 = idx % (DQK_ / 4);
    int t = idx / (DQK_ / 4);
    int s = t % S_; t /= S_;
    int h = t % H_;
    int b = t / H_;
    int d = d4 * 4;
    float4 val;
    if (d < DN_)
        val = *reinterpret_cast<const float4*>(
            kvflat + (((long long)(b * S_ + s)) * H_ + h) * (DN_ + DV_) + d);
    else
        val = *reinterpret_cast<const float4*>(
            kpe + ((long long)b * S_ + s) * DR_ + (d - DN_));
    *reinterpret_cast<float4*>(kfull + (long long)idx * 4) = val;
}

/* v transpose: per (b,h) [S, DV] (stride 4096) -> vT [DV, S], smem tiled */
__global__ void vbuildT_kernel(const float* __restrict__ kvflat, float* __restrict__ vT)
{
    __shared__ float t[32][33];
    int bh = blockIdx.z;
    int b = bh >> 4, h = bh & 15;
    int s0 = blockIdx.x * 32, d0 = blockIdx.y * 32;
    int x = threadIdx.x, y = threadIdx.y;
    const float* src = kvflat + ((long long)b * S_ * H_ + h) * (DN_ + DV_) + DN_;
    #pragma unroll
    for (int i = 0; i < 32; i += 8) {
        int s = s0 + y + i, d = d0 + x;
        t[y + i][x] = src[(long long)s * (H_ * (DN_ + DV_)) + d];
    }
    __syncthreads();
    float* dst = vT + ((long long)bh * DV_) * S_;
    #pragma unroll
    for (int i = 0; i < 32; i += 8) {
        int d = d0 + y + i, s = s0 + x;
        dst[(long long)d * S_ + s] = t[x][y + i];
    }
}

/* ---------------- causal softmax (FFMA exp) --------------------------------- */
__global__ __launch_bounds__(256) void softmax_kernel(float* __restrict__ wts)
{
    long long row = blockIdx.x;
    int i = (int)(row % S_);
    float* r = wts + row * (long long)S_;
    int tid = threadIdx.x;
    int nvalid = i + 1;

    float e[8];
    float mx = -1e30f;
    int cnt = 0;
    for (int j = tid; j < nvalid; j += 256) { e[cnt] = r[j]; mx = fmaxf(mx, e[cnt]); cnt++; }

    __shared__ float sm[8];
    #pragma unroll
    for (int o = 16; o; o >>= 1) mx = fmaxf(mx, __shfl_xor_sync(0xffffffffu, mx, o));
    if ((tid & 31) == 0) sm[tid >> 5] = mx;
    __syncthreads();
    if (tid < 32) {
        float v = (tid < 8) ? sm[tid] : -1e30f;
        #pragma unroll
        for (int o = 4; o; o >>= 1) v = fmaxf(v, __shfl_xor_sync(0xffffffffu, v, o));
        if (tid == 0) sm[0] = v;
    }
    __syncthreads();
    mx = sm[0];
    __syncthreads();

    float sum = 0.0f;
    cnt = 0;
    for (int j = tid; j < nvalid; j += 256) {
        float ev = fast_exp(e[cnt] - mx);
        e[cnt] = ev;
        sum += ev;
        cnt++;
    }
    #pragma unroll
    for (int o = 16; o; o >>= 1) sum += __shfl_xor_sync(0xffffffffu, sum, o);
    if ((tid & 31) == 0) sm[tid >> 5] = sum;
    __syncthreads();
    if (tid < 32) {
        float v = (tid < 8) ? sm[tid] : 0.0f;
        #pragma unroll
        for (int o = 4; o; o >>= 1) v += __shfl_xor_sync(0xffffffffu, v, o);
        if (tid == 0) sm[0] = v;
    }
    __syncthreads();
    float inv = 1.0f / sm[0];

    cnt = 0;
    for (int j = tid; j < nvalid; j += 256) { r[j] = e[cnt] * inv; cnt++; }
    for (int j = nvalid + tid; j < S_; j += 256) r[j] = 0.0f;
}

/* ---------------- host ------------------------------------------------------ */
static inline void mma_gemm(const float* A, const float* Bm, float* C,
                            int M, int N, int K, int lda, int ldb, int ldc,
                            long long sA, long long sB,
                            int zdiv, long long csOut, long long csIn,
                            float alpha, int causalSkip, int causalK, int batch)
{
    dim3 grid((N + 127) / 128, (M + 127) / 128, batch);
    mma_gemm_kernel<<<grid, 256, GEMM_SMEM>>>(A, Bm, C, M, N, K, lda, ldb, ldc,
                                              sA, sB, zdiv, csOut, csIn,
                                              alpha, causalSkip, causalK);
}

extern "C" void kernel_launch(void* const* d_in, const int* in_sizes, int n_in,
                              void* d_out, int out_size)
{
    const float* hs      = (const float*)d_in[0];
    const float* cs      = (const float*)d_in[1];
    const float* sn      = (const float*)d_in[2];
    const float* q_a_w   = (const float*)d_in[4];
    const float* q_a_ln  = (const float*)d_in[5];
    const float* q_b_w   = (const float*)d_in[6];
    const float* kv_a_w  = (const float*)d_in[7];
    const float* kv_a_ln = (const float*)d_in[8];
    const float* kv_b_w  = (const float*)d_in[9];
    const float* o_w     = (const float*)d_in[10];

    float* out = (float*)d_out;
    float* wts = out + (long long)B_ * S_ * HID_;

    static bool attr_set = false;
    if (!attr_set) {
        cudaFuncSetAttribute(mma_gemm_kernel, cudaFuncAttributeMaxDynamicSharedMemorySize, GEMM_SMEM);
        attr_set = true;
    }

    float *qlat, *qflat, *qfull, *ckv, *kc, *kpe, *kvflat, *kfull, *vT, *omid;
    float *wqaT, *wqbT, *wkvaT, *wkvbT, *woT;
    cudaGetSymbolAddress((void**)&qlat,   g_qlat);
    cudaGetSymbolAddress((void**)&qflat,  g_qflat);
    cudaGetSymbolAddress((void**)&qfull,  g_qfull);
    cudaGetSymbolAddress((void**)&ckv,    g_ckv);
    cudaGetSymbolAddress((void**)&kc,     g_kc);
    cudaGetSymbolAddress((void**)&kpe,    g_kpe);
    cudaGetSymbolAddress((void**)&kvflat, g_kvflat);
    cudaGetSymbolAddress((void**)&kfull,  g_kfull);
    cudaGetSymbolAddress((void**)&vT,     g_vT);
    cudaGetSymbolAddress((void**)&omid,   g_omid);
    cudaGetSymbolAddress((void**)&wqaT,   g_wqaT);
    cudaGetSymbolAddress((void**)&wqbT,   g_wqbT);
    cudaGetSymbolAddress((void**)&wkvaT,  g_wkvaT);
    cudaGetSymbolAddress((void**)&wkvbT,  g_wkvbT);
    cudaGetSymbolAddress((void**)&woT,    g_woT);

    dim3 tb(32, 8);
    /* order chosen so in-call launch index 3 = q_a GEMM (gets profiled by ncu -s) */
    /* 0 */ transpose_kernel<<<dim3(QLORA_ / 32, HID_ / 32), tb>>>(q_a_w, wqaT, HID_, QLORA_);
    /* 1 */ transpose_kernel<<<dim3((KVLORA_ + DR_) / 32, HID_ / 32), tb>>>(kv_a_w, wkvaT, HID_, KVLORA_ + DR_);
    /* 2 */ mma_gemm(hs, wkvaT, ckv, NTOK_, KVLORA_ + DR_, HID_, HID_, HID_, KVLORA_ + DR_,
                     0, 0, 1, 0, 0, 1.0f, 0, 0, 1);
    /* 3 */ mma_gemm(hs, wqaT, qlat, NTOK_, QLORA_, HID_, HID_, HID_, QLORA_,
                     0, 0, 1, 0, 0, 1.0f, 0, 0, 1);
    /* 4 */ rmsnorm_kernel<<<NTOK_, 256>>>(qlat, q_a_ln, qlat, QLORA_, QLORA_, QLORA_);
    /* 5 */ transpose_kernel<<<dim3(H_ * DQK_ / 32, QLORA_ / 32), tb>>>(q_b_w, wqbT, QLORA_, H_ * DQK_);
    /* 6 */ mma_gemm(qlat, wqbT, qflat, NTOK_, H_ * DQK_, QLORA_, QLORA_, QLORA_, H_ * DQK_,
                     0, 0, 1, 0, 0, 1.0f, 0, 0, 1);
    /* 7 */ {
        int total4 = B_ * H_ * S_ * (DQK_ / 4);
        qrope_kernel<<<(total4 + 255) / 256, 256>>>(qflat, cs, sn, qfull);
    }
    /* 8 */ rmsnorm_kernel<<<NTOK_, 256>>>(ckv, kv_a_ln, kc, KVLORA_, KVLORA_ + DR_, KVLORA_);
    /* 9 */ krope_kernel<<<(B_ * S_ * (DR_ / 4) + 255) / 256, 256>>>(ckv, cs, sn, kpe);
    /* 10 */ transpose_kernel<<<dim3(H_ * (DN_ + DV_) / 32, KVLORA_ / 32), tb>>>(kv_b_w, wkvbT, KVLORA_, H_ * (DN_ + DV_));
    /* 11 */ mma_gemm(kc, wkvbT, kvflat, NTOK_, H_ * (DN_ + DV_), KVLORA_,
                      KVLORA_, KVLORA_, H_ * (DN_ + DV_),
                      0, 0, 1, 0, 0, 1.0f, 0, 0, 1);
    /* 12 */ {
        int total4 = B_ * H_ * S_ * (DQK_ / 4);
        kbuild_kernel<<<(total4 + 255) / 256, 256>>>(kvflat, kpe, kfull);
    }
    /* 13 */ vbuildT_kernel<<<dim3(S_ / 32, DV_ / 32, B_ * H_), tb>>>(kvflat, vT);
    /* 14 */ mma_gemm(qfull, kfull, wts, S_, S_, DQK_, DQK_, DQK_, S_,
                      (long long)S_ * DQK_, (long long)S_ * DQK_,
                      1, (long long)S_ * S_, 0,
                      SCALING_, 1, 0, B_ * H_);
    /* 15 */ softmax_kernel<<<B_ * H_ * S_, 256>>>(wts);
    /* 16 */ mma_gemm(wts, vT, omid, S_, DV_, S_, S_, S_, H_ * DV_,
                      (long long)S_ * S_, (long long)DV_ * S_,
                      H_, (long long)S_ * H_ * DV_, (long long)DV_,
                      1.0f, 0, 1, B_ * H_);
    /* 17 */ transpose_kernel<<<dim3(HID_ / 32, (H_ * DV_) / 32), tb>>>(o_w, woT, H_ * DV_, HID_);
    /* 18 */ mma_gemm(omid, woT, out, NTOK_, HID_, H_ * DV_, H_ * DV_, H_ * DV_, HID_,
                      0, 0, 1, 0, 0, 1.0f, 0, 0, 1);
}

// round 5
// speedup vs baseline: 2.4955x; 1.1100x over previous
#include <cuda_runtime.h>
#include <cuda_bf16.h>
#include <math.h>
#include <stdint.h>

#define B_      2
#define S_      2048
#define HID_    2048
#define H_      16
#define QLORA_  1536
#define KVLORA_ 512
#define DR_     64
#define DN_     128
#define DQK_    192
#define DV_     128
#define NTOK_   (B_*S_)
#define SCALING_ 0.07216878364870322f

typedef __nv_bfloat16 bf16;

/* ------------------------------- scratch ---------------------------------- */
__device__ bf16  g_hs_hi [NTOK_*HID_];
__device__ bf16  g_hs_lo [NTOK_*HID_];
__device__ float g_qlat  [NTOK_*QLORA_];
__device__ bf16  g_qlatn_hi[NTOK_*QLORA_];
__device__ bf16  g_qlatn_lo[NTOK_*QLORA_];
__device__ float g_qflat [NTOK_*H_*DQK_];
__device__ bf16  g_qfull_hi[B_*H_*S_*DQK_];
__device__ bf16  g_qfull_lo[B_*H_*S_*DQK_];
__device__ float g_ckv   [NTOK_*(KVLORA_+DR_)];
__device__ bf16  g_kc_hi [NTOK_*KVLORA_];
__device__ bf16  g_kc_lo [NTOK_*KVLORA_];
__device__ float g_kpe   [B_*S_*DR_];
__device__ float g_kvflat[NTOK_*H_*(DN_+DV_)];
__device__ bf16  g_kfull_hi[B_*H_*S_*DQK_];
__device__ bf16  g_kfull_lo[B_*H_*S_*DQK_];
__device__ bf16  g_vT_hi [B_*H_*DV_*S_];
__device__ bf16  g_vT_lo [B_*H_*DV_*S_];
__device__ bf16  g_w_hi  [(long long)B_*H_*S_*S_];
__device__ bf16  g_w_lo  [(long long)B_*H_*S_*S_];
__device__ bf16  g_omid_hi[NTOK_*H_*DV_];
__device__ bf16  g_omid_lo[NTOK_*H_*DV_];
__device__ bf16  g_wqaT_hi [QLORA_*HID_];
__device__ bf16  g_wqaT_lo [QLORA_*HID_];
__device__ bf16  g_wqbT_hi [H_*DQK_*QLORA_];
__device__ bf16  g_wqbT_lo [H_*DQK_*QLORA_];
__device__ bf16  g_wkvaT_hi[(KVLORA_+DR_)*HID_];
__device__ bf16  g_wkvaT_lo[(KVLORA_+DR_)*HID_];
__device__ bf16  g_wkvbT_hi[H_*(DN_+DV_)*KVLORA_];
__device__ bf16  g_wkvbT_lo[H_*(DN_+DV_)*KVLORA_];
__device__ bf16  g_woT_hi  [HID_*H_*DV_];
__device__ bf16  g_woT_lo  [HID_*H_*DV_];

/* --------------------------- helpers --------------------------------------- */
__device__ __forceinline__ uint32_t smem_u32(const void* p) {
    uint32_t a;
    asm("{ .reg .u64 t; cvta.to.shared.u64 t, %1; cvt.u32.u64 %0, t; }" : "=r"(a) : "l"(p));
    return a;
}
__device__ __forceinline__ void ldsm_x4(uint32_t& r0, uint32_t& r1, uint32_t& r2, uint32_t& r3,
                                        uint32_t addr) {
    asm volatile("ldmatrix.sync.aligned.m8n8.x4.shared.b16 {%0,%1,%2,%3}, [%4];"
                 : "=r"(r0), "=r"(r1), "=r"(r2), "=r"(r3) : "r"(addr));
}
__device__ __forceinline__ void mma16816(float* c, const uint32_t* a, uint32_t b0, uint32_t b1) {
    asm volatile("mma.sync.aligned.m16n8k16.row.col.f32.bf16.bf16.f32 "
                 "{%0,%1,%2,%3}, {%4,%5,%6,%7}, {%8,%9}, {%0,%1,%2,%3};"
                 : "+f"(c[0]), "+f"(c[1]), "+f"(c[2]), "+f"(c[3])
                 : "r"(a[0]), "r"(a[1]), "r"(a[2]), "r"(a[3]), "r"(b0), "r"(b1));
}
__device__ __forceinline__ void cpa16(uint32_t dst, const void* src, uint32_t nbytes) {
    asm volatile("cp.async.cg.shared.global [%0], [%1], 16, %2;"
                 :: "r"(dst), "l"(src), "r"(nbytes) : "memory");
}
#define CP_COMMIT() asm volatile("cp.async.commit_group;" ::: "memory")
#define CP_WAIT2()  asm volatile("cp.async.wait_group 2;" ::: "memory")

/* split 4 floats into packed 4xbf16 hi (uint2) and lo (uint2) */
__device__ __forceinline__ void split4v(float4 v, uint2& hi, uint2& lo) {
    float f[4] = {v.x, v.y, v.z, v.w};
    unsigned short h[4], l[4];
    #pragma unroll
    for (int i = 0; i < 4; i++) {
        bf16 hb = __float2bfloat16(f[i]);
        bf16 lb = __float2bfloat16(f[i] - __bfloat162float(hb));
        h[i] = *(unsigned short*)&hb;
        l[i] = *(unsigned short*)&lb;
    }
    hi.x = (uint32_t)h[0] | ((uint32_t)h[1] << 16);
    hi.y = (uint32_t)h[2] | ((uint32_t)h[3] << 16);
    lo.x = (uint32_t)l[0] | ((uint32_t)l[1] << 16);
    lo.y = (uint32_t)l[2] | ((uint32_t)l[3] << 16);
}

/* FFMA-only exp */
__device__ __forceinline__ float fast_exp(float x) {
    float t = x * 1.4426950408889634f;
    float r = rintf(t);
    float f = t - r;
    float p =          1.339887440266574e-3f;
    p = fmaf(p, f,     9.618437357674640e-3f);
    p = fmaf(p, f,     5.550332471162809e-2f);
    p = fmaf(p, f,     2.402264791363012e-1f);
    p = fmaf(p, f,     6.931472028550421e-1f);
    p = fmaf(p, f,     1.0f);
    int ri = (int)r;
    if (ri < -126) ri = -126;
    float s = __int_as_float((uint32_t)(ri + 127) << 23);
    return p * s;
}

/* smem: per stage 4 operand tiles of 128 rows x 32 bf16, rows padded to 80B */
#define ROWB   80
#define AHI_O  0
#define ALO_O  10240
#define BHI_O  20480
#define BLO_O  30720
#define STGSZ  40960
#define NSTG   4
#define GEMM_SMEM (NSTG*STGSZ)

/* --------------------------- bf16 HMMA GEMM, cp.async 4-stage -------------- */
/* C = alpha * (Ahi+Alo)[M,K] @ (Bhi+Blo)[N,K]^T  (3-pass compensated)        */
__global__ __launch_bounds__(256, 1) void mma_gemm2_kernel(
    const bf16* __restrict__ Ahi, const bf16* __restrict__ Alo,
    const bf16* __restrict__ Bhi, const bf16* __restrict__ Blo,
    float* __restrict__ Cf, bf16* __restrict__ Chi, bf16* __restrict__ Clo,
    int M, int N, int K, int lda, int ldb, int ldc,
    long long sA, long long sB, int zdiv, long long csOut, long long csIn,
    float alpha, int causalSkip, int causalK)
{
    const int row0 = blockIdx.y * 128;
    const int col0 = blockIdx.x * 128;
    if (causalSkip && col0 > row0 + 127) return;
    const int bz = blockIdx.z;
    const bf16* Ah = Ahi + (long long)bz * sA;
    const bf16* Al = Alo + (long long)bz * sA;
    const bf16* Bh = Bhi + (long long)bz * sB;
    const bf16* Bl = Blo + (long long)bz * sB;
    const long long coff = (long long)(bz / zdiv) * csOut + (long long)(bz % zdiv) * csIn;

    extern __shared__ __align__(16) char smem[];
    const uint32_t sb = smem_u32(smem);

    const int tid  = threadIdx.x;
    const int wid  = tid >> 5;
    const int lane = tid & 31;
    const int wm = wid & 3;
    const int wn = wid >> 2;
    const int laneIn = lane & 7;
    const int quad   = lane >> 3;

    const uint32_t aBase = (uint32_t)((wm * 32 + laneIn + (quad & 1) * 8) * ROWB
                                      + ((quad >> 1) * 8) * 2);
    const uint32_t bBase = (uint32_t)((wn * 64 + laneIn + (quad >> 1) * 8) * ROWB
                                      + ((quad & 1) * 8) * 2);

    int kend = K;
    if (causalK) { int kl = row0 + 128; if (kl < kend) kend = kl; }
    const int nch = kend >> 5;

    float acc[2][8][4];
    #pragma unroll
    for (int i = 0; i < 2; i++)
        #pragma unroll
        for (int j = 0; j < 8; j++)
            #pragma unroll
            for (int q = 0; q < 4; q++) acc[i][j][q] = 0.0f;

    /* per-thread load coords: 2 iterations x (row, 16B-seg) */
    const int r0t  = tid >> 2;
    const int sg0  = tid & 3;

    auto issue = [&](int s) {
        const uint32_t dst = sb + (uint32_t)(s & (NSTG - 1)) * STGSZ;
        const int k0 = s << 5;
        #pragma unroll
        for (int i = 0; i < 2; i++) {
            const int r  = r0t + i * 64;
            const int sg = sg0;
            const uint32_t so = (uint32_t)(r * ROWB + sg * 16);
            const long long ak = (long long)(row0 + r) * lda + k0 + sg * 8;
            cpa16(dst + AHI_O + so, Ah + ak, 16);
            cpa16(dst + ALO_O + so, Al + ak, 16);
            const int brow = col0 + r;
            const uint32_t bb = (brow < N) ? 16u : 0u;
            const int brc = (brow < N) ? brow : (N > 0 ? N - 1 : 0);
            const long long bk = (long long)brc * ldb + k0 + sg * 8;
            cpa16(dst + BHI_O + so, Bh + bk, bb);
            cpa16(dst + BLO_O + so, Bl + bk, bb);
        }
    };

    /* prologue: 3 stages ahead */
    #pragma unroll
    for (int s = 0; s < NSTG - 1; s++) {
        if (s < nch) issue(s);
        CP_COMMIT();
    }

    for (int c = 0; c < nch; c++) {
        CP_WAIT2();
        __syncthreads();
        if (c + NSTG - 1 < nch) issue(c + NSTG - 1);
        CP_COMMIT();

        const uint32_t bufb = sb + (uint32_t)(c & (NSTG - 1)) * STGSZ;
        #pragma unroll
        for (int p = 0; p < 3; p++) {
            const uint32_t aOp = bufb + (p == 2 ? ALO_O : AHI_O);
            const uint32_t bOp = bufb + (p == 1 ? BLO_O : BHI_O);
            #pragma unroll
            for (int ks = 0; ks < 2; ks++) {
                const uint32_t kb = (uint32_t)(ks * 16 * 2);
                uint32_t af[2][4];
                #pragma unroll
                for (int mt = 0; mt < 2; mt++)
                    ldsm_x4(af[mt][0], af[mt][1], af[mt][2], af[mt][3],
                            aOp + aBase + (uint32_t)(mt * 16 * ROWB) + kb);
                uint32_t bf[4][4];
                #pragma unroll
                for (int np = 0; np < 4; np++)
                    ldsm_x4(bf[np][0], bf[np][1], bf[np][2], bf[np][3],
                            bOp + bBase + (uint32_t)(np * 16 * ROWB) + kb);
                #pragma unroll
                for (int mt = 0; mt < 2; mt++)
                    #pragma unroll
                    for (int nt = 0; nt < 8; nt++)
                        mma16816(acc[mt][nt], af[mt],
                                 bf[nt >> 1][(nt & 1) * 2], bf[nt >> 1][(nt & 1) * 2 + 1]);
            }
        }
    }

    /* epilogue */
    const int lr  = lane >> 2;
    const int lc2 = (lane & 3) * 2;
    #pragma unroll
    for (int mt = 0; mt < 2; mt++) {
        #pragma unroll
        for (int nt = 0; nt < 8; nt++) {
            const int gr = row0 + wm * 32 + mt * 16 + lr;
            const int gc = col0 + wn * 64 + nt * 8 + lc2;
            if (gc >= N) continue;
            float a0 = acc[mt][nt][0] * alpha, a1 = acc[mt][nt][1] * alpha;
            float a2 = acc[mt][nt][2] * alpha, a3 = acc[mt][nt][3] * alpha;
            const long long o0 = coff + (long long)gr * ldc + gc;
            const long long o1 = coff + (long long)(gr + 8) * ldc + gc;
            if (Cf) {
                *reinterpret_cast<float2*>(Cf + o0) = make_float2(a0, a1);
                *reinterpret_cast<float2*>(Cf + o1) = make_float2(a2, a3);
            }
            if (Chi) {
                bf16 h0 = __float2bfloat16(a0), h1 = __float2bfloat16(a1);
                bf16 h2 = __float2bfloat16(a2), h3 = __float2bfloat16(a3);
                __nv_bfloat162 hv0; hv0.x = h0; hv0.y = h1;
                __nv_bfloat162 hv1; hv1.x = h2; hv1.y = h3;
                *reinterpret_cast<__nv_bfloat162*>(Chi + o0) = hv0;
                *reinterpret_cast<__nv_bfloat162*>(Chi + o1) = hv1;
                __nv_bfloat162 lv0, lv1;
                lv0.x = __float2bfloat16(a0 - __bfloat162float(h0));
                lv0.y = __float2bfloat16(a1 - __bfloat162float(h1));
                lv1.x = __float2bfloat16(a2 - __bfloat162float(h2));
                lv1.y = __float2bfloat16(a3 - __bfloat162float(h3));
                *reinterpret_cast<__nv_bfloat162*>(Clo + o0) = lv0;
                *reinterpret_cast<__nv_bfloat162*>(Clo + o1) = lv1;
            }
        }
    }
}

/* ---------------- split fp32 -> hi/lo bf16 ---------------------------------- */
__global__ void split_kernel(const float* __restrict__ x, bf16* __restrict__ hi,
                             bf16* __restrict__ lo, int n4)
{
    int idx = blockIdx.x * blockDim.x + threadIdx.x;
    if (idx >= n4) return;
    float4 v = reinterpret_cast<const float4*>(x)[idx];
    uint2 h, l;
    split4v(v, h, l);
    reinterpret_cast<uint2*>(hi)[idx] = h;
    reinterpret_cast<uint2*>(lo)[idx] = l;
}

/* ---------------- transpose [K,N] fp32 -> [N,K] hi/lo bf16 ------------------ */
__global__ void transpose_split_kernel(const float* __restrict__ in,
                                       bf16* __restrict__ outHi, bf16* __restrict__ outLo,
                                       int K, int N)
{
    __shared__ float t[32][33];
    int k0 = blockIdx.y * 32, n0 = blockIdx.x * 32;
    int x = threadIdx.x, y = threadIdx.y;
    #pragma unroll
    for (int i = 0; i < 32; i += 8) {
        int k = k0 + y + i, n = n0 + x;
        t[y + i][x] = (k < K && n < N) ? in[(long long)k * N + n] : 0.0f;
    }
    __syncthreads();
    #pragma unroll
    for (int i = 0; i < 32; i += 8) {
        int n = n0 + y + i, k = k0 + x;
        if (n < N && k < K) {
            float v = t[x][y + i];
            bf16 hb = __float2bfloat16(v);
            outHi[(long long)n * K + k] = hb;
            outLo[(long long)n * K + k] = __float2bfloat16(v - __bfloat162float(hb));
        }
    }
}

/* ---------------- RMS norm -> hi/lo ----------------------------------------- */
__global__ __launch_bounds__(256) void rmsnorm_split_kernel(
    const float* __restrict__ x, const float* __restrict__ w,
    bf16* __restrict__ yh, bf16* __restrict__ yl, int n, int ldx, int ldy)
{
    int row = blockIdx.x;
    const float* xr = x + (long long)row * ldx;
    int tid = threadIdx.x;
    float ss = 0.0f;
    for (int i = tid; i < n; i += 256) { float v = xr[i]; ss += v * v; }
    __shared__ float red[8];
    #pragma unroll
    for (int o = 16; o; o >>= 1) ss += __shfl_xor_sync(0xffffffffu, ss, o);
    if ((tid & 31) == 0) red[tid >> 5] = ss;
    __syncthreads();
    if (tid < 32) {
        float v = (tid < 8) ? red[tid] : 0.0f;
        #pragma unroll
        for (int o = 4; o; o >>= 1) v += __shfl_xor_sync(0xffffffffu, v, o);
        if (tid == 0) red[0] = v;
    }
    __syncthreads();
    float inv = rsqrtf(red[0] / (float)n + 1e-6f);
    bf16* yhr = yh + (long long)row * ldy;
    bf16* ylr = yl + (long long)row * ldy;
    for (int i = tid; i < n; i += 256) {
        float v = w[i] * xr[i] * inv;
        bf16 hb = __float2bfloat16(v);
        yhr[i] = hb;
        ylr[i] = __float2bfloat16(v - __bfloat162float(hb));
    }
}

/* ---------------- q rope -> qfull hi/lo -------------------------------------- */
__global__ void qrope_split_kernel(const float* __restrict__ qf, const float* __restrict__ cs,
                                   const float* __restrict__ sn,
                                   bf16* __restrict__ oh, bf16* __restrict__ ol)
{
    int idx = blockIdx.x * blockDim.x + threadIdx.x;
    const int total4 = B_ * H_ * S_ * (DQK_ / 4);
    if (idx >= total4) return;
    int d4 = idx % (DQK_ / 4);
    int t = idx / (DQK_ / 4);
    int s = t % S_; t /= S_;
    int h = t % H_;
    int b = t / H_;
    int d = d4 * 4;
    const float* src = qf + (((long long)(b * S_ + s)) * H_ + h) * DQK_;
    float4 val;
    if (d < DN_) {
        val = *reinterpret_cast<const float4*>(src + d);
    } else {
        int p = d - DN_;
        float4 x = *reinterpret_cast<const float4*>(src + DN_ + p);
        float4 other;
        if (p < DR_ / 2) {
            float4 o = *reinterpret_cast<const float4*>(src + DN_ + p + DR_ / 2);
            other = make_float4(-o.x, -o.y, -o.z, -o.w);
        } else {
            other = *reinterpret_cast<const float4*>(src + DN_ + p - DR_ / 2);
        }
        long long co = ((long long)b * S_ + s) * DR_ + p;
        float4 c = *reinterpret_cast<const float4*>(cs + co);
        float4 ss2 = *reinterpret_cast<const float4*>(sn + co);
        val.x = fmaf(x.x, c.x, other.x * ss2.x);
        val.y = fmaf(x.y, c.y, other.y * ss2.y);
        val.z = fmaf(x.z, c.z, other.z * ss2.z);
        val.w = fmaf(x.w, c.w, other.w * ss2.w);
    }
    uint2 hh, ll;
    split4v(val, hh, ll);
    reinterpret_cast<uint2*>(oh)[idx] = hh;
    reinterpret_cast<uint2*>(ol)[idx] = ll;
}

__global__ void krope_kernel(const float* __restrict__ ckv, const float* __restrict__ cs,
                             const float* __restrict__ sn, float* __restrict__ kpe)
{
    int idx = blockIdx.x * blockDim.x + threadIdx.x;
    if (idx >= B_ * S_ * (DR_ / 4)) return;
    int p4 = idx % (DR_ / 4);
    int bs = idx / (DR_ / 4);
    int p = p4 * 4;
    const float* src = ckv + (long long)bs * (KVLORA_ + DR_) + KVLORA_;
    float4 x = *reinterpret_cast<const float4*>(src + p);
    float4 other;
    if (p < DR_ / 2) {
        float4 o = *reinterpret_cast<const float4*>(src + p + DR_ / 2);
        other = make_float4(-o.x, -o.y, -o.z, -o.w);
    } else {
        other = *reinterpret_cast<const float4*>(src + p - DR_ / 2);
    }
    long long co = (long long)bs * DR_ + p;
    float4 c = *reinterpret_cast<const float4*>(cs + co);
    float4 ss2 = *reinterpret_cast<const float4*>(sn + co);
    float4 val;
    val.x = fmaf(x.x, c.x, other.x * ss2.x);
    val.y = fmaf(x.y, c.y, other.y * ss2.y);
    val.z = fmaf(x.z, c.z, other.z * ss2.z);
    val.w = fmaf(x.w, c.w, other.w * ss2.w);
    *reinterpret_cast<float4*>(kpe + co) = val;
}

__global__ void kbuild_split_kernel(const float* __restrict__ kvflat, const float* __restrict__ kpe,
                                    bf16* __restrict__ oh, bf16* __restrict__ ol)
{
    int idx = blockIdx.x * blockDim.x + threadIdx.x;
    const int total4 = B_ * H_ * S_ * (DQK_ / 4);
    if (idx >= total4) return;
    int d4 = idx % (DQK_ / 4);
    int t = idx / (DQK_ / 4);
    int s = t % S_; t /= S_;
    int h = t % H_;
    int b = t / H_;
    int d = d4 * 4;
    float4 val;
    if (d < DN_)
        val = *reinterpret_cast<const float4*>(
            kvflat + (((long long)(b * S_ + s)) * H_ + h) * (DN_ + DV_) + d);
    else
        val = *reinterpret_cast<const float4*>(
            kpe + ((long long)b * S_ + s) * DR_ + (d - DN_));
    uint2 hh, ll;
    split4v(val, hh, ll);
    reinterpret_cast<uint2*>(oh)[idx] = hh;
    reinterpret_cast<uint2*>(ol)[idx] = ll;
}

/* v transpose -> vT hi/lo [b,h,d,s] */
__global__ void vbuildT_split_kernel(const float* __restrict__ kvflat,
                                     bf16* __restrict__ oh, bf16* __restrict__ ol)
{
    __shared__ float t[32][33];
    int bh = blockIdx.z;
    int b = bh >> 4, h = bh & 15;
    int s0 = blockIdx.x * 32, d0 = blockIdx.y * 32;
    int x = threadIdx.x, y = threadIdx.y;
    const float* src = kvflat + ((long long)b * S_ * H_ + h) * (DN_ + DV_) + DN_;
    #pragma unroll
    for (int i = 0; i < 32; i += 8) {
        int s = s0 + y + i, d = d0 + x;
        t[y + i][x] = src[(long long)s * (H_ * (DN_ + DV_)) + d];
    }
    __syncthreads();
    long long base = ((long long)bh * DV_) * S_;
    #pragma unroll
    for (int i = 0; i < 32; i += 8) {
        int d = d0 + y + i, s = s0 + x;
        float v = t[x][y + i];
        bf16 hb = __float2bfloat16(v);
        oh[base + (long long)d * S_ + s] = hb;
        ol[base + (long long)d * S_ + s] = __float2bfloat16(v - __bfloat162float(hb));
    }
}

/* ---------------- causal softmax: fp32 out + hi/lo bf16 out ------------------ */
__global__ __launch_bounds__(256) void softmax_kernel(float* __restrict__ wts,
                                                      bf16* __restrict__ wh,
                                                      bf16* __restrict__ wl)
{
    long long row = blockIdx.x;
    int i = (int)(row % S_);
    float* r = wts + row * (long long)S_;
    bf16* rh = wh + row * (long long)S_;
    bf16* rl = wl + row * (long long)S_;
    int tid = threadIdx.x;
    int nvalid = i + 1;

    float e[8];
    float mx = -1e30f;
    int cnt = 0;
    for (int j = tid; j < nvalid; j += 256) { e[cnt] = r[j]; mx = fmaxf(mx, e[cnt]); cnt++; }

    __shared__ float sm[8];
    #pragma unroll
    for (int o = 16; o; o >>= 1) mx = fmaxf(mx, __shfl_xor_sync(0xffffffffu, mx, o));
    if ((tid & 31) == 0) sm[tid >> 5] = mx;
    __syncthreads();
    if (tid < 32) {
        float v = (tid < 8) ? sm[tid] : -1e30f;
        #pragma unroll
        for (int o = 4; o; o >>= 1) v = fmaxf(v, __shfl_xor_sync(0xffffffffu, v, o));
        if (tid == 0) sm[0] = v;
    }
    __syncthreads();
    mx = sm[0];
    __syncthreads();

    float sum = 0.0f;
    cnt = 0;
    for (int j = tid; j < nvalid; j += 256) {
        float ev = fast_exp(e[cnt] - mx);
        e[cnt] = ev;
        sum += ev;
        cnt++;
    }
    #pragma unroll
    for (int o = 16; o; o >>= 1) sum += __shfl_xor_sync(0xffffffffu, sum, o);
    if ((tid & 31) == 0) sm[tid >> 5] = sum;
    __syncthreads();
    if (tid < 32) {
        float v = (tid < 8) ? sm[tid] : 0.0f;
        #pragma unroll
        for (int o = 4; o; o >>= 1) v += __shfl_xor_sync(0xffffffffu, v, o);
        if (tid == 0) sm[0] = v;
    }
    __syncthreads();
    float inv = 1.0f / sm[0];

    cnt = 0;
    for (int j = tid; j < nvalid; j += 256) {
        float v = e[cnt] * inv;
        r[j] = v;
        bf16 hb = __float2bfloat16(v);
        rh[j] = hb;
        rl[j] = __float2bfloat16(v - __bfloat162float(hb));
        cnt++;
    }
    bf16 z = __float2bfloat16(0.0f);
    for (int j = nvalid + tid; j < S_; j += 256) { r[j] = 0.0f; rh[j] = z; rl[j] = z; }
}

/* ---------------- host ------------------------------------------------------ */
static inline void mma_gemm(const bf16* Ah, const bf16* Al, const bf16* Bh, const bf16* Bl,
                            float* Cf, bf16* Chi, bf16* Clo,
                            int M, int N, int K, int lda, int ldb, int ldc,
                            long long sA, long long sB,
                            int zdiv, long long csOut, long long csIn,
                            float alpha, int causalSkip, int causalK, int batch)
{
    dim3 grid((N + 127) / 128, (M + 127) / 128, batch);
    mma_gemm2_kernel<<<grid, 256, GEMM_SMEM>>>(Ah, Al, Bh, Bl, Cf, Chi, Clo,
                                               M, N, K, lda, ldb, ldc,
                                               sA, sB, zdiv, csOut, csIn,
                                               alpha, causalSkip, causalK);
}

extern "C" void kernel_launch(void* const* d_in, const int* in_sizes, int n_in,
                              void* d_out, int out_size)
{
    const float* hs      = (const float*)d_in[0];
    const float* cs      = (const float*)d_in[1];
    const float* sn      = (const float*)d_in[2];
    const float* q_a_w   = (const float*)d_in[4];
    const float* q_a_ln  = (const float*)d_in[5];
    const float* q_b_w   = (const float*)d_in[6];
    const float* kv_a_w  = (const float*)d_in[7];
    const float* kv_a_ln = (const float*)d_in[8];
    const float* kv_b_w  = (const float*)d_in[9];
    const float* o_w     = (const float*)d_in[10];

    float* out = (float*)d_out;
    float* wts = out + (long long)B_ * S_ * HID_;

    static bool attr_set = false;
    if (!attr_set) {
        cudaFuncSetAttribute(mma_gemm2_kernel, cudaFuncAttributeMaxDynamicSharedMemorySize, GEMM_SMEM);
        attr_set = true;
    }

#define GETSYM(p, s) cudaGetSymbolAddress((void**)&p, s)
    bf16 *hsh, *hsl, *qlnh, *qlnl, *qfh, *qfl, *kch, *kcl, *kfh, *kfl, *vth, *vtl;
    bf16 *whi, *wlo, *omh, *oml;
    bf16 *wqah, *wqal, *wqbh, *wqbl, *wkah, *wkal, *wkbh, *wkbl, *woh, *wol;
    float *qlat, *qflat, *ckv, *kpe, *kvflat;
    GETSYM(hsh, g_hs_hi);   GETSYM(hsl, g_hs_lo);
    GETSYM(qlat, g_qlat);   GETSYM(qlnh, g_qlatn_hi); GETSYM(qlnl, g_qlatn_lo);
    GETSYM(qflat, g_qflat); GETSYM(qfh, g_qfull_hi);  GETSYM(qfl, g_qfull_lo);
    GETSYM(ckv, g_ckv);     GETSYM(kch, g_kc_hi);     GETSYM(kcl, g_kc_lo);
    GETSYM(kpe, g_kpe);     GETSYM(kvflat, g_kvflat);
    GETSYM(kfh, g_kfull_hi);GETSYM(kfl, g_kfull_lo);
    GETSYM(vth, g_vT_hi);   GETSYM(vtl, g_vT_lo);
    GETSYM(whi, g_w_hi);    GETSYM(wlo, g_w_lo);
    GETSYM(omh, g_omid_hi); GETSYM(oml, g_omid_lo);
    GETSYM(wqah, g_wqaT_hi); GETSYM(wqal, g_wqaT_lo);
    GETSYM(wqbh, g_wqbT_hi); GETSYM(wqbl, g_wqbT_lo);
    GETSYM(wkah, g_wkvaT_hi); GETSYM(wkal, g_wkvaT_lo);
    GETSYM(wkbh, g_wkvbT_hi); GETSYM(wkbl, g_wkvbT_lo);
    GETSYM(woh, g_woT_hi);  GETSYM(wol, g_woT_lo);
#undef GETSYM

    dim3 tb(32, 8);
    /* 0 */ transpose_split_kernel<<<dim3(QLORA_ / 32, HID_ / 32), tb>>>(q_a_w, wqah, wqal, HID_, QLORA_);
    /* 1 */ split_kernel<<<(NTOK_ * HID_ / 4 + 255) / 256, 256>>>(hs, hsh, hsl, NTOK_ * HID_ / 4);
    /* 2 */ transpose_split_kernel<<<dim3((KVLORA_ + DR_) / 32, HID_ / 32), tb>>>(kv_a_w, wkah, wkal, HID_, KVLORA_ + DR_);
    /* 3 q_a (profiled) */
    mma_gemm(hsh, hsl, wqah, wqal, qlat, 0, 0,
             NTOK_, QLORA_, HID_, HID_, HID_, QLORA_,
             0, 0, 1, 0, 0, 1.0f, 0, 0, 1);
    /* 4 kv_a */
    mma_gemm(hsh, hsl, wkah, wkal, ckv, 0, 0,
             NTOK_, KVLORA_ + DR_, HID_, HID_, HID_, KVLORA_ + DR_,
             0, 0, 1, 0, 0, 1.0f, 0, 0, 1);
    /* 5 */ rmsnorm_split_kernel<<<NTOK_, 256>>>(qlat, q_a_ln, qlnh, qlnl, QLORA_, QLORA_, QLORA_);
    /* 6 */ transpose_split_kernel<<<dim3(H_ * DQK_ / 32, QLORA_ / 32), tb>>>(q_b_w, wqbh, wqbl, QLORA_, H_ * DQK_);
    /* 7 q_b */
    mma_gemm(qlnh, qlnl, wqbh, wqbl, qflat, 0, 0,
             NTOK_, H_ * DQK_, QLORA_, QLORA_, QLORA_, H_ * DQK_,
             0, 0, 1, 0, 0, 1.0f, 0, 0, 1);
    /* 8 */ qrope_split_kernel<<<(B_ * H_ * S_ * (DQK_ / 4) + 255) / 256, 256>>>(qflat, cs, sn, qfh, qfl);
    /* 9 */ rmsnorm_split_kernel<<<NTOK_, 256>>>(ckv, kv_a_ln, kch, kcl, KVLORA_, KVLORA_ + DR_, KVLORA_);
    /* 10 */ krope_kernel<<<(B_ * S_ * (DR_ / 4) + 255) / 256, 256>>>(ckv, cs, sn, kpe);
    /* 11 */ transpose_split_kernel<<<dim3(H_ * (DN_ + DV_) / 32, KVLORA_ / 32), tb>>>(kv_b_w, wkbh, wkbl, KVLORA_, H_ * (DN_ + DV_));
    /* 12 kv_b */
    mma_gemm(kch, kcl, wkbh, wkbl, kvflat, 0, 0,
             NTOK_, H_ * (DN_ + DV_), KVLORA_, KVLORA_, KVLORA_, H_ * (DN_ + DV_),
             0, 0, 1, 0, 0, 1.0f, 0, 0, 1);
    /* 13 */ kbuild_split_kernel<<<(B_ * H_ * S_ * (DQK_ / 4) + 255) / 256, 256>>>(kvflat, kpe, kfh, kfl);
    /* 14 */ vbuildT_split_kernel<<<dim3(S_ / 32, DV_ / 32, B_ * H_), tb>>>(kvflat, vth, vtl);
    /* 15 scores */
    mma_gemm(qfh, qfl, kfh, kfl, wts, 0, 0,
             S_, S_, DQK_, DQK_, DQK_, S_,
             (long long)S_ * DQK_, (long long)S_ * DQK_,
             1, (long long)S_ * S_, 0,
             SCALING_, 1, 0, B_ * H_);
    /* 16 */ softmax_kernel<<<B_ * H_ * S_, 256>>>(wts, whi, wlo);
    /* 17 PV -> omid hi/lo */
    mma_gemm(whi, wlo, vth, vtl, 0, omh, oml,
             S_, DV_, S_, S_, S_, H_ * DV_,
             (long long)S_ * S_, (long long)DV_ * S_,
             H_, (long long)S_ * H_ * DV_, (long long)DV_,
             1.0f, 0, 1, B_ * H_);
    /* 18 */ transpose_split_kernel<<<dim3(HID_ / 32, (H_ * DV_) / 32), tb>>>(o_w, woh, wol, H_ * DV_, HID_);
    /* 19 o_proj */
    mma_gemm(omh, oml, woh, wol, out, 0, 0,
             NTOK_, HID_, H_ * DV_, H_ * DV_, H_ * DV_, HID_,
             0, 0, 1, 0, 0, 1.0f, 0, 0, 1);
}

// round 6
// speedup vs baseline: 2.7849x; 1.1160x over previous
#include <cuda_runtime.h>
#include <cuda_bf16.h>
#include <math.h>
#include <stdint.h>

#define B_      2
#define S_      2048
#define HID_    2048
#define H_      16
#define QLORA_  1536
#define KVLORA_ 512
#define DR_     64
#define DN_     128
#define DQK_    192
#define DV_     128
#define NTOK_   (B_*S_)
#define SCALING_ 0.07216878364870322f

typedef __nv_bfloat16 bf16;

/* ------------------------------- scratch ---------------------------------- */
__device__ bf16  g_hs_hi [NTOK_*HID_];
__device__ bf16  g_hs_lo [NTOK_*HID_];
__device__ float g_qlat  [NTOK_*QLORA_];
__device__ bf16  g_qlatn_hi[NTOK_*QLORA_];
__device__ bf16  g_qlatn_lo[NTOK_*QLORA_];
__device__ float g_qflat [NTOK_*H_*DQK_];
__device__ bf16  g_qfull_hi[B_*H_*S_*DQK_];
__device__ bf16  g_qfull_lo[B_*H_*S_*DQK_];
__device__ float g_ckv   [NTOK_*(KVLORA_+DR_)];
__device__ bf16  g_kc_hi [NTOK_*KVLORA_];
__device__ bf16  g_kc_lo [NTOK_*KVLORA_];
__device__ float g_kpe   [B_*S_*DR_];
__device__ float g_kvflat[NTOK_*H_*(DN_+DV_)];
__device__ bf16  g_kfull_hi[B_*H_*S_*DQK_];
__device__ bf16  g_kfull_lo[B_*H_*S_*DQK_];
__device__ bf16  g_vT_hi [B_*H_*DV_*S_];
__device__ bf16  g_vT_lo [B_*H_*DV_*S_];
__device__ bf16  g_w_hi  [(long long)B_*H_*S_*S_];
__device__ bf16  g_w_lo  [(long long)B_*H_*S_*S_];
__device__ bf16  g_omid_hi[NTOK_*H_*DV_];
__device__ bf16  g_omid_lo[NTOK_*H_*DV_];
__device__ bf16  g_wqaT_hi [QLORA_*HID_];
__device__ bf16  g_wqaT_lo [QLORA_*HID_];
__device__ bf16  g_wqbT_hi [H_*DQK_*QLORA_];
__device__ bf16  g_wqbT_lo [H_*DQK_*QLORA_];
__device__ bf16  g_wkvaT_hi[(KVLORA_+DR_)*HID_];
__device__ bf16  g_wkvaT_lo[(KVLORA_+DR_)*HID_];
__device__ bf16  g_wkvbT_hi[H_*(DN_+DV_)*KVLORA_];
__device__ bf16  g_wkvbT_lo[H_*(DN_+DV_)*KVLORA_];
__device__ bf16  g_woT_hi  [HID_*H_*DV_];
__device__ bf16  g_woT_lo  [HID_*H_*DV_];

/* --------------------------- helpers --------------------------------------- */
__device__ __forceinline__ uint32_t smem_u32(const void* p) {
    uint32_t a;
    asm("{ .reg .u64 t; cvta.to.shared.u64 t, %1; cvt.u32.u64 %0, t; }" : "=r"(a) : "l"(p));
    return a;
}
__device__ __forceinline__ void ldsm_x4(uint32_t& r0, uint32_t& r1, uint32_t& r2, uint32_t& r3,
                                        uint32_t addr) {
    asm volatile("ldmatrix.sync.aligned.m8n8.x4.shared.b16 {%0,%1,%2,%3}, [%4];"
                 : "=r"(r0), "=r"(r1), "=r"(r2), "=r"(r3) : "r"(addr));
}
__device__ __forceinline__ void mma16816(float* c, const uint32_t* a, uint32_t b0, uint32_t b1) {
    asm volatile("mma.sync.aligned.m16n8k16.row.col.f32.bf16.bf16.f32 "
                 "{%0,%1,%2,%3}, {%4,%5,%6,%7}, {%8,%9}, {%0,%1,%2,%3};"
                 : "+f"(c[0]), "+f"(c[1]), "+f"(c[2]), "+f"(c[3])
                 : "r"(a[0]), "r"(a[1]), "r"(a[2]), "r"(a[3]), "r"(b0), "r"(b1));
}
__device__ __forceinline__ void cpa16(uint32_t dst, const void* src) {
    asm volatile("cp.async.cg.shared.global [%0], [%1], 16;"
                 :: "r"(dst), "l"(src) : "memory");
}
#define CP_COMMIT() asm volatile("cp.async.commit_group;" ::: "memory")
#define CP_WAIT1()  asm volatile("cp.async.wait_group 1;" ::: "memory")

/* split 4 floats into packed 4xbf16 hi (uint2) and lo (uint2) */
__device__ __forceinline__ void split4v(float4 v, uint2& hi, uint2& lo) {
    float f[4] = {v.x, v.y, v.z, v.w};
    unsigned short h[4], l[4];
    #pragma unroll
    for (int i = 0; i < 4; i++) {
        bf16 hb = __float2bfloat16(f[i]);
        bf16 lb = __float2bfloat16(f[i] - __bfloat162float(hb));
        h[i] = *(unsigned short*)&hb;
        l[i] = *(unsigned short*)&lb;
    }
    hi.x = (uint32_t)h[0] | ((uint32_t)h[1] << 16);
    hi.y = (uint32_t)h[2] | ((uint32_t)h[3] << 16);
    lo.x = (uint32_t)l[0] | ((uint32_t)l[1] << 16);
    lo.y = (uint32_t)l[2] | ((uint32_t)l[3] << 16);
}

/* FFMA-only exp */
__device__ __forceinline__ float fast_exp(float x) {
    float t = x * 1.4426950408889634f;
    float r = rintf(t);
    float f = t - r;
    float p =          1.339887440266574e-3f;
    p = fmaf(p, f,     9.618437357674640e-3f);
    p = fmaf(p, f,     5.550332471162809e-2f);
    p = fmaf(p, f,     2.402264791363012e-1f);
    p = fmaf(p, f,     6.931472028550421e-1f);
    p = fmaf(p, f,     1.0f);
    int ri = (int)r;
    if (ri < -126) ri = -126;
    float s = __int_as_float((uint32_t)(ri + 127) << 23);
    return p * s;
}

/* smem: A tiles 128x32 bf16 (rows padded to 80B), B tiles 64x32 */
#define ROWB   80
#define AHI_O  0
#define ALO_O  10240
#define BHI_O  20480
#define BLO_O  25600
#define STGSZ  30720
#define NSTG   3
#define GEMM_SMEM (NSTG*STGSZ)

/* ------------- bf16 HMMA GEMM: 128x64 CTA tile, 2 CTAs/SM, 3-stage --------- */
/* C = alpha * (Ahi+Alo)[M,K] @ (Bhi+Blo)[N,K]^T  (3-pass compensated)
   M % 128 == 0, N % 64 == 0, K % 32 == 0 */
__global__ __launch_bounds__(256, 2) void mma_gemm3_kernel(
    const bf16* __restrict__ Ahi, const bf16* __restrict__ Alo,
    const bf16* __restrict__ Bhi, const bf16* __restrict__ Blo,
    float* __restrict__ Cf, bf16* __restrict__ Chi, bf16* __restrict__ Clo,
    int M, int N, int K, int lda, int ldb, int ldc,
    long long sA, long long sB, int zdiv, long long csOut, long long csIn,
    float alpha, int causalSkip, int causalK)
{
    const int row0 = blockIdx.y * 128;
    const int col0 = blockIdx.x * 64;
    if (causalSkip && col0 > row0 + 127) return;
    const int bz = blockIdx.z;
    const bf16* Ah = Ahi + (long long)bz * sA;
    const bf16* Al = Alo + (long long)bz * sA;
    const bf16* Bh = Bhi + (long long)bz * sB;
    const bf16* Bl = Blo + (long long)bz * sB;
    const long long coff = (long long)(bz / zdiv) * csOut + (long long)(bz % zdiv) * csIn;

    extern __shared__ __align__(16) char smem[];
    const uint32_t sb = smem_u32(smem);

    const int tid  = threadIdx.x;
    const int wid  = tid >> 5;
    const int lane = tid & 31;
    const int wm = wid & 3;          /* M strip: rows wm*32..+32 */
    const int wn = wid >> 2;         /* N strip: cols wn*32..+32 */
    const int laneIn = lane & 7;
    const int quad   = lane >> 3;

    const uint32_t aBase = (uint32_t)((wm * 32 + laneIn + (quad & 1) * 8) * ROWB
                                      + ((quad >> 1) * 8) * 2);
    const uint32_t bBase = (uint32_t)((wn * 32 + laneIn + (quad >> 1) * 8) * ROWB
                                      + ((quad & 1) * 8) * 2);

    int kend = K;
    if (causalK) { int kl = row0 + 128; if (kl < kend) kend = kl; }
    const int nch = kend >> 5;

    float acc[2][4][4];
    #pragma unroll
    for (int i = 0; i < 2; i++)
        #pragma unroll
        for (int j = 0; j < 4; j++)
            #pragma unroll
            for (int q = 0; q < 4; q++) acc[i][j][q] = 0.0f;

    /* per-thread load coords: A rows r, r+64 (seg sg); B row r (seg sg) */
    const int r0t = tid >> 2;
    const int sg0 = tid & 3;
    const uint32_t soA0 = (uint32_t)(r0t * ROWB + sg0 * 16);
    const uint32_t soA1 = (uint32_t)((r0t + 64) * ROWB + sg0 * 16);

    auto issue = [&](int s) {
        const uint32_t dst = sb + (uint32_t)(s % NSTG) * STGSZ;
        const long long kk = (long long)(s << 5) + sg0 * 8;
        const long long a0 = (long long)(row0 + r0t) * lda + kk;
        const long long a1 = (long long)(row0 + r0t + 64) * lda + kk;
        const long long b0 = (long long)(col0 + r0t) * ldb + kk;
        cpa16(dst + AHI_O + soA0, Ah + a0);
        cpa16(dst + AHI_O + soA1, Ah + a1);
        cpa16(dst + ALO_O + soA0, Al + a0);
        cpa16(dst + ALO_O + soA1, Al + a1);
        cpa16(dst + BHI_O + soA0, Bh + b0);
        cpa16(dst + BLO_O + soA0, Bl + b0);
    };

    /* prologue: 2 stages ahead */
    if (0 < nch) issue(0);
    CP_COMMIT();
    if (1 < nch) issue(1);
    CP_COMMIT();

    for (int c = 0; c < nch; c++) {
        CP_WAIT1();
        __syncthreads();
        if (c + 2 < nch) issue(c + 2);
        CP_COMMIT();

        const uint32_t bufb = sb + (uint32_t)(c % NSTG) * STGSZ;
        #pragma unroll
        for (int p = 0; p < 3; p++) {
            const uint32_t aOp = bufb + (p == 2 ? ALO_O : AHI_O);
            const uint32_t bOp = bufb + (p == 1 ? BLO_O : BHI_O);
            #pragma unroll
            for (int ks = 0; ks < 2; ks++) {
                const uint32_t kb = (uint32_t)(ks * 16 * 2);
                uint32_t af[2][4];
                #pragma unroll
                for (int mt = 0; mt < 2; mt++)
                    ldsm_x4(af[mt][0], af[mt][1], af[mt][2], af[mt][3],
                            aOp + aBase + (uint32_t)(mt * 16 * ROWB) + kb);
                uint32_t bf[2][4];
                #pragma unroll
                for (int np = 0; np < 2; np++)
                    ldsm_x4(bf[np][0], bf[np][1], bf[np][2], bf[np][3],
                            bOp + bBase + (uint32_t)(np * 16 * ROWB) + kb);
                #pragma unroll
                for (int mt = 0; mt < 2; mt++)
                    #pragma unroll
                    for (int nt = 0; nt < 4; nt++)
                        mma16816(acc[mt][nt], af[mt],
                                 bf[nt >> 1][(nt & 1) * 2], bf[nt >> 1][(nt & 1) * 2 + 1]);
            }
        }
    }

    /* epilogue */
    const int lr  = lane >> 2;
    const int lc2 = (lane & 3) * 2;
    #pragma unroll
    for (int mt = 0; mt < 2; mt++) {
        #pragma unroll
        for (int nt = 0; nt < 4; nt++) {
            const int gr = row0 + wm * 32 + mt * 16 + lr;
            const int gc = col0 + wn * 32 + nt * 8 + lc2;
            float a0 = acc[mt][nt][0] * alpha, a1 = acc[mt][nt][1] * alpha;
            float a2 = acc[mt][nt][2] * alpha, a3 = acc[mt][nt][3] * alpha;
            const long long o0 = coff + (long long)gr * ldc + gc;
            const long long o1 = coff + (long long)(gr + 8) * ldc + gc;
            if (Cf) {
                *reinterpret_cast<float2*>(Cf + o0) = make_float2(a0, a1);
                *reinterpret_cast<float2*>(Cf + o1) = make_float2(a2, a3);
            }
            if (Chi) {
                bf16 h0 = __float2bfloat16(a0), h1 = __float2bfloat16(a1);
                bf16 h2 = __float2bfloat16(a2), h3 = __float2bfloat16(a3);
                __nv_bfloat162 hv0; hv0.x = h0; hv0.y = h1;
                __nv_bfloat162 hv1; hv1.x = h2; hv1.y = h3;
                *reinterpret_cast<__nv_bfloat162*>(Chi + o0) = hv0;
                *reinterpret_cast<__nv_bfloat162*>(Chi + o1) = hv1;
                __nv_bfloat162 lv0, lv1;
                lv0.x = __float2bfloat16(a0 - __bfloat162float(h0));
                lv0.y = __float2bfloat16(a1 - __bfloat162float(h1));
                lv1.x = __float2bfloat16(a2 - __bfloat162float(h2));
                lv1.y = __float2bfloat16(a3 - __bfloat162float(h3));
                *reinterpret_cast<__nv_bfloat162*>(Clo + o0) = lv0;
                *reinterpret_cast<__nv_bfloat162*>(Clo + o1) = lv1;
            }
        }
    }
}

/* ---------------- split fp32 -> hi/lo bf16 ---------------------------------- */
__global__ void split_kernel(const float* __restrict__ x, bf16* __restrict__ hi,
                             bf16* __restrict__ lo, int n4)
{
    int idx = blockIdx.x * blockDim.x + threadIdx.x;
    if (idx >= n4) return;
    float4 v = reinterpret_cast<const float4*>(x)[idx];
    uint2 h, l;
    split4v(v, h, l);
    reinterpret_cast<uint2*>(hi)[idx] = h;
    reinterpret_cast<uint2*>(lo)[idx] = l;
}

/* ---------------- transpose [K,N] fp32 -> [N,K] hi/lo bf16 ------------------ */
__global__ void transpose_split_kernel(const float* __restrict__ in,
                                       bf16* __restrict__ outHi, bf16* __restrict__ outLo,
                                       int K, int N)
{
    __shared__ float t[32][33];
    int k0 = blockIdx.y * 32, n0 = blockIdx.x * 32;
    int x = threadIdx.x, y = threadIdx.y;
    #pragma unroll
    for (int i = 0; i < 32; i += 8) {
        int k = k0 + y + i, n = n0 + x;
        t[y + i][x] = (k < K && n < N) ? in[(long long)k * N + n] : 0.0f;
    }
    __syncthreads();
    #pragma unroll
    for (int i = 0; i < 32; i += 8) {
        int n = n0 + y + i, k = k0 + x;
        if (n < N && k < K) {
            float v = t[x][y + i];
            bf16 hb = __float2bfloat16(v);
            outHi[(long long)n * K + k] = hb;
            outLo[(long long)n * K + k] = __float2bfloat16(v - __bfloat162float(hb));
        }
    }
}

/* ---------------- RMS norm -> hi/lo ----------------------------------------- */
__global__ __launch_bounds__(256) void rmsnorm_split_kernel(
    const float* __restrict__ x, const float* __restrict__ w,
    bf16* __restrict__ yh, bf16* __restrict__ yl, int n, int ldx, int ldy)
{
    int row = blockIdx.x;
    const float* xr = x + (long long)row * ldx;
    int tid = threadIdx.x;
    float ss = 0.0f;
    for (int i = tid; i < n; i += 256) { float v = xr[i]; ss += v * v; }
    __shared__ float red[8];
    #pragma unroll
    for (int o = 16; o; o >>= 1) ss += __shfl_xor_sync(0xffffffffu, ss, o);
    if ((tid & 31) == 0) red[tid >> 5] = ss;
    __syncthreads();
    if (tid < 32) {
        float v = (tid < 8) ? red[tid] : 0.0f;
        #pragma unroll
        for (int o = 4; o; o >>= 1) v += __shfl_xor_sync(0xffffffffu, v, o);
        if (tid == 0) red[0] = v;
    }
    __syncthreads();
    float inv = rsqrtf(red[0] / (float)n + 1e-6f);
    bf16* yhr = yh + (long long)row * ldy;
    bf16* ylr = yl + (long long)row * ldy;
    for (int i = tid; i < n; i += 256) {
        float v = w[i] * xr[i] * inv;
        bf16 hb = __float2bfloat16(v);
        yhr[i] = hb;
        ylr[i] = __float2bfloat16(v - __bfloat162float(hb));
    }
}

/* ---------------- q rope -> qfull hi/lo -------------------------------------- */
__global__ void qrope_split_kernel(const float* __restrict__ qf, const float* __restrict__ cs,
                                   const float* __restrict__ sn,
                                   bf16* __restrict__ oh, bf16* __restrict__ ol)
{
    int idx = blockIdx.x * blockDim.x + threadIdx.x;
    const int total4 = B_ * H_ * S_ * (DQK_ / 4);
    if (idx >= total4) return;
    int d4 = idx % (DQK_ / 4);
    int t = idx / (DQK_ / 4);
    int s = t % S_; t /= S_;
    int h = t % H_;
    int b = t / H_;
    int d = d4 * 4;
    const float* src = qf + (((long long)(b * S_ + s)) * H_ + h) * DQK_;
    float4 val;
    if (d < DN_) {
        val = *reinterpret_cast<const float4*>(src + d);
    } else {
        int p = d - DN_;
        float4 x = *reinterpret_cast<const float4*>(src + DN_ + p);
        float4 other;
        if (p < DR_ / 2) {
            float4 o = *reinterpret_cast<const float4*>(src + DN_ + p + DR_ / 2);
            other = make_float4(-o.x, -o.y, -o.z, -o.w);
        } else {
            other = *reinterpret_cast<const float4*>(src + DN_ + p - DR_ / 2);
        }
        long long co = ((long long)b * S_ + s) * DR_ + p;
        float4 c = *reinterpret_cast<const float4*>(cs + co);
        float4 ss2 = *reinterpret_cast<const float4*>(sn + co);
        val.x = fmaf(x.x, c.x, other.x * ss2.x);
        val.y = fmaf(x.y, c.y, other.y * ss2.y);
        val.z = fmaf(x.z, c.z, other.z * ss2.z);
        val.w = fmaf(x.w, c.w, other.w * ss2.w);
    }
    uint2 hh, ll;
    split4v(val, hh, ll);
    reinterpret_cast<uint2*>(oh)[idx] = hh;
    reinterpret_cast<uint2*>(ol)[idx] = ll;
}

__global__ void krope_kernel(const float* __restrict__ ckv, const float* __restrict__ cs,
                             const float* __restrict__ sn, float* __restrict__ kpe)
{
    int idx = blockIdx.x * blockDim.x + threadIdx.x;
    if (idx >= B_ * S_ * (DR_ / 4)) return;
    int p4 = idx % (DR_ / 4);
    int bs = idx / (DR_ / 4);
    int p = p4 * 4;
    const float* src = ckv + (long long)bs * (KVLORA_ + DR_) + KVLORA_;
    float4 x = *reinterpret_cast<const float4*>(src + p);
    float4 other;
    if (p < DR_ / 2) {
        float4 o = *reinterpret_cast<const float4*>(src + p + DR_ / 2);
        other = make_float4(-o.x, -o.y, -o.z, -o.w);
    } else {
        other = *reinterpret_cast<const float4*>(src + p - DR_ / 2);
    }
    long long co = (long long)bs * DR_ + p;
    float4 c = *reinterpret_cast<const float4*>(cs + co);
    float4 ss2 = *reinterpret_cast<const float4*>(sn + co);
    float4 val;
    val.x = fmaf(x.x, c.x, other.x * ss2.x);
    val.y = fmaf(x.y, c.y, other.y * ss2.y);
    val.z = fmaf(x.z, c.z, other.z * ss2.z);
    val.w = fmaf(x.w, c.w, other.w * ss2.w);
    *reinterpret_cast<float4*>(kpe + co) = val;
}

__global__ void kbuild_split_kernel(const float* __restrict__ kvflat, const float* __restrict__ kpe,
                                    bf16* __restrict__ oh, bf16* __restrict__ ol)
{
    int idx = blockIdx.x * blockDim.x + threadIdx.x;
    const int total4 = B_ * H_ * S_ * (DQK_ / 4);
    if (idx >= total4) return;
    int d4 = idx % (DQK_ / 4);
    int t = idx / (DQK_ / 4);
    int s = t % S_; t /= S_;
    int h = t % H_;
    int b = t / H_;
    int d = d4 * 4;
    float4 val;
    if (d < DN_)
        val = *reinterpret_cast<const float4*>(
            kvflat + (((long long)(b * S_ + s)) * H_ + h) * (DN_ + DV_) + d);
    else
        val = *reinterpret_cast<const float4*>(
            kpe + ((long long)b * S_ + s) * DR_ + (d - DN_));
    uint2 hh, ll;
    split4v(val, hh, ll);
    reinterpret_cast<uint2*>(oh)[idx] = hh;
    reinterpret_cast<uint2*>(ol)[idx] = ll;
}

/* v transpose -> vT hi/lo [b,h,d,s] */
__global__ void vbuildT_split_kernel(const float* __restrict__ kvflat,
                                     bf16* __restrict__ oh, bf16* __restrict__ ol)
{
    __shared__ float t[32][33];
    int bh = blockIdx.z;
    int b = bh >> 4, h = bh & 15;
    int s0 = blockIdx.x * 32, d0 = blockIdx.y * 32;
    int x = threadIdx.x, y = threadIdx.y;
    const float* src = kvflat + ((long long)b * S_ * H_ + h) * (DN_ + DV_) + DN_;
    #pragma unroll
    for (int i = 0; i < 32; i += 8) {
        int s = s0 + y + i, d = d0 + x;
        t[y + i][x] = src[(long long)s * (H_ * (DN_ + DV_)) + d];
    }
    __syncthreads();
    long long base = ((long long)bh * DV_) * S_;
    #pragma unroll
    for (int i = 0; i < 32; i += 8) {
        int d = d0 + y + i, s = s0 + x;
        float v = t[x][y + i];
        bf16 hb = __float2bfloat16(v);
        oh[base + (long long)d * S_ + s] = hb;
        ol[base + (long long)d * S_ + s] = __float2bfloat16(v - __bfloat162float(hb));
    }
}

/* ---------------- causal softmax: fp32 out + hi/lo bf16 out ------------------ */
__global__ __launch_bounds__(256) void softmax_kernel(float* __restrict__ wts,
                                                      bf16* __restrict__ wh,
                                                      bf16* __restrict__ wl)
{
    long long row = blockIdx.x;
    int i = (int)(row % S_);
    float* r = wts + row * (long long)S_;
    bf16* rh = wh + row * (long long)S_;
    bf16* rl = wl + row * (long long)S_;
    int tid = threadIdx.x;
    int nvalid = i + 1;

    float e[8];
    float mx = -1e30f;
    int cnt = 0;
    for (int j = tid; j < nvalid; j += 256) { e[cnt] = r[j]; mx = fmaxf(mx, e[cnt]); cnt++; }

    __shared__ float sm[8];
    #pragma unroll
    for (int o = 16; o; o >>= 1) mx = fmaxf(mx, __shfl_xor_sync(0xffffffffu, mx, o));
    if ((tid & 31) == 0) sm[tid >> 5] = mx;
    __syncthreads();
    if (tid < 32) {
        float v = (tid < 8) ? sm[tid] : -1e30f;
        #pragma unroll
        for (int o = 4; o; o >>= 1) v = fmaxf(v, __shfl_xor_sync(0xffffffffu, v, o));
        if (tid == 0) sm[0] = v;
    }
    __syncthreads();
    mx = sm[0];
    __syncthreads();

    float sum = 0.0f;
    cnt = 0;
    for (int j = tid; j < nvalid; j += 256) {
        float ev = fast_exp(e[cnt] - mx);
        e[cnt] = ev;
        sum += ev;
        cnt++;
    }
    #pragma unroll
    for (int o = 16; o; o >>= 1) sum += __shfl_xor_sync(0xffffffffu, sum, o);
    if ((tid & 31) == 0) sm[tid >> 5] = sum;
    __syncthreads();
    if (tid < 32) {
        float v = (tid < 8) ? sm[tid] : 0.0f;
        #pragma unroll
        for (int o = 4; o; o >>= 1) v += __shfl_xor_sync(0xffffffffu, v, o);
        if (tid == 0) sm[0] = v;
    }
    __syncthreads();
    float inv = 1.0f / sm[0];

    cnt = 0;
    for (int j = tid; j < nvalid; j += 256) {
        float v = e[cnt] * inv;
        r[j] = v;
        bf16 hb = __float2bfloat16(v);
        rh[j] = hb;
        rl[j] = __float2bfloat16(v - __bfloat162float(hb));
        cnt++;
    }
    bf16 z = __float2bfloat16(0.0f);
    for (int j = nvalid + tid; j < S_; j += 256) { r[j] = 0.0f; rh[j] = z; rl[j] = z; }
}

/* ---------------- host ------------------------------------------------------ */
static inline void mma_gemm(const bf16* Ah, const bf16* Al, const bf16* Bh, const bf16* Bl,
                            float* Cf, bf16* Chi, bf16* Clo,
                            int M, int N, int K, int lda, int ldb, int ldc,
                            long long sA, long long sB,
                            int zdiv, long long csOut, long long csIn,
                            float alpha, int causalSkip, int causalK, int batch)
{
    dim3 grid((N + 63) / 64, (M + 127) / 128, batch);
    mma_gemm3_kernel<<<grid, 256, GEMM_SMEM>>>(Ah, Al, Bh, Bl, Cf, Chi, Clo,
                                               M, N, K, lda, ldb, ldc,
                                               sA, sB, zdiv, csOut, csIn,
                                               alpha, causalSkip, causalK);
}

extern "C" void kernel_launch(void* const* d_in, const int* in_sizes, int n_in,
                              void* d_out, int out_size)
{
    const float* hs      = (const float*)d_in[0];
    const float* cs      = (const float*)d_in[1];
    const float* sn      = (const float*)d_in[2];
    const float* q_a_w   = (const float*)d_in[4];
    const float* q_a_ln  = (const float*)d_in[5];
    const float* q_b_w   = (const float*)d_in[6];
    const float* kv_a_w  = (const float*)d_in[7];
    const float* kv_a_ln = (const float*)d_in[8];
    const float* kv_b_w  = (const float*)d_in[9];
    const float* o_w     = (const float*)d_in[10];

    float* out = (float*)d_out;
    float* wts = out + (long long)B_ * S_ * HID_;

    static bool attr_set = false;
    if (!attr_set) {
        cudaFuncSetAttribute(mma_gemm3_kernel, cudaFuncAttributeMaxDynamicSharedMemorySize, GEMM_SMEM);
        attr_set = true;
    }

#define GETSYM(p, s) cudaGetSymbolAddress((void**)&p, s)
    bf16 *hsh, *hsl, *qlnh, *qlnl, *qfh, *qfl, *kch, *kcl, *kfh, *kfl, *vth, *vtl;
    bf16 *whi, *wlo, *omh, *oml;
    bf16 *wqah, *wqal, *wqbh, *wqbl, *wkah, *wkal, *wkbh, *wkbl, *woh, *wol;
    float *qlat, *qflat, *ckv, *kpe, *kvflat;
    GETSYM(hsh, g_hs_hi);   GETSYM(hsl, g_hs_lo);
    GETSYM(qlat, g_qlat);   GETSYM(qlnh, g_qlatn_hi); GETSYM(qlnl, g_qlatn_lo);
    GETSYM(qflat, g_qflat); GETSYM(qfh, g_qfull_hi);  GETSYM(qfl, g_qfull_lo);
    GETSYM(ckv, g_ckv);     GETSYM(kch, g_kc_hi);     GETSYM(kcl, g_kc_lo);
    GETSYM(kpe, g_kpe);     GETSYM(kvflat, g_kvflat);
    GETSYM(kfh, g_kfull_hi);GETSYM(kfl, g_kfull_lo);
    GETSYM(vth, g_vT_hi);   GETSYM(vtl, g_vT_lo);
    GETSYM(whi, g_w_hi);    GETSYM(wlo, g_w_lo);
    GETSYM(omh, g_omid_hi); GETSYM(oml, g_omid_lo);
    GETSYM(wqah, g_wqaT_hi); GETSYM(wqal, g_wqaT_lo);
    GETSYM(wqbh, g_wqbT_hi); GETSYM(wqbl, g_wqbT_lo);
    GETSYM(wkah, g_wkvaT_hi); GETSYM(wkal, g_wkvaT_lo);
    GETSYM(wkbh, g_wkvbT_hi); GETSYM(wkbl, g_wkvbT_lo);
    GETSYM(woh, g_woT_hi);  GETSYM(wol, g_woT_lo);
#undef GETSYM

    dim3 tb(32, 8);
    /* 0 */ transpose_split_kernel<<<dim3(QLORA_ / 32, HID_ / 32), tb>>>(q_a_w, wqah, wqal, HID_, QLORA_);
    /* 1 */ split_kernel<<<(NTOK_ * HID_ / 4 + 255) / 256, 256>>>(hs, hsh, hsl, NTOK_ * HID_ / 4);
    /* 2 */ transpose_split_kernel<<<dim3((KVLORA_ + DR_) / 32, HID_ / 32), tb>>>(kv_a_w, wkah, wkal, HID_, KVLORA_ + DR_);
    /* 3 q_a (profiled) */
    mma_gemm(hsh, hsl, wqah, wqal, qlat, 0, 0,
             NTOK_, QLORA_, HID_, HID_, HID_, QLORA_,
             0, 0, 1, 0, 0, 1.0f, 0, 0, 1);
    /* 4 kv_a */
    mma_gemm(hsh, hsl, wkah, wkal, ckv, 0, 0,
             NTOK_, KVLORA_ + DR_, HID_, HID_, HID_, KVLORA_ + DR_,
             0, 0, 1, 0, 0, 1.0f, 0, 0, 1);
    /* 5 */ rmsnorm_split_kernel<<<NTOK_, 256>>>(qlat, q_a_ln, qlnh, qlnl, QLORA_, QLORA_, QLORA_);
    /* 6 */ transpose_split_kernel<<<dim3(H_ * DQK_ / 32, QLORA_ / 32), tb>>>(q_b_w, wqbh, wqbl, QLORA_, H_ * DQK_);
    /* 7 q_b */
    mma_gemm(qlnh, qlnl, wqbh, wqbl, qflat, 0, 0,
             NTOK_, H_ * DQK_, QLORA_, QLORA_, QLORA_, H_ * DQK_,
             0, 0, 1, 0, 0, 1.0f, 0, 0, 1);
    /* 8 */ qrope_split_kernel<<<(B_ * H_ * S_ * (DQK_ / 4) + 255) / 256, 256>>>(qflat, cs, sn, qfh, qfl);
    /* 9 */ rmsnorm_split_kernel<<<NTOK_, 256>>>(ckv, kv_a_ln, kch, kcl, KVLORA_, KVLORA_ + DR_, KVLORA_);
    /* 10 */ krope_kernel<<<(B_ * S_ * (DR_ / 4) + 255) / 256, 256>>>(ckv, cs, sn, kpe);
    /* 11 */ transpose_split_kernel<<<dim3(H_ * (DN_ + DV_) / 32, KVLORA_ / 32), tb>>>(kv_b_w, wkbh, wkbl, KVLORA_, H_ * (DN_ + DV_));
    /* 12 kv_b */
    mma_gemm(kch, kcl, wkbh, wkbl, kvflat, 0, 0,
             NTOK_, H_ * (DN_ + DV_), KVLORA_, KVLORA_, KVLORA_, H_ * (DN_ + DV_),
             0, 0, 1, 0, 0, 1.0f, 0, 0, 1);
    /* 13 */ kbuild_split_kernel<<<(B_ * H_ * S_ * (DQK_ / 4) + 255) / 256, 256>>>(kvflat, kpe, kfh, kfl);
    /* 14 */ vbuildT_split_kernel<<<dim3(S_ / 32, DV_ / 32, B_ * H_), tb>>>(kvflat, vth, vtl);
    /* 15 scores */
    mma_gemm(qfh, qfl, kfh, kfl, wts, 0, 0,
             S_, S_, DQK_, DQK_, DQK_, S_,
             (long long)S_ * DQK_, (long long)S_ * DQK_,
             1, (long long)S_ * S_, 0,
             SCALING_, 1, 0, B_ * H_);
    /* 16 */ softmax_kernel<<<B_ * H_ * S_, 256>>>(wts, whi, wlo);
    /* 17 PV -> omid hi/lo */
    mma_gemm(whi, wlo, vth, vtl, 0, omh, oml,
             S_, DV_, S_, S_, S_, H_ * DV_,
             (long long)S_ * S_, (long long)DV_ * S_,
             H_, (long long)S_ * H_ * DV_, (long long)DV_,
             1.0f, 0, 1, B_ * H_);
    /* 18 */ transpose_split_kernel<<<dim3(HID_ / 32, (H_ * DV_) / 32), tb>>>(o_w, woh, wol, H_ * DV_, HID_);
    /* 19 o_proj */
    mma_gemm(omh, oml, woh, wol, out, 0, 0,
             NTOK_, HID_, H_ * DV_, H_ * DV_, H_ * DV_, HID_,
             0, 0, 1, 0, 0, 1.0f, 0, 0, 1);
}

// round 7
// speedup vs baseline: 2.9651x; 1.0647x over previous
#include <cuda_runtime.h>
#include <cuda_bf16.h>
#include <math.h>
#include <stdint.h>

#define B_      2
#define S_      2048
#define HID_    2048
#define H_      16
#define QLORA_  1536
#define KVLORA_ 512
#define DR_     64
#define DN_     128
#define DQK_    192
#define DV_     128
#define NTOK_   (B_*S_)
#define SCALING_ 0.07216878364870322f

typedef __nv_bfloat16 bf16;

/* ------------------------------- scratch ---------------------------------- */
__device__ bf16  g_hs_hi [NTOK_*HID_];
__device__ bf16  g_hs_lo [NTOK_*HID_];
__device__ float g_qlat  [NTOK_*QLORA_];
__device__ bf16  g_qlatn_hi[NTOK_*QLORA_];
__device__ bf16  g_qlatn_lo[NTOK_*QLORA_];
__device__ float g_qflat [NTOK_*H_*DQK_];
__device__ bf16  g_qfull_hi[B_*H_*S_*DQK_];
__device__ bf16  g_qfull_lo[B_*H_*S_*DQK_];
__device__ float g_ckv   [NTOK_*(KVLORA_+DR_)];
__device__ bf16  g_kc_hi [NTOK_*KVLORA_];
__device__ bf16  g_kc_lo [NTOK_*KVLORA_];
__device__ float g_kpe   [B_*S_*DR_];
__device__ float g_kvflat[NTOK_*H_*(DN_+DV_)];
__device__ bf16  g_kfull_hi[B_*H_*S_*DQK_];
__device__ bf16  g_kfull_lo[B_*H_*S_*DQK_];
__device__ bf16  g_vT_hi [B_*H_*DV_*S_];
__device__ bf16  g_vT_lo [B_*H_*DV_*S_];
__device__ bf16  g_w_hi  [(long long)B_*H_*S_*S_];
__device__ bf16  g_w_lo  [(long long)B_*H_*S_*S_];
__device__ bf16  g_omid_hi[NTOK_*H_*DV_];
__device__ bf16  g_omid_lo[NTOK_*H_*DV_];
__device__ bf16  g_wqaT_hi [QLORA_*HID_];
__device__ bf16  g_wqaT_lo [QLORA_*HID_];
__device__ bf16  g_wqbT_hi [H_*DQK_*QLORA_];
__device__ bf16  g_wqbT_lo [H_*DQK_*QLORA_];
__device__ bf16  g_wkvaT_hi[(KVLORA_+DR_)*HID_];
__device__ bf16  g_wkvaT_lo[(KVLORA_+DR_)*HID_];
__device__ bf16  g_wkvbT_hi[H_*(DN_+DV_)*KVLORA_];
__device__ bf16  g_wkvbT_lo[H_*(DN_+DV_)*KVLORA_];
__device__ bf16  g_woT_hi  [HID_*H_*DV_];
__device__ bf16  g_woT_lo  [HID_*H_*DV_];

/* --------------------------- helpers --------------------------------------- */
__device__ __forceinline__ uint32_t smem_u32(const void* p) {
    uint32_t a;
    asm("{ .reg .u64 t; cvta.to.shared.u64 t, %1; cvt.u32.u64 %0, t; }" : "=r"(a) : "l"(p));
    return a;
}
__device__ __forceinline__ void ldsm_x4(uint32_t& r0, uint32_t& r1, uint32_t& r2, uint32_t& r3,
                                        uint32_t addr) {
    asm volatile("ldmatrix.sync.aligned.m8n8.x4.shared.b16 {%0,%1,%2,%3}, [%4];"
                 : "=r"(r0), "=r"(r1), "=r"(r2), "=r"(r3) : "r"(addr));
}
__device__ __forceinline__ void mma16816(float* c, const uint32_t* a, uint32_t b0, uint32_t b1) {
    asm volatile("mma.sync.aligned.m16n8k16.row.col.f32.bf16.bf16.f32 "
                 "{%0,%1,%2,%3}, {%4,%5,%6,%7}, {%8,%9}, {%0,%1,%2,%3};"
                 : "+f"(c[0]), "+f"(c[1]), "+f"(c[2]), "+f"(c[3])
                 : "r"(a[0]), "r"(a[1]), "r"(a[2]), "r"(a[3]), "r"(b0), "r"(b1));
}
__device__ __forceinline__ void cpa16(uint32_t dst, const void* src) {
    asm volatile("cp.async.cg.shared.global [%0], [%1], 16;"
                 :: "r"(dst), "l"(src) : "memory");
}
#define CP_COMMIT() asm volatile("cp.async.commit_group;" ::: "memory")
#define CP_WAIT1()  asm volatile("cp.async.wait_group 1;" ::: "memory")

/* split 4 floats into packed 4xbf16 hi (uint2) and lo (uint2) */
__device__ __forceinline__ void split4v(float4 v, uint2& hi, uint2& lo) {
    float f[4] = {v.x, v.y, v.z, v.w};
    unsigned short h[4], l[4];
    #pragma unroll
    for (int i = 0; i < 4; i++) {
        bf16 hb = __float2bfloat16(f[i]);
        bf16 lb = __float2bfloat16(f[i] - __bfloat162float(hb));
        h[i] = *(unsigned short*)&hb;
        l[i] = *(unsigned short*)&lb;
    }
    hi.x = (uint32_t)h[0] | ((uint32_t)h[1] << 16);
    hi.y = (uint32_t)h[2] | ((uint32_t)h[3] << 16);
    lo.x = (uint32_t)l[0] | ((uint32_t)l[1] << 16);
    lo.y = (uint32_t)l[2] | ((uint32_t)l[3] << 16);
}

/* FFMA-only exp */
__device__ __forceinline__ float fast_exp(float x) {
    float t = x * 1.4426950408889634f;
    float r = rintf(t);
    float f = t - r;
    float p =          1.339887440266574e-3f;
    p = fmaf(p, f,     9.618437357674640e-3f);
    p = fmaf(p, f,     5.550332471162809e-2f);
    p = fmaf(p, f,     2.402264791363012e-1f);
    p = fmaf(p, f,     6.931472028550421e-1f);
    p = fmaf(p, f,     1.0f);
    int ri = (int)r;
    if (ri < -126) ri = -126;
    float s = __int_as_float((uint32_t)(ri + 127) << 23);
    return p * s;
}

/* smem: K-chunk 64. A tiles 128x64 bf16, B 64x64; rows padded to 144B. */
#define ROWB   144
#define AHI_O  0
#define ALO_O  18432
#define BHI_O  36864
#define BLO_O  46080
#define STGSZ  55296
#define NSTG   2
#define GEMM_SMEM (NSTG*STGSZ)

/* ------- bf16 HMMA GEMM: 128x64 CTA tile, K-chunk 64, 2 CTAs/SM, 2-stage --- */
/* C = alpha * (Ahi+Alo)[M,K] @ (Bhi+Blo)[N,K]^T  (3-pass compensated)
   M % 128 == 0, N % 64 == 0, K % 64 == 0 */
__global__ __launch_bounds__(256, 2) void mma_gemm4_kernel(
    const bf16* __restrict__ Ahi, const bf16* __restrict__ Alo,
    const bf16* __restrict__ Bhi, const bf16* __restrict__ Blo,
    float* __restrict__ Cf, bf16* __restrict__ Chi, bf16* __restrict__ Clo,
    int M, int N, int K, int lda, int ldb, int ldc,
    long long sA, long long sB, int zdiv, long long csOut, long long csIn,
    float alpha, int causalSkip, int causalK)
{
    const int row0 = blockIdx.y * 128;
    const int col0 = blockIdx.x * 64;
    if (causalSkip && col0 > row0 + 127) return;
    const int bz = blockIdx.z;
    const bf16* Ah = Ahi + (long long)bz * sA;
    const bf16* Al = Alo + (long long)bz * sA;
    const bf16* Bh = Bhi + (long long)bz * sB;
    const bf16* Bl = Blo + (long long)bz * sB;
    const long long coff = (long long)(bz / zdiv) * csOut + (long long)(bz % zdiv) * csIn;

    extern __shared__ __align__(16) char smem[];
    const uint32_t sb = smem_u32(smem);

    const int tid  = threadIdx.x;
    const int wid  = tid >> 5;
    const int lane = tid & 31;
    const int wm = wid & 3;          /* M strip: rows wm*32..+32 */
    const int wn = wid >> 2;         /* N strip: cols wn*32..+32 */
    const int laneIn = lane & 7;
    const int quad   = lane >> 3;

    const uint32_t aBase = (uint32_t)((wm * 32 + laneIn + (quad & 1) * 8) * ROWB
                                      + ((quad >> 1) * 8) * 2);
    const uint32_t bBase = (uint32_t)((wn * 32 + laneIn + (quad >> 1) * 8) * ROWB
                                      + ((quad & 1) * 8) * 2);

    int kend = K;
    if (causalK) { int kl = row0 + 128; if (kl < kend) kend = kl; }
    const int nch = kend >> 6;

    float acc[2][4][4];
    #pragma unroll
    for (int i = 0; i < 2; i++)
        #pragma unroll
        for (int j = 0; j < 4; j++)
            #pragma unroll
            for (int q = 0; q < 4; q++) acc[i][j][q] = 0.0f;

    auto issue = [&](int s) {
        const uint32_t dst = sb + (uint32_t)(s & 1) * STGSZ;
        const int k0 = s << 6;
        /* A hi/lo: 128 rows x 8 segs of 16B, 4 per thread per operand */
        #pragma unroll
        for (int i = 0; i < 4; i++) {
            const int g = tid + i * 256;
            const int r = g >> 3, sg = g & 7;
            const uint32_t so = (uint32_t)(r * ROWB + sg * 16);
            const long long ga = (long long)(row0 + r) * lda + k0 + sg * 8;
            cpa16(dst + AHI_O + so, Ah + ga);
            cpa16(dst + ALO_O + so, Al + ga);
        }
        /* B hi/lo: 64 rows x 8 segs, 2 per thread per operand */
        #pragma unroll
        for (int i = 0; i < 2; i++) {
            const int g = tid + i * 256;
            const int r = g >> 3, sg = g & 7;
            const uint32_t so = (uint32_t)(r * ROWB + sg * 16);
            const long long gb = (long long)(col0 + r) * ldb + k0 + sg * 8;
            cpa16(dst + BHI_O + so, Bh + gb);
            cpa16(dst + BLO_O + so, Bl + gb);
        }
    };

    /* 2-stage pipeline */
    issue(0);
    CP_COMMIT();

    for (int c = 0; c < nch; c++) {
        if (c + 1 < nch) issue(c + 1);
        CP_COMMIT();
        CP_WAIT1();                 /* stage c complete */
        __syncthreads();

        const uint32_t bufb = sb + (uint32_t)(c & 1) * STGSZ;
        #pragma unroll
        for (int p = 0; p < 3; p++) {
            const uint32_t aOp = bufb + (p == 2 ? ALO_O : AHI_O);
            const uint32_t bOp = bufb + (p == 1 ? BLO_O : BHI_O);
            #pragma unroll
            for (int ks = 0; ks < 4; ks++) {
                const uint32_t kb = (uint32_t)(ks * 32);
                uint32_t af[2][4];
                #pragma unroll
                for (int mt = 0; mt < 2; mt++)
                    ldsm_x4(af[mt][0], af[mt][1], af[mt][2], af[mt][3],
                            aOp + aBase + (uint32_t)(mt * 16 * ROWB) + kb);
                uint32_t bfr[2][4];
                #pragma unroll
                for (int np = 0; np < 2; np++)
                    ldsm_x4(bfr[np][0], bfr[np][1], bfr[np][2], bfr[np][3],
                            bOp + bBase + (uint32_t)(np * 16 * ROWB) + kb);
                #pragma unroll
                for (int mt = 0; mt < 2; mt++)
                    #pragma unroll
                    for (int nt = 0; nt < 4; nt++)
                        mma16816(acc[mt][nt], af[mt],
                                 bfr[nt >> 1][(nt & 1) * 2], bfr[nt >> 1][(nt & 1) * 2 + 1]);
            }
        }
        __syncthreads();            /* all warps done reading before next overwrite */
    }

    /* epilogue */
    const int lr  = lane >> 2;
    const int lc2 = (lane & 3) * 2;
    #pragma unroll
    for (int mt = 0; mt < 2; mt++) {
        #pragma unroll
        for (int nt = 0; nt < 4; nt++) {
            const int gr = row0 + wm * 32 + mt * 16 + lr;
            const int gc = col0 + wn * 32 + nt * 8 + lc2;
            float a0 = acc[mt][nt][0] * alpha, a1 = acc[mt][nt][1] * alpha;
            float a2 = acc[mt][nt][2] * alpha, a3 = acc[mt][nt][3] * alpha;
            const long long o0 = coff + (long long)gr * ldc + gc;
            const long long o1 = coff + (long long)(gr + 8) * ldc + gc;
            if (Cf) {
                *reinterpret_cast<float2*>(Cf + o0) = make_float2(a0, a1);
                *reinterpret_cast<float2*>(Cf + o1) = make_float2(a2, a3);
            }
            if (Chi) {
                bf16 h0 = __float2bfloat16(a0), h1 = __float2bfloat16(a1);
                bf16 h2 = __float2bfloat16(a2), h3 = __float2bfloat16(a3);
                __nv_bfloat162 hv0; hv0.x = h0; hv0.y = h1;
                __nv_bfloat162 hv1; hv1.x = h2; hv1.y = h3;
                *reinterpret_cast<__nv_bfloat162*>(Chi + o0) = hv0;
                *reinterpret_cast<__nv_bfloat162*>(Chi + o1) = hv1;
                __nv_bfloat162 lv0, lv1;
                lv0.x = __float2bfloat16(a0 - __bfloat162float(h0));
                lv0.y = __float2bfloat16(a1 - __bfloat162float(h1));
                lv1.x = __float2bfloat16(a2 - __bfloat162float(h2));
                lv1.y = __float2bfloat16(a3 - __bfloat162float(h3));
                *reinterpret_cast<__nv_bfloat162*>(Clo + o0) = lv0;
                *reinterpret_cast<__nv_bfloat162*>(Clo + o1) = lv1;
            }
        }
    }
}

/* ---------------- split fp32 -> hi/lo bf16 ---------------------------------- */
__global__ void split_kernel(const float* __restrict__ x, bf16* __restrict__ hi,
                             bf16* __restrict__ lo, int n4)
{
    int idx = blockIdx.x * blockDim.x + threadIdx.x;
    if (idx >= n4) return;
    float4 v = reinterpret_cast<const float4*>(x)[idx];
    uint2 h, l;
    split4v(v, h, l);
    reinterpret_cast<uint2*>(hi)[idx] = h;
    reinterpret_cast<uint2*>(lo)[idx] = l;
}

/* ---------------- transpose [K,N] fp32 -> [N,K] hi/lo bf16 ------------------ */
__global__ void transpose_split_kernel(const float* __restrict__ in,
                                       bf16* __restrict__ outHi, bf16* __restrict__ outLo,
                                       int K, int N)
{
    __shared__ float t[32][33];
    int k0 = blockIdx.y * 32, n0 = blockIdx.x * 32;
    int x = threadIdx.x, y = threadIdx.y;
    #pragma unroll
    for (int i = 0; i < 32; i += 8) {
        int k = k0 + y + i, n = n0 + x;
        t[y + i][x] = (k < K && n < N) ? in[(long long)k * N + n] : 0.0f;
    }
    __syncthreads();
    #pragma unroll
    for (int i = 0; i < 32; i += 8) {
        int n = n0 + y + i, k = k0 + x;
        if (n < N && k < K) {
            float v = t[x][y + i];
            bf16 hb = __float2bfloat16(v);
            outHi[(long long)n * K + k] = hb;
            outLo[(long long)n * K + k] = __float2bfloat16(v - __bfloat162float(hb));
        }
    }
}

/* ---------------- RMS norm -> hi/lo ----------------------------------------- */
__global__ __launch_bounds__(256) void rmsnorm_split_kernel(
    const float* __restrict__ x, const float* __restrict__ w,
    bf16* __restrict__ yh, bf16* __restrict__ yl, int n, int ldx, int ldy)
{
    int row = blockIdx.x;
    const float* xr = x + (long long)row * ldx;
    int tid = threadIdx.x;
    float ss = 0.0f;
    for (int i = tid; i < n; i += 256) { float v = xr[i]; ss += v * v; }
    __shared__ float red[8];
    #pragma unroll
    for (int o = 16; o; o >>= 1) ss += __shfl_xor_sync(0xffffffffu, ss, o);
    if ((tid & 31) == 0) red[tid >> 5] = ss;
    __syncthreads();
    if (tid < 32) {
        float v = (tid < 8) ? red[tid] : 0.0f;
        #pragma unroll
        for (int o = 4; o; o >>= 1) v += __shfl_xor_sync(0xffffffffu, v, o);
        if (tid == 0) red[0] = v;
    }
    __syncthreads();
    float inv = rsqrtf(red[0] / (float)n + 1e-6f);
    bf16* yhr = yh + (long long)row * ldy;
    bf16* ylr = yl + (long long)row * ldy;
    for (int i = tid; i < n; i += 256) {
        float v = w[i] * xr[i] * inv;
        bf16 hb = __float2bfloat16(v);
        yhr[i] = hb;
        ylr[i] = __float2bfloat16(v - __bfloat162float(hb));
    }
}

/* ---------------- q rope -> qfull hi/lo -------------------------------------- */
__global__ void qrope_split_kernel(const float* __restrict__ qf, const float* __restrict__ cs,
                                   const float* __restrict__ sn,
                                   bf16* __restrict__ oh, bf16* __restrict__ ol)
{
    int idx = blockIdx.x * blockDim.x + threadIdx.x;
    const int total4 = B_ * H_ * S_ * (DQK_ / 4);
    if (idx >= total4) return;
    int d4 = idx % (DQK_ / 4);
    int t = idx / (DQK_ / 4);
    int s = t % S_; t /= S_;
    int h = t % H_;
    int b = t / H_;
    int d = d4 * 4;
    const float* src = qf + (((long long)(b * S_ + s)) * H_ + h) * DQK_;
    float4 val;
    if (d < DN_) {
        val = *reinterpret_cast<const float4*>(src + d);
    } else {
        int p = d - DN_;
        float4 x = *reinterpret_cast<const float4*>(src + DN_ + p);
        float4 other;
        if (p < DR_ / 2) {
            float4 o = *reinterpret_cast<const float4*>(src + DN_ + p + DR_ / 2);
            other = make_float4(-o.x, -o.y, -o.z, -o.w);
        } else {
            other = *reinterpret_cast<const float4*>(src + DN_ + p - DR_ / 2);
        }
        long long co = ((long long)b * S_ + s) * DR_ + p;
        float4 c = *reinterpret_cast<const float4*>(cs + co);
        float4 ss2 = *reinterpret_cast<const float4*>(sn + co);
        val.x = fmaf(x.x, c.x, other.x * ss2.x);
        val.y = fmaf(x.y, c.y, other.y * ss2.y);
        val.z = fmaf(x.z, c.z, other.z * ss2.z);
        val.w = fmaf(x.w, c.w, other.w * ss2.w);
    }
    uint2 hh, ll;
    split4v(val, hh, ll);
    reinterpret_cast<uint2*>(oh)[idx] = hh;
    reinterpret_cast<uint2*>(ol)[idx] = ll;
}

__global__ void krope_kernel(const float* __restrict__ ckv, const float* __restrict__ cs,
                             const float* __restrict__ sn, float* __restrict__ kpe)
{
    int idx = blockIdx.x * blockDim.x + threadIdx.x;
    if (idx >= B_ * S_ * (DR_ / 4)) return;
    int p4 = idx % (DR_ / 4);
    int bs = idx / (DR_ / 4);
    int p = p4 * 4;
    const float* src = ckv + (long long)bs * (KVLORA_ + DR_) + KVLORA_;
    float4 x = *reinterpret_cast<const float4*>(src + p);
    float4 other;
    if (p < DR_ / 2) {
        float4 o = *reinterpret_cast<const float4*>(src + p + DR_ / 2);
        other = make_float4(-o.x, -o.y, -o.z, -o.w);
    } else {
        other = *reinterpret_cast<const float4*>(src + p - DR_ / 2);
    }
    long long co = (long long)bs * DR_ + p;
    float4 c = *reinterpret_cast<const float4*>(cs + co);
    float4 ss2 = *reinterpret_cast<const float4*>(sn + co);
    float4 val;
    val.x = fmaf(x.x, c.x, other.x * ss2.x);
    val.y = fmaf(x.y, c.y, other.y * ss2.y);
    val.z = fmaf(x.z, c.z, other.z * ss2.z);
    val.w = fmaf(x.w, c.w, other.w * ss2.w);
    *reinterpret_cast<float4*>(kpe + co) = val;
}

__global__ void kbuild_split_kernel(const float* __restrict__ kvflat, const float* __restrict__ kpe,
                                    bf16* __restrict__ oh, bf16* __restrict__ ol)
{
    int idx = blockIdx.x * blockDim.x + threadIdx.x;
    const int total4 = B_ * H_ * S_ * (DQK_ / 4);
    if (idx >= total4) return;
    int d4 = idx % (DQK_ / 4);
    int t = idx / (DQK_ / 4);
    int s = t % S_; t /= S_;
    int h = t % H_;
    int b = t / H_;
    int d = d4 * 4;
    float4 val;
    if (d < DN_)
        val = *reinterpret_cast<const float4*>(
            kvflat + (((long long)(b * S_ + s)) * H_ + h) * (DN_ + DV_) + d);
    else
        val = *reinterpret_cast<const float4*>(
            kpe + ((long long)b * S_ + s) * DR_ + (d - DN_));
    uint2 hh, ll;
    split4v(val, hh, ll);
    reinterpret_cast<uint2*>(oh)[idx] = hh;
    reinterpret_cast<uint2*>(ol)[idx] = ll;
}

/* v transpose -> vT hi/lo [b,h,d,s] */
__global__ void vbuildT_split_kernel(const float* __restrict__ kvflat,
                                     bf16* __restrict__ oh, bf16* __restrict__ ol)
{
    __shared__ float t[32][33];
    int bh = blockIdx.z;
    int b = bh >> 4, h = bh & 15;
    int s0 = blockIdx.x * 32, d0 = blockIdx.y * 32;
    int x = threadIdx.x, y = threadIdx.y;
    const float* src = kvflat + ((long long)b * S_ * H_ + h) * (DN_ + DV_) + DN_;
    #pragma unroll
    for (int i = 0; i < 32; i += 8) {
        int s = s0 + y + i, d = d0 + x;
        t[y + i][x] = src[(long long)s * (H_ * (DN_ + DV_)) + d];
    }
    __syncthreads();
    long long base = ((long long)bh * DV_) * S_;
    #pragma unroll
    for (int i = 0; i < 32; i += 8) {
        int d = d0 + y + i, s = s0 + x;
        float v = t[x][y + i];
        bf16 hb = __float2bfloat16(v);
        oh[base + (long long)d * S_ + s] = hb;
        ol[base + (long long)d * S_ + s] = __float2bfloat16(v - __bfloat162float(hb));
    }
}

/* ---------------- causal softmax: fp32 out + hi/lo bf16 out ------------------ */
__global__ __launch_bounds__(256) void softmax_kernel(float* __restrict__ wts,
                                                      bf16* __restrict__ wh,
                                                      bf16* __restrict__ wl)
{
    long long row = blockIdx.x;
    int i = (int)(row % S_);
    float* r = wts + row * (long long)S_;
    bf16* rh = wh + row * (long long)S_;
    bf16* rl = wl + row * (long long)S_;
    int tid = threadIdx.x;
    int nvalid = i + 1;

    float e[8];
    float mx = -1e30f;
    int cnt = 0;
    for (int j = tid; j < nvalid; j += 256) { e[cnt] = r[j]; mx = fmaxf(mx, e[cnt]); cnt++; }

    __shared__ float sm[8];
    #pragma unroll
    for (int o = 16; o; o >>= 1) mx = fmaxf(mx, __shfl_xor_sync(0xffffffffu, mx, o));
    if ((tid & 31) == 0) sm[tid >> 5] = mx;
    __syncthreads();
    if (tid < 32) {
        float v = (tid < 8) ? sm[tid] : -1e30f;
        #pragma unroll
        for (int o = 4; o; o >>= 1) v = fmaxf(v, __shfl_xor_sync(0xffffffffu, v, o));
        if (tid == 0) sm[0] = v;
    }
    __syncthreads();
    mx = sm[0];
    __syncthreads();

    float sum = 0.0f;
    cnt = 0;
    for (int j = tid; j < nvalid; j += 256) {
        float ev = fast_exp(e[cnt] - mx);
        e[cnt] = ev;
        sum += ev;
        cnt++;
    }
    #pragma unroll
    for (int o = 16; o; o >>= 1) sum += __shfl_xor_sync(0xffffffffu, sum, o);
    if ((tid & 31) == 0) sm[tid >> 5] = sum;
    __syncthreads();
    if (tid < 32) {
        float v = (tid < 8) ? sm[tid] : 0.0f;
        #pragma unroll
        for (int o = 4; o; o >>= 1) v += __shfl_xor_sync(0xffffffffu, v, o);
        if (tid == 0) sm[0] = v;
    }
    __syncthreads();
    float inv = 1.0f / sm[0];

    cnt = 0;
    for (int j = tid; j < nvalid; j += 256) {
        float v = e[cnt] * inv;
        r[j] = v;
        bf16 hb = __float2bfloat16(v);
        rh[j] = hb;
        rl[j] = __float2bfloat16(v - __bfloat162float(hb));
        cnt++;
    }
    bf16 z = __float2bfloat16(0.0f);
    for (int j = nvalid + tid; j < S_; j += 256) { r[j] = 0.0f; rh[j] = z; rl[j] = z; }
}

/* ---------------- host ------------------------------------------------------ */
static inline void mma_gemm(const bf16* Ah, const bf16* Al, const bf16* Bh, const bf16* Bl,
                            float* Cf, bf16* Chi, bf16* Clo,
                            int M, int N, int K, int lda, int ldb, int ldc,
                            long long sA, long long sB,
                            int zdiv, long long csOut, long long csIn,
                            float alpha, int causalSkip, int causalK, int batch)
{
    dim3 grid((N + 63) / 64, (M + 127) / 128, batch);
    mma_gemm4_kernel<<<grid, 256, GEMM_SMEM>>>(Ah, Al, Bh, Bl, Cf, Chi, Clo,
                                               M, N, K, lda, ldb, ldc,
                                               sA, sB, zdiv, csOut, csIn,
                                               alpha, causalSkip, causalK);
}

extern "C" void kernel_launch(void* const* d_in, const int* in_sizes, int n_in,
                              void* d_out, int out_size)
{
    const float* hs      = (const float*)d_in[0];
    const float* cs      = (const float*)d_in[1];
    const float* sn      = (const float*)d_in[2];
    const float* q_a_w   = (const float*)d_in[4];
    const float* q_a_ln  = (const float*)d_in[5];
    const float* q_b_w   = (const float*)d_in[6];
    const float* kv_a_w  = (const float*)d_in[7];
    const float* kv_a_ln = (const float*)d_in[8];
    const float* kv_b_w  = (const float*)d_in[9];
    const float* o_w     = (const float*)d_in[10];

    float* out = (float*)d_out;
    float* wts = out + (long long)B_ * S_ * HID_;

    static bool attr_set = false;
    if (!attr_set) {
        cudaFuncSetAttribute(mma_gemm4_kernel, cudaFuncAttributeMaxDynamicSharedMemorySize, GEMM_SMEM);
        attr_set = true;
    }

#define GETSYM(p, s) cudaGetSymbolAddress((void**)&p, s)
    bf16 *hsh, *hsl, *qlnh, *qlnl, *qfh, *qfl, *kch, *kcl, *kfh, *kfl, *vth, *vtl;
    bf16 *whi, *wlo, *omh, *oml;
    bf16 *wqah, *wqal, *wqbh, *wqbl, *wkah, *wkal, *wkbh, *wkbl, *woh, *wol;
    float *qlat, *qflat, *ckv, *kpe, *kvflat;
    GETSYM(hsh, g_hs_hi);   GETSYM(hsl, g_hs_lo);
    GETSYM(qlat, g_qlat);   GETSYM(qlnh, g_qlatn_hi); GETSYM(qlnl, g_qlatn_lo);
    GETSYM(qflat, g_qflat); GETSYM(qfh, g_qfull_hi);  GETSYM(qfl, g_qfull_lo);
    GETSYM(ckv, g_ckv);     GETSYM(kch, g_kc_hi);     GETSYM(kcl, g_kc_lo);
    GETSYM(kpe, g_kpe);     GETSYM(kvflat, g_kvflat);
    GETSYM(kfh, g_kfull_hi);GETSYM(kfl, g_kfull_lo);
    GETSYM(vth, g_vT_hi);   GETSYM(vtl, g_vT_lo);
    GETSYM(whi, g_w_hi);    GETSYM(wlo, g_w_lo);
    GETSYM(omh, g_omid_hi); GETSYM(oml, g_omid_lo);
    GETSYM(wqah, g_wqaT_hi); GETSYM(wqal, g_wqaT_lo);
    GETSYM(wqbh, g_wqbT_hi); GETSYM(wqbl, g_wqbT_lo);
    GETSYM(wkah, g_wkvaT_hi); GETSYM(wkal, g_wkvaT_lo);
    GETSYM(wkbh, g_wkvbT_hi); GETSYM(wkbl, g_wkvbT_lo);
    GETSYM(woh, g_woT_hi);  GETSYM(wol, g_woT_lo);
#undef GETSYM

    dim3 tb(32, 8);
    /* 0 */ transpose_split_kernel<<<dim3(QLORA_ / 32, HID_ / 32), tb>>>(q_a_w, wqah, wqal, HID_, QLORA_);
    /* 1 */ split_kernel<<<(NTOK_ * HID_ / 4 + 255) / 256, 256>>>(hs, hsh, hsl, NTOK_ * HID_ / 4);
    /* 2 */ transpose_split_kernel<<<dim3((KVLORA_ + DR_) / 32, HID_ / 32), tb>>>(kv_a_w, wkah, wkal, HID_, KVLORA_ + DR_);
    /* 3 q_a (profiled) */
    mma_gemm(hsh, hsl, wqah, wqal, qlat, 0, 0,
             NTOK_, QLORA_, HID_, HID_, HID_, QLORA_,
             0, 0, 1, 0, 0, 1.0f, 0, 0, 1);
    /* 4 kv_a */
    mma_gemm(hsh, hsl, wkah, wkal, ckv, 0, 0,
             NTOK_, KVLORA_ + DR_, HID_, HID_, HID_, KVLORA_ + DR_,
             0, 0, 1, 0, 0, 1.0f, 0, 0, 1);
    /* 5 */ rmsnorm_split_kernel<<<NTOK_, 256>>>(qlat, q_a_ln, qlnh, qlnl, QLORA_, QLORA_, QLORA_);
    /* 6 */ transpose_split_kernel<<<dim3(H_ * DQK_ / 32, QLORA_ / 32), tb>>>(q_b_w, wqbh, wqbl, QLORA_, H_ * DQK_);
    /* 7 q_b */
    mma_gemm(qlnh, qlnl, wqbh, wqbl, qflat, 0, 0,
             NTOK_, H_ * DQK_, QLORA_, QLORA_, QLORA_, H_ * DQK_,
             0, 0, 1, 0, 0, 1.0f, 0, 0, 1);
    /* 8 */ qrope_split_kernel<<<(B_ * H_ * S_ * (DQK_ / 4) + 255) / 256, 256>>>(qflat, cs, sn, qfh, qfl);
    /* 9 */ rmsnorm_split_kernel<<<NTOK_, 256>>>(ckv, kv_a_ln, kch, kcl, KVLORA_, KVLORA_ + DR_, KVLORA_);
    /* 10 */ krope_kernel<<<(B_ * S_ * (DR_ / 4) + 255) / 256, 256>>>(ckv, cs, sn, kpe);
    /* 11 */ transpose_split_kernel<<<dim3(H_ * (DN_ + DV_) / 32, KVLORA_ / 32), tb>>>(kv_b_w, wkbh, wkbl, KVLORA_, H_ * (DN_ + DV_));
    /* 12 kv_b */
    mma_gemm(kch, kcl, wkbh, wkbl, kvflat, 0, 0,
             NTOK_, H_ * (DN_ + DV_), KVLORA_, KVLORA_, KVLORA_, H_ * (DN_ + DV_),
             0, 0, 1, 0, 0, 1.0f, 0, 0, 1);
    /* 13 */ kbuild_split_kernel<<<(B_ * H_ * S_ * (DQK_ / 4) + 255) / 256, 256>>>(kvflat, kpe, kfh, kfl);
    /* 14 */ vbuildT_split_kernel<<<dim3(S_ / 32, DV_ / 32, B_ * H_), tb>>>(kvflat, vth, vtl);
    /* 15 scores */
    mma_gemm(qfh, qfl, kfh, kfl, wts, 0, 0,
             S_, S_, DQK_, DQK_, DQK_, S_,
             (long long)S_ * DQK_, (long long)S_ * DQK_,
             1, (long long)S_ * S_, 0,
             SCALING_, 1, 0, B_ * H_);
    /* 16 */ softmax_kernel<<<B_ * H_ * S_, 256>>>(wts, whi, wlo);
    /* 17 PV -> omid hi/lo */
    mma_gemm(whi, wlo, vth, vtl, 0, omh, oml,
             S_, DV_, S_, S_, S_, H_ * DV_,
             (long long)S_ * S_, (long long)DV_ * S_,
             H_, (long long)S_ * H_ * DV_, (long long)DV_,
             1.0f, 0, 1, B_ * H_);
    /* 18 */ transpose_split_kernel<<<dim3(HID_ / 32, (H_ * DV_) / 32), tb>>>(o_w, woh, wol, H_ * DV_, HID_);
    /* 19 o_proj */
    mma_gemm(omh, oml, woh, wol, out, 0, 0,
             NTOK_, HID_, H_ * DV_, H_ * DV_, H_ * DV_, HID_,
             0, 0, 1, 0, 0, 1.0f, 0, 0, 1);
}

// round 8
// speedup vs baseline: 3.2106x; 1.0828x over previous
#include <cuda_runtime.h>
#include <cuda_bf16.h>
#include <math.h>
#include <stdint.h>

#define B_      2
#define S_      2048
#define HID_    2048
#define H_      16
#define QLORA_  1536
#define KVLORA_ 512
#define DR_     64
#define DN_     128
#define DQK_    192
#define DV_     128
#define NTOK_   (B_*S_)
#define SCALING_ 0.07216878364870322f

typedef __nv_bfloat16 bf16;

/* ------------------------------- scratch ---------------------------------- */
__device__ bf16  g_hs_hi [NTOK_*HID_];
__device__ bf16  g_hs_lo [NTOK_*HID_];
__device__ float g_qlat  [NTOK_*QLORA_];
__device__ bf16  g_qlatn_hi[NTOK_*QLORA_];
__device__ bf16  g_qlatn_lo[NTOK_*QLORA_];
__device__ float g_qflat [NTOK_*H_*DQK_];
__device__ bf16  g_qfull_hi[B_*H_*S_*DQK_];
__device__ bf16  g_qfull_lo[B_*H_*S_*DQK_];
__device__ float g_ckv   [NTOK_*(KVLORA_+DR_)];
__device__ bf16  g_kc_hi [NTOK_*KVLORA_];
__device__ bf16  g_kc_lo [NTOK_*KVLORA_];
__device__ float g_kpe   [B_*S_*DR_];
__device__ float g_kvflat[NTOK_*H_*(DN_+DV_)];
__device__ bf16  g_kfull_hi[B_*H_*S_*DQK_];
__device__ bf16  g_kfull_lo[B_*H_*S_*DQK_];
__device__ bf16  g_vT_hi [B_*H_*DV_*S_];
__device__ bf16  g_vT_lo [B_*H_*DV_*S_];
__device__ bf16  g_w_hi  [(long long)B_*H_*S_*S_];
__device__ bf16  g_w_lo  [(long long)B_*H_*S_*S_];
__device__ bf16  g_omid_hi[NTOK_*H_*DV_];
__device__ bf16  g_omid_lo[NTOK_*H_*DV_];
__device__ bf16  g_wqaT_hi [QLORA_*HID_];
__device__ bf16  g_wqaT_lo [QLORA_*HID_];
__device__ bf16  g_wqbT_hi [H_*DQK_*QLORA_];
__device__ bf16  g_wqbT_lo [H_*DQK_*QLORA_];
__device__ bf16  g_wkvaT_hi[(KVLORA_+DR_)*HID_];
__device__ bf16  g_wkvaT_lo[(KVLORA_+DR_)*HID_];
__device__ bf16  g_wkvbT_hi[H_*(DN_+DV_)*KVLORA_];
__device__ bf16  g_wkvbT_lo[H_*(DN_+DV_)*KVLORA_];
__device__ bf16  g_woT_hi  [HID_*H_*DV_];
__device__ bf16  g_woT_lo  [HID_*H_*DV_];

/* --------------------------- helpers --------------------------------------- */
__device__ __forceinline__ uint32_t smem_u32(const void* p) {
    uint32_t a;
    asm("{ .reg .u64 t; cvta.to.shared.u64 t, %1; cvt.u32.u64 %0, t; }" : "=r"(a) : "l"(p));
    return a;
}
__device__ __forceinline__ void ldsm_x4(uint32_t& r0, uint32_t& r1, uint32_t& r2, uint32_t& r3,
                                        uint32_t addr) {
    asm volatile("ldmatrix.sync.aligned.m8n8.x4.shared.b16 {%0,%1,%2,%3}, [%4];"
                 : "=r"(r0), "=r"(r1), "=r"(r2), "=r"(r3) : "r"(addr));
}
__device__ __forceinline__ void mma16816(float* c, const uint32_t* a, uint32_t b0, uint32_t b1) {
    asm volatile("mma.sync.aligned.m16n8k16.row.col.f32.bf16.bf16.f32 "
                 "{%0,%1,%2,%3}, {%4,%5,%6,%7}, {%8,%9}, {%0,%1,%2,%3};"
                 : "+f"(c[0]), "+f"(c[1]), "+f"(c[2]), "+f"(c[3])
                 : "r"(a[0]), "r"(a[1]), "r"(a[2]), "r"(a[3]), "r"(b0), "r"(b1));
}
__device__ __forceinline__ void cpa16(uint32_t dst, const void* src) {
    asm volatile("cp.async.cg.shared.global [%0], [%1], 16;"
                 :: "r"(dst), "l"(src) : "memory");
}
#define CP_COMMIT() asm volatile("cp.async.commit_group;" ::: "memory")
#define CP_WAIT1()  asm volatile("cp.async.wait_group 1;" ::: "memory")

/* split 4 floats into packed 4xbf16 hi (uint2) and lo (uint2) */
__device__ __forceinline__ void split4v(float4 v, uint2& hi, uint2& lo) {
    float f[4] = {v.x, v.y, v.z, v.w};
    unsigned short h[4], l[4];
    #pragma unroll
    for (int i = 0; i < 4; i++) {
        bf16 hb = __float2bfloat16(f[i]);
        bf16 lb = __float2bfloat16(f[i] - __bfloat162float(hb));
        h[i] = *(unsigned short*)&hb;
        l[i] = *(unsigned short*)&lb;
    }
    hi.x = (uint32_t)h[0] | ((uint32_t)h[1] << 16);
    hi.y = (uint32_t)h[2] | ((uint32_t)h[3] << 16);
    lo.x = (uint32_t)l[0] | ((uint32_t)l[1] << 16);
    lo.y = (uint32_t)l[2] | ((uint32_t)l[3] << 16);
}

/* FFMA-only exp */
__device__ __forceinline__ float fast_exp(float x) {
    float t = x * 1.4426950408889634f;
    float r = rintf(t);
    float f = t - r;
    float p =          1.339887440266574e-3f;
    p = fmaf(p, f,     9.618437357674640e-3f);
    p = fmaf(p, f,     5.550332471162809e-2f);
    p = fmaf(p, f,     2.402264791363012e-1f);
    p = fmaf(p, f,     6.931472028550421e-1f);
    p = fmaf(p, f,     1.0f);
    int ri = (int)r;
    if (ri < -126) ri = -126;
    float s = __int_as_float((uint32_t)(ri + 127) << 23);
    return p * s;
}

/* smem: K-chunk 64. A tiles 128x64 bf16, B 64x64; rows padded to 144B. */
#define ROWB   144
#define AHI_O  0
#define ALO_O  18432
#define BHI_O  36864
#define BLO_O  46080
#define STGSZ  55296
#define NSTG   2
#define GEMM_SMEM (NSTG*STGSZ)

/* ------- bf16 HMMA GEMM: 128x64 CTA tile, K-chunk 64, 2 CTAs/SM, 2-stage,
   fragment-reuse across the 3 compensation passes (8 LDSM -> 24 MMA per ks) -- */
__global__ __launch_bounds__(256, 2) void mma_gemm5_kernel(
    const bf16* __restrict__ Ahi, const bf16* __restrict__ Alo,
    const bf16* __restrict__ Bhi, const bf16* __restrict__ Blo,
    float* __restrict__ Cf, bf16* __restrict__ Chi, bf16* __restrict__ Clo,
    int M, int N, int K, int lda, int ldb, int ldc,
    long long sA, long long sB, int zdiv, long long csOut, long long csIn,
    float alpha, int causalSkip, int causalK)
{
    const int row0 = blockIdx.y * 128;
    const int col0 = blockIdx.x * 64;
    if (causalSkip && col0 > row0 + 127) return;
    const int bz = blockIdx.z;
    const bf16* Ah = Ahi + (long long)bz * sA;
    const bf16* Al = Alo + (long long)bz * sA;
    const bf16* Bh = Bhi + (long long)bz * sB;
    const bf16* Bl = Blo + (long long)bz * sB;
    const long long coff = (long long)(bz / zdiv) * csOut + (long long)(bz % zdiv) * csIn;

    extern __shared__ __align__(16) char smem[];
    const uint32_t sb = smem_u32(smem);

    const int tid  = threadIdx.x;
    const int wid  = tid >> 5;
    const int lane = tid & 31;
    const int wm = wid & 3;          /* M strip: rows wm*32..+32 */
    const int wn = wid >> 2;         /* N strip: cols wn*32..+32 */
    const int laneIn = lane & 7;
    const int quad   = lane >> 3;

    const uint32_t aBase = (uint32_t)((wm * 32 + laneIn + (quad & 1) * 8) * ROWB
                                      + ((quad >> 1) * 8) * 2);
    const uint32_t bBase = (uint32_t)((wn * 32 + laneIn + (quad >> 1) * 8) * ROWB
                                      + ((quad & 1) * 8) * 2);

    int kend = K;
    if (causalK) { int kl = row0 + 128; if (kl < kend) kend = kl; }
    const int nch = kend >> 6;

    float acc[2][4][4];
    #pragma unroll
    for (int i = 0; i < 2; i++)
        #pragma unroll
        for (int j = 0; j < 4; j++)
            #pragma unroll
            for (int q = 0; q < 4; q++) acc[i][j][q] = 0.0f;

    auto issue = [&](int s) {
        const uint32_t dst = sb + (uint32_t)(s & 1) * STGSZ;
        const int k0 = s << 6;
        #pragma unroll
        for (int i = 0; i < 4; i++) {
            const int g = tid + i * 256;
            const int r = g >> 3, sg = g & 7;
            const uint32_t so = (uint32_t)(r * ROWB + sg * 16);
            const long long ga = (long long)(row0 + r) * lda + k0 + sg * 8;
            cpa16(dst + AHI_O + so, Ah + ga);
            cpa16(dst + ALO_O + so, Al + ga);
        }
        #pragma unroll
        for (int i = 0; i < 2; i++) {
            const int g = tid + i * 256;
            const int r = g >> 3, sg = g & 7;
            const uint32_t so = (uint32_t)(r * ROWB + sg * 16);
            const long long gb = (long long)(col0 + r) * ldb + k0 + sg * 8;
            cpa16(dst + BHI_O + so, Bh + gb);
            cpa16(dst + BLO_O + so, Bl + gb);
        }
    };

    /* 2-stage pipeline */
    issue(0);
    CP_COMMIT();

    for (int c = 0; c < nch; c++) {
        if (c + 1 < nch) issue(c + 1);
        CP_COMMIT();
        CP_WAIT1();
        __syncthreads();

        const uint32_t bufb = sb + (uint32_t)(c & 1) * STGSZ;
        #pragma unroll
        for (int ks = 0; ks < 4; ks++) {
            const uint32_t kb = (uint32_t)(ks * 32);
            /* load all fragments once per ks: 8 LDSM feed 24 MMA */
            uint32_t ah[2][4], al[2][4], bh[2][4], bl[2][4];
            #pragma unroll
            for (int mt = 0; mt < 2; mt++) {
                const uint32_t ao = aBase + (uint32_t)(mt * 16 * ROWB) + kb;
                ldsm_x4(ah[mt][0], ah[mt][1], ah[mt][2], ah[mt][3], bufb + AHI_O + ao);
                ldsm_x4(al[mt][0], al[mt][1], al[mt][2], al[mt][3], bufb + ALO_O + ao);
            }
            #pragma unroll
            for (int np = 0; np < 2; np++) {
                const uint32_t bo = bBase + (uint32_t)(np * 16 * ROWB) + kb;
                ldsm_x4(bh[np][0], bh[np][1], bh[np][2], bh[np][3], bufb + BHI_O + bo);
                ldsm_x4(bl[np][0], bl[np][1], bl[np][2], bl[np][3], bufb + BLO_O + bo);
            }
            /* p0: Ahi x Bhi */
            #pragma unroll
            for (int mt = 0; mt < 2; mt++)
                #pragma unroll
                for (int nt = 0; nt < 4; nt++)
                    mma16816(acc[mt][nt], ah[mt],
                             bh[nt >> 1][(nt & 1) * 2], bh[nt >> 1][(nt & 1) * 2 + 1]);
            /* p1: Ahi x Blo */
            #pragma unroll
            for (int mt = 0; mt < 2; mt++)
                #pragma unroll
                for (int nt = 0; nt < 4; nt++)
                    mma16816(acc[mt][nt], ah[mt],
                             bl[nt >> 1][(nt & 1) * 2], bl[nt >> 1][(nt & 1) * 2 + 1]);
            /* p2: Alo x Bhi */
            #pragma unroll
            for (int mt = 0; mt < 2; mt++)
                #pragma unroll
                for (int nt = 0; nt < 4; nt++)
                    mma16816(acc[mt][nt], al[mt],
                             bh[nt >> 1][(nt & 1) * 2], bh[nt >> 1][(nt & 1) * 2 + 1]);
        }
        __syncthreads();
    }

    /* epilogue */
    const int lr  = lane >> 2;
    const int lc2 = (lane & 3) * 2;
    #pragma unroll
    for (int mt = 0; mt < 2; mt++) {
        #pragma unroll
        for (int nt = 0; nt < 4; nt++) {
            const int gr = row0 + wm * 32 + mt * 16 + lr;
            const int gc = col0 + wn * 32 + nt * 8 + lc2;
            float a0 = acc[mt][nt][0] * alpha, a1 = acc[mt][nt][1] * alpha;
            float a2 = acc[mt][nt][2] * alpha, a3 = acc[mt][nt][3] * alpha;
            const long long o0 = coff + (long long)gr * ldc + gc;
            const long long o1 = coff + (long long)(gr + 8) * ldc + gc;
            if (Cf) {
                *reinterpret_cast<float2*>(Cf + o0) = make_float2(a0, a1);
                *reinterpret_cast<float2*>(Cf + o1) = make_float2(a2, a3);
            }
            if (Chi) {
                bf16 h0 = __float2bfloat16(a0), h1 = __float2bfloat16(a1);
                bf16 h2 = __float2bfloat16(a2), h3 = __float2bfloat16(a3);
                __nv_bfloat162 hv0; hv0.x = h0; hv0.y = h1;
                __nv_bfloat162 hv1; hv1.x = h2; hv1.y = h3;
                *reinterpret_cast<__nv_bfloat162*>(Chi + o0) = hv0;
                *reinterpret_cast<__nv_bfloat162*>(Chi + o1) = hv1;
                __nv_bfloat162 lv0, lv1;
                lv0.x = __float2bfloat16(a0 - __bfloat162float(h0));
                lv0.y = __float2bfloat16(a1 - __bfloat162float(h1));
                lv1.x = __float2bfloat16(a2 - __bfloat162float(h2));
                lv1.y = __float2bfloat16(a3 - __bfloat162float(h3));
                *reinterpret_cast<__nv_bfloat162*>(Clo + o0) = lv0;
                *reinterpret_cast<__nv_bfloat162*>(Clo + o1) = lv1;
            }
        }
    }
}

/* ---------------- split fp32 -> hi/lo bf16 ---------------------------------- */
__global__ void split_kernel(const float* __restrict__ x, bf16* __restrict__ hi,
                             bf16* __restrict__ lo, int n4)
{
    int idx = blockIdx.x * blockDim.x + threadIdx.x;
    if (idx >= n4) return;
    float4 v = reinterpret_cast<const float4*>(x)[idx];
    uint2 h, l;
    split4v(v, h, l);
    reinterpret_cast<uint2*>(hi)[idx] = h;
    reinterpret_cast<uint2*>(lo)[idx] = l;
}

/* ---------------- transpose [K,N] fp32 -> [N,K] hi/lo bf16 ------------------ */
__global__ void transpose_split_kernel(const float* __restrict__ in,
                                       bf16* __restrict__ outHi, bf16* __restrict__ outLo,
                                       int K, int N)
{
    __shared__ float t[32][33];
    int k0 = blockIdx.y * 32, n0 = blockIdx.x * 32;
    int x = threadIdx.x, y = threadIdx.y;
    #pragma unroll
    for (int i = 0; i < 32; i += 8) {
        int k = k0 + y + i, n = n0 + x;
        t[y + i][x] = (k < K && n < N) ? in[(long long)k * N + n] : 0.0f;
    }
    __syncthreads();
    #pragma unroll
    for (int i = 0; i < 32; i += 8) {
        int n = n0 + y + i, k = k0 + x;
        if (n < N && k < K) {
            float v = t[x][y + i];
            bf16 hb = __float2bfloat16(v);
            outHi[(long long)n * K + k] = hb;
            outLo[(long long)n * K + k] = __float2bfloat16(v - __bfloat162float(hb));
        }
    }
}

/* ---------------- RMS norm -> hi/lo ----------------------------------------- */
__global__ __launch_bounds__(256) void rmsnorm_split_kernel(
    const float* __restrict__ x, const float* __restrict__ w,
    bf16* __restrict__ yh, bf16* __restrict__ yl, int n, int ldx, int ldy)
{
    int row = blockIdx.x;
    const float* xr = x + (long long)row * ldx;
    int tid = threadIdx.x;
    float ss = 0.0f;
    for (int i = tid; i < n; i += 256) { float v = xr[i]; ss += v * v; }
    __shared__ float red[8];
    #pragma unroll
    for (int o = 16; o; o >>= 1) ss += __shfl_xor_sync(0xffffffffu, ss, o);
    if ((tid & 31) == 0) red[tid >> 5] = ss;
    __syncthreads();
    if (tid < 32) {
        float v = (tid < 8) ? red[tid] : 0.0f;
        #pragma unroll
        for (int o = 4; o; o >>= 1) v += __shfl_xor_sync(0xffffffffu, v, o);
        if (tid == 0) red[0] = v;
    }
    __syncthreads();
    float inv = rsqrtf(red[0] / (float)n + 1e-6f);
    bf16* yhr = yh + (long long)row * ldy;
    bf16* ylr = yl + (long long)row * ldy;
    for (int i = tid; i < n; i += 256) {
        float v = w[i] * xr[i] * inv;
        bf16 hb = __float2bfloat16(v);
        yhr[i] = hb;
        ylr[i] = __float2bfloat16(v - __bfloat162float(hb));
    }
}

/* ---------------- q rope -> qfull hi/lo -------------------------------------- */
__global__ void qrope_split_kernel(const float* __restrict__ qf, const float* __restrict__ cs,
                                   const float* __restrict__ sn,
                                   bf16* __restrict__ oh, bf16* __restrict__ ol)
{
    int idx = blockIdx.x * blockDim.x + threadIdx.x;
    const int total4 = B_ * H_ * S_ * (DQK_ / 4);
    if (idx >= total4) return;
    int d4 = idx % (DQK_ / 4);
    int t = idx / (DQK_ / 4);
    int s = t % S_; t /= S_;
    int h = t % H_;
    int b = t / H_;
    int d = d4 * 4;
    const float* src = qf + (((long long)(b * S_ + s)) * H_ + h) * DQK_;
    float4 val;
    if (d < DN_) {
        val = *reinterpret_cast<const float4*>(src + d);
    } else {
        int p = d - DN_;
        float4 x = *reinterpret_cast<const float4*>(src + DN_ + p);
        float4 other;
        if (p < DR_ / 2) {
            float4 o = *reinterpret_cast<const float4*>(src + DN_ + p + DR_ / 2);
            other = make_float4(-o.x, -o.y, -o.z, -o.w);
        } else {
            other = *reinterpret_cast<const float4*>(src + DN_ + p - DR_ / 2);
        }
        long long co = ((long long)b * S_ + s) * DR_ + p;
        float4 c = *reinterpret_cast<const float4*>(cs + co);
        float4 ss2 = *reinterpret_cast<const float4*>(sn + co);
        val.x = fmaf(x.x, c.x, other.x * ss2.x);
        val.y = fmaf(x.y, c.y, other.y * ss2.y);
        val.z = fmaf(x.z, c.z, other.z * ss2.z);
        val.w = fmaf(x.w, c.w, other.w * ss2.w);
    }
    uint2 hh, ll;
    split4v(val, hh, ll);
    reinterpret_cast<uint2*>(oh)[idx] = hh;
    reinterpret_cast<uint2*>(ol)[idx] = ll;
}

__global__ void krope_kernel(const float* __restrict__ ckv, const float* __restrict__ cs,
                             const float* __restrict__ sn, float* __restrict__ kpe)
{
    int idx = blockIdx.x * blockDim.x + threadIdx.x;
    if (idx >= B_ * S_ * (DR_ / 4)) return;
    int p4 = idx % (DR_ / 4);
    int bs = idx / (DR_ / 4);
    int p = p4 * 4;
    const float* src = ckv + (long long)bs * (KVLORA_ + DR_) + KVLORA_;
    float4 x = *reinterpret_cast<const float4*>(src + p);
    float4 other;
    if (p < DR_ / 2) {
        float4 o = *reinterpret_cast<const float4*>(src + p + DR_ / 2);
        other = make_float4(-o.x, -o.y, -o.z, -o.w);
    } else {
        other = *reinterpret_cast<const float4*>(src + p - DR_ / 2);
    }
    long long co = (long long)bs * DR_ + p;
    float4 c = *reinterpret_cast<const float4*>(cs + co);
    float4 ss2 = *reinterpret_cast<const float4*>(sn + co);
    float4 val;
    val.x = fmaf(x.x, c.x, other.x * ss2.x);
    val.y = fmaf(x.y, c.y, other.y * ss2.y);
    val.z = fmaf(x.z, c.z, other.z * ss2.z);
    val.w = fmaf(x.w, c.w, other.w * ss2.w);
    *reinterpret_cast<float4*>(kpe + co) = val;
}

__global__ void kbuild_split_kernel(const float* __restrict__ kvflat, const float* __restrict__ kpe,
                                    bf16* __restrict__ oh, bf16* __restrict__ ol)
{
    int idx = blockIdx.x * blockDim.x + threadIdx.x;
    const int total4 = B_ * H_ * S_ * (DQK_ / 4);
    if (idx >= total4) return;
    int d4 = idx % (DQK_ / 4);
    int t = idx / (DQK_ / 4);
    int s = t % S_; t /= S_;
    int h = t % H_;
    int b = t / H_;
    int d = d4 * 4;
    float4 val;
    if (d < DN_)
        val = *reinterpret_cast<const float4*>(
            kvflat + (((long long)(b * S_ + s)) * H_ + h) * (DN_ + DV_) + d);
    else
        val = *reinterpret_cast<const float4*>(
            kpe + ((long long)b * S_ + s) * DR_ + (d - DN_));
    uint2 hh, ll;
    split4v(val, hh, ll);
    reinterpret_cast<uint2*>(oh)[idx] = hh;
    reinterpret_cast<uint2*>(ol)[idx] = ll;
}

/* v transpose -> vT hi/lo [b,h,d,s] */
__global__ void vbuildT_split_kernel(const float* __restrict__ kvflat,
                                     bf16* __restrict__ oh, bf16* __restrict__ ol)
{
    __shared__ float t[32][33];
    int bh = blockIdx.z;
    int b = bh >> 4, h = bh & 15;
    int s0 = blockIdx.x * 32, d0 = blockIdx.y * 32;
    int x = threadIdx.x, y = threadIdx.y;
    const float* src = kvflat + ((long long)b * S_ * H_ + h) * (DN_ + DV_) + DN_;
    #pragma unroll
    for (int i = 0; i < 32; i += 8) {
        int s = s0 + y + i, d = d0 + x;
        t[y + i][x] = src[(long long)s * (H_ * (DN_ + DV_)) + d];
    }
    __syncthreads();
    long long base = ((long long)bh * DV_) * S_;
    #pragma unroll
    for (int i = 0; i < 32; i += 8) {
        int d = d0 + y + i, s = s0 + x;
        float v = t[x][y + i];
        bf16 hb = __float2bfloat16(v);
        oh[base + (long long)d * S_ + s] = hb;
        ol[base + (long long)d * S_ + s] = __float2bfloat16(v - __bfloat162float(hb));
    }
}

/* ---------------- causal softmax: fp32 out + hi/lo bf16 out ------------------ */
__global__ __launch_bounds__(256) void softmax_kernel(float* __restrict__ wts,
                                                      bf16* __restrict__ wh,
                                                      bf16* __restrict__ wl)
{
    long long row = blockIdx.x;
    int i = (int)(row % S_);
    float* r = wts + row * (long long)S_;
    bf16* rh = wh + row * (long long)S_;
    bf16* rl = wl + row * (long long)S_;
    int tid = threadIdx.x;
    int nvalid = i + 1;

    float e[8];
    float mx = -1e30f;
    int cnt = 0;
    for (int j = tid; j < nvalid; j += 256) { e[cnt] = r[j]; mx = fmaxf(mx, e[cnt]); cnt++; }

    __shared__ float sm[8];
    #pragma unroll
    for (int o = 16; o; o >>= 1) mx = fmaxf(mx, __shfl_xor_sync(0xffffffffu, mx, o));
    if ((tid & 31) == 0) sm[tid >> 5] = mx;
    __syncthreads();
    if (tid < 32) {
        float v = (tid < 8) ? sm[tid] : -1e30f;
        #pragma unroll
        for (int o = 4; o; o >>= 1) v = fmaxf(v, __shfl_xor_sync(0xffffffffu, v, o));
        if (tid == 0) sm[0] = v;
    }
    __syncthreads();
    mx = sm[0];
    __syncthreads();

    float sum = 0.0f;
    cnt = 0;
    for (int j = tid; j < nvalid; j += 256) {
        float ev = fast_exp(e[cnt] - mx);
        e[cnt] = ev;
        sum += ev;
        cnt++;
    }
    #pragma unroll
    for (int o = 16; o; o >>= 1) sum += __shfl_xor_sync(0xffffffffu, sum, o);
    if ((tid & 31) == 0) sm[tid >> 5] = sum;
    __syncthreads();
    if (tid < 32) {
        float v = (tid < 8) ? sm[tid] : 0.0f;
        #pragma unroll
        for (int o = 4; o; o >>= 1) v += __shfl_xor_sync(0xffffffffu, v, o);
        if (tid == 0) sm[0] = v;
    }
    __syncthreads();
    float inv = 1.0f / sm[0];

    cnt = 0;
    for (int j = tid; j < nvalid; j += 256) {
        float v = e[cnt] * inv;
        r[j] = v;
        bf16 hb = __float2bfloat16(v);
        rh[j] = hb;
        rl[j] = __float2bfloat16(v - __bfloat162float(hb));
        cnt++;
    }
    bf16 z = __float2bfloat16(0.0f);
    for (int j = nvalid + tid; j < S_; j += 256) { r[j] = 0.0f; rh[j] = z; rl[j] = z; }
}

/* ---------------- host ------------------------------------------------------ */
static inline void mma_gemm(const bf16* Ah, const bf16* Al, const bf16* Bh, const bf16* Bl,
                            float* Cf, bf16* Chi, bf16* Clo,
                            int M, int N, int K, int lda, int ldb, int ldc,
                            long long sA, long long sB,
                            int zdiv, long long csOut, long long csIn,
                            float alpha, int causalSkip, int causalK, int batch)
{
    dim3 grid((N + 63) / 64, (M + 127) / 128, batch);
    mma_gemm5_kernel<<<grid, 256, GEMM_SMEM>>>(Ah, Al, Bh, Bl, Cf, Chi, Clo,
                                               M, N, K, lda, ldb, ldc,
                                               sA, sB, zdiv, csOut, csIn,
                                               alpha, causalSkip, causalK);
}

extern "C" void kernel_launch(void* const* d_in, const int* in_sizes, int n_in,
                              void* d_out, int out_size)
{
    const float* hs      = (const float*)d_in[0];
    const float* cs      = (const float*)d_in[1];
    const float* sn      = (const float*)d_in[2];
    const float* q_a_w   = (const float*)d_in[4];
    const float* q_a_ln  = (const float*)d_in[5];
    const float* q_b_w   = (const float*)d_in[6];
    const float* kv_a_w  = (const float*)d_in[7];
    const float* kv_a_ln = (const float*)d_in[8];
    const float* kv_b_w  = (const float*)d_in[9];
    const float* o_w     = (const float*)d_in[10];

    float* out = (float*)d_out;
    float* wts = out + (long long)B_ * S_ * HID_;

    static bool attr_set = false;
    if (!attr_set) {
        cudaFuncSetAttribute(mma_gemm5_kernel, cudaFuncAttributeMaxDynamicSharedMemorySize, GEMM_SMEM);
        attr_set = true;
    }

#define GETSYM(p, s) cudaGetSymbolAddress((void**)&p, s)
    bf16 *hsh, *hsl, *qlnh, *qlnl, *qfh, *qfl, *kch, *kcl, *kfh, *kfl, *vth, *vtl;
    bf16 *whi, *wlo, *omh, *oml;
    bf16 *wqah, *wqal, *wqbh, *wqbl, *wkah, *wkal, *wkbh, *wkbl, *woh, *wol;
    float *qlat, *qflat, *ckv, *kpe, *kvflat;
    GETSYM(hsh, g_hs_hi);   GETSYM(hsl, g_hs_lo);
    GETSYM(qlat, g_qlat);   GETSYM(qlnh, g_qlatn_hi); GETSYM(qlnl, g_qlatn_lo);
    GETSYM(qflat, g_qflat); GETSYM(qfh, g_qfull_hi);  GETSYM(qfl, g_qfull_lo);
    GETSYM(ckv, g_ckv);     GETSYM(kch, g_kc_hi);     GETSYM(kcl, g_kc_lo);
    GETSYM(kpe, g_kpe);     GETSYM(kvflat, g_kvflat);
    GETSYM(kfh, g_kfull_hi);GETSYM(kfl, g_kfull_lo);
    GETSYM(vth, g_vT_hi);   GETSYM(vtl, g_vT_lo);
    GETSYM(whi, g_w_hi);    GETSYM(wlo, g_w_lo);
    GETSYM(omh, g_omid_hi); GETSYM(oml, g_omid_lo);
    GETSYM(wqah, g_wqaT_hi); GETSYM(wqal, g_wqaT_lo);
    GETSYM(wqbh, g_wqbT_hi); GETSYM(wqbl, g_wqbT_lo);
    GETSYM(wkah, g_wkvaT_hi); GETSYM(wkal, g_wkvaT_lo);
    GETSYM(wkbh, g_wkvbT_hi); GETSYM(wkbl, g_wkvbT_lo);
    GETSYM(woh, g_woT_hi);  GETSYM(wol, g_woT_lo);
#undef GETSYM

    dim3 tb(32, 8);
    /* 0 */ transpose_split_kernel<<<dim3(QLORA_ / 32, HID_ / 32), tb>>>(q_a_w, wqah, wqal, HID_, QLORA_);
    /* 1 */ split_kernel<<<(NTOK_ * HID_ / 4 + 255) / 256, 256>>>(hs, hsh, hsl, NTOK_ * HID_ / 4);
    /* 2 */ transpose_split_kernel<<<dim3((KVLORA_ + DR_) / 32, HID_ / 32), tb>>>(kv_a_w, wkah, wkal, HID_, KVLORA_ + DR_);
    /* 3 q_a (profiled) */
    mma_gemm(hsh, hsl, wqah, wqal, qlat, 0, 0,
             NTOK_, QLORA_, HID_, HID_, HID_, QLORA_,
             0, 0, 1, 0, 0, 1.0f, 0, 0, 1);
    /* 4 kv_a */
    mma_gemm(hsh, hsl, wkah, wkal, ckv, 0, 0,
             NTOK_, KVLORA_ + DR_, HID_, HID_, HID_, KVLORA_ + DR_,
             0, 0, 1, 0, 0, 1.0f, 0, 0, 1);
    /* 5 */ rmsnorm_split_kernel<<<NTOK_, 256>>>(qlat, q_a_ln, qlnh, qlnl, QLORA_, QLORA_, QLORA_);
    /* 6 */ transpose_split_kernel<<<dim3(H_ * DQK_ / 32, QLORA_ / 32), tb>>>(q_b_w, wqbh, wqbl, QLORA_, H_ * DQK_);
    /* 7 q_b */
    mma_gemm(qlnh, qlnl, wqbh, wqbl, qflat, 0, 0,
             NTOK_, H_ * DQK_, QLORA_, QLORA_, QLORA_, H_ * DQK_,
             0, 0, 1, 0, 0, 1.0f, 0, 0, 1);
    /* 8 */ qrope_split_kernel<<<(B_ * H_ * S_ * (DQK_ / 4) + 255) / 256, 256>>>(qflat, cs, sn, qfh, qfl);
    /* 9 */ rmsnorm_split_kernel<<<NTOK_, 256>>>(ckv, kv_a_ln, kch, kcl, KVLORA_, KVLORA_ + DR_, KVLORA_);
    /* 10 */ krope_kernel<<<(B_ * S_ * (DR_ / 4) + 255) / 256, 256>>>(ckv, cs, sn, kpe);
    /* 11 */ transpose_split_kernel<<<dim3(H_ * (DN_ + DV_) / 32, KVLORA_ / 32), tb>>>(kv_b_w, wkbh, wkbl, KVLORA_, H_ * (DN_ + DV_));
    /* 12 kv_b */
    mma_gemm(kch, kcl, wkbh, wkbl, kvflat, 0, 0,
             NTOK_, H_ * (DN_ + DV_), KVLORA_, KVLORA_, KVLORA_, H_ * (DN_ + DV_),
             0, 0, 1, 0, 0, 1.0f, 0, 0, 1);
    /* 13 */ kbuild_split_kernel<<<(B_ * H_ * S_ * (DQK_ / 4) + 255) / 256, 256>>>(kvflat, kpe, kfh, kfl);
    /* 14 */ vbuildT_split_kernel<<<dim3(S_ / 32, DV_ / 32, B_ * H_), tb>>>(kvflat, vth, vtl);
    /* 15 scores */
    mma_gemm(qfh, qfl, kfh, kfl, wts, 0, 0,
             S_, S_, DQK_, DQK_, DQK_, S_,
             (long long)S_ * DQK_, (long long)S_ * DQK_,
             1, (long long)S_ * S_, 0,
             SCALING_, 1, 0, B_ * H_);
    /* 16 */ softmax_kernel<<<B_ * H_ * S_, 256>>>(wts, whi, wlo);
    /* 17 PV -> omid hi/lo */
    mma_gemm(whi, wlo, vth, vtl, 0, omh, oml,
             S_, DV_, S_, S_, S_, H_ * DV_,
             (long long)S_ * S_, (long long)DV_ * S_,
             H_, (long long)S_ * H_ * DV_, (long long)DV_,
             1.0f, 0, 1, B_ * H_);
    /* 18 */ transpose_split_kernel<<<dim3(HID_ / 32, (H_ * DV_) / 32), tb>>>(o_w, woh, wol, H_ * DV_, HID_);
    /* 19 o_proj */
    mma_gemm(omh, oml, woh, wol, out, 0, 0,
             NTOK_, HID_, H_ * DV_, H_ * DV_, H_ * DV_, HID_,
             0, 0, 1, 0, 0, 1.0f, 0, 0, 1);
}